// round 1
// baseline (speedup 1.0000x reference)
#include <cuda_runtime.h>
#include <cuda_bf16.h>
#include <math.h>

// Problem constants
#define Bn 8
#define Tn 8192
#define Dn 512
#define Hn 4
#define DKn 256
#define DVn 512
#define HKn 64
#define HVn 128
#define Cn 64
#define Nn 128               // T / C
#define BTn (Bn * Tn)        // 65536
#define LOWn 16

// ---------------- scratch (device globals; no runtime allocation) ----------
__device__ float g_q[(size_t)BTn * DKn];                 // 64 MB
__device__ float g_k[(size_t)BTn * DKn];                 // 64 MB
__device__ float g_v[(size_t)BTn * DVn];                 // 128 MB
__device__ float g_g[(size_t)BTn * DVn];                 // 128 MB
__device__ float g_gk[(size_t)BTn * DKn];                // 64 MB (raw -> cumsum in place)
__device__ float g_U[(size_t)Bn * Hn * Nn * HKn * HVn];  // 128 MB (U -> S_init in place)
__device__ float g_dec[(size_t)Bn * Hn * Nn * HKn];      // 1 MB
__device__ float g_o[(size_t)BTn * DVn];                 // 128 MB

// ---------------- generic fp32 GEMM: C[m][n] = sum_k A[m][k] * W[n][k] -----
// A: (M,K) row-major, W: (N,K) row-major ("NT"). M%64==0, N%64==0, K%16==0.
__global__ void gemm_nt(const float* __restrict__ A, const float* __restrict__ W,
                        float* __restrict__ Cout, int M, int N, int K) {
    __shared__ float sA[64][17];
    __shared__ float sB[64][17];
    int tid = threadIdx.x;                // 256 threads
    int tx = tid & 15, ty = tid >> 4;     // 16x16, each 4x4
    int m0 = blockIdx.x * 64;
    int n0 = blockIdx.y * 64;
    int lr = tid >> 2;                    // load row 0..63
    int lc = (tid & 3) * 4;               // load col group
    float acc[4][4];
#pragma unroll
    for (int i = 0; i < 4; i++)
#pragma unroll
        for (int j = 0; j < 4; j++) acc[i][j] = 0.f;

    for (int k0 = 0; k0 < K; k0 += 16) {
        float4 a4 = *(const float4*)(A + (size_t)(m0 + lr) * K + k0 + lc);
        sA[lr][lc + 0] = a4.x; sA[lr][lc + 1] = a4.y;
        sA[lr][lc + 2] = a4.z; sA[lr][lc + 3] = a4.w;
        float4 b4 = *(const float4*)(W + (size_t)(n0 + lr) * K + k0 + lc);
        sB[lr][lc + 0] = b4.x; sB[lr][lc + 1] = b4.y;
        sB[lr][lc + 2] = b4.z; sB[lr][lc + 3] = b4.w;
        __syncthreads();
#pragma unroll
        for (int kk = 0; kk < 16; kk++) {
            float a[4], b[4];
#pragma unroll
            for (int i = 0; i < 4; i++) a[i] = sA[ty * 4 + i][kk];
#pragma unroll
            for (int j = 0; j < 4; j++) b[j] = sB[tx * 4 + j][kk];
#pragma unroll
            for (int i = 0; i < 4; i++)
#pragma unroll
                for (int j = 0; j < 4; j++) acc[i][j] += a[i] * b[j];
        }
        __syncthreads();
    }
#pragma unroll
    for (int i = 0; i < 4; i++) {
        float* cp = Cout + (size_t)(m0 + ty * 4 + i) * N + n0 + tx * 4;
#pragma unroll
        for (int j = 0; j < 4; j++) cp[j] = acc[i][j];
    }
}

// ---------------- low-rank gate: gk = logsigmoid(x@W1^T@W2^T + b)/16 -------
__global__ void gk_kernel(const float* __restrict__ x, const float* __restrict__ W1,
                          const float* __restrict__ W2, const float* __restrict__ bias,
                          float* __restrict__ gk) {
    int row = blockIdx.x;                // 0..BT-1
    int tid = threadIdx.x;               // 256
    __shared__ float xs[512];
    __shared__ float zs[16];
    xs[tid]       = x[(size_t)row * 512 + tid];
    xs[tid + 256] = x[(size_t)row * 512 + tid + 256];
    __syncthreads();
    int warp = tid >> 5, lane = tid & 31;
#pragma unroll
    for (int jj = 0; jj < 2; jj++) {
        int j = warp * 2 + jj;
        float s = 0.f;
        for (int i = lane; i < 512; i += 32) s += xs[i] * W1[(size_t)j * 512 + i];
#pragma unroll
        for (int off = 16; off; off >>= 1) s += __shfl_down_sync(0xffffffffu, s, off);
        if (lane == 0) zs[j] = s;
    }
    __syncthreads();
    float acc = bias[tid];
#pragma unroll
    for (int j = 0; j < 16; j++) acc += zs[j] * W2[tid * 16 + j];
    float ls = fminf(acc, 0.f) - log1pf(expf(-fabsf(acc)));
    gk[(size_t)row * 256 + tid] = ls * (1.f / 16.f);
}

// ---------------- per-chunk: cumsum gk (in place), decay, U = k_dec^T @ v --
__global__ void chunk_state_kernel(const float* __restrict__ k, const float* __restrict__ v,
                                   float* __restrict__ gk, float* __restrict__ U,
                                   float* __restrict__ decay) {
    __shared__ float bc[64][65];
    __shared__ float kd[64][65];
    __shared__ float vt[16][132];
    __shared__ float blast[64];
    int ch = blockIdx.x;                      // B*N*H = 4096
    int h = ch % Hn;
    int n = (ch / Hn) % Nn;
    int b = ch / (Hn * Nn);
    int tid = threadIdx.x;                    // 256
    size_t rowbase = (size_t)b * Tn + (size_t)n * 64;

#pragma unroll
    for (int i = 0; i < 16; i++) {
        int e = tid + i * 256;
        int c = e >> 6, d = e & 63;
        bc[c][d] = gk[(rowbase + c) * 256 + h * 64 + d];
    }
    __syncthreads();
    if (tid < 64) {
        float s = 0.f;
#pragma unroll
        for (int c = 0; c < 64; c++) { s += bc[c][tid]; bc[c][tid] = s; }
        blast[tid] = s;
        decay[((size_t)((b * Hn + h) * Nn + n)) * 64 + tid] = expf(s);
    }
    __syncthreads();
#pragma unroll
    for (int i = 0; i < 16; i++) {
        int e = tid + i * 256;
        int c = e >> 6, d = e & 63;
        float bcv = bc[c][d];
        gk[(rowbase + c) * 256 + h * 64 + d] = bcv;  // write cumsum back
        kd[c][d] = k[(rowbase + c) * 256 + h * 64 + d] * expf(blast[d] - bcv);
    }
    __syncthreads();

    int d = tid >> 2, vg = tid & 3;
    float acc[32];
#pragma unroll
    for (int i = 0; i < 32; i++) acc[i] = 0.f;
    for (int c0 = 0; c0 < 64; c0 += 16) {
#pragma unroll
        for (int li = 0; li < 8; li++) {
            int e = tid + li * 256;
            int cc = e >> 7, vv = e & 127;
            vt[cc][vv] = v[(rowbase + c0 + cc) * 512 + h * 128 + vv];
        }
        __syncthreads();
#pragma unroll
        for (int cc = 0; cc < 16; cc++) {
            float kval = kd[c0 + cc][d];
#pragma unroll
            for (int i = 0; i < 32; i++) acc[i] += kval * vt[cc][vg + 4 * i];
        }
        __syncthreads();
    }
    size_t ubase = ((size_t)((b * Hn + h) * Nn + n)) * 8192 + (size_t)d * 128 + vg;
#pragma unroll
    for (int i = 0; i < 32; i++) U[ubase + 4 * i] = acc[i];
}

// ---------------- inter-chunk scan: S_init[j] stored in place over U -------
__global__ void scan_kernel(float* __restrict__ U, const float* __restrict__ decay) {
    int bh = blockIdx.x;                 // 32 = B*H
    int tid = threadIdx.x;               // 256
    float s[32];
#pragma unroll
    for (int i = 0; i < 32; i++) s[i] = 0.f;
    for (int n = 0; n < Nn; n++) {
        size_t base = ((size_t)bh * Nn + n) * 8192;
        const float* dec = decay + ((size_t)bh * Nn + n) * 64;
#pragma unroll
        for (int i = 0; i < 32; i++) {
            int e = tid + i * 256;
            float u = U[base + e];
            float dv = dec[e >> 7];
            U[base + e] = s[i];          // store state BEFORE this chunk
            s[i] = dv * s[i] + u;
        }
    }
}

// ---------------- per-chunk output: o = tril(q_e k_e^T) v + q_e S_init -----
__global__ void output_kernel(const float* __restrict__ q, const float* __restrict__ k,
                              const float* __restrict__ v, const float* __restrict__ gk,
                              const float* __restrict__ Sinit, float* __restrict__ o) {
    extern __shared__ float smem[];
    float (*qe)[65]  = (float(*)[65])smem;
    float (*ke)[65]  = (float(*)[65])(smem + 64 * 65);
    float (*Ash)[65] = (float(*)[65])(smem + 2 * 64 * 65);
    float (*vt)[132] = (float(*)[132])(smem + 3 * 64 * 65);
    int ch = blockIdx.x;
    int h = ch % Hn;
    int n = (ch / Hn) % Nn;
    int b = ch / (Hn * Nn);
    int tid = threadIdx.x;               // 256
    size_t rowbase = (size_t)b * Tn + (size_t)n * 64;
    const float scale = 0.125f;          // HK^-0.5

#pragma unroll
    for (int i = 0; i < 16; i++) {
        int e = tid + i * 256;
        int c = e >> 6, d = e & 63;
        float bcv = gk[(rowbase + c) * 256 + h * 64 + d];   // cumsummed
        float eb = expf(bcv);
        qe[c][d] = q[(rowbase + c) * 256 + h * 64 + d] * eb * scale;
        ke[c][d] = k[(rowbase + c) * 256 + h * 64 + d] * expf(-bcv);
    }
    __syncthreads();
    {
        int c = tid >> 2, eg = tid & 3;
#pragma unroll
        for (int j = 0; j < 16; j++) {
            int e = eg + 4 * j;
            float a = 0.f;
            if (e <= c) {
#pragma unroll
                for (int d = 0; d < 64; d++) a += qe[c][d] * ke[e][d];
            }
            Ash[c][e] = a;
        }
    }
    __syncthreads();

    int c = tid >> 2, vg = tid & 3;
    float acc[32];
#pragma unroll
    for (int i = 0; i < 32; i++) acc[i] = 0.f;

    // inter-chunk part: q_e @ S_init
    size_t sbase = ((size_t)((b * Hn + h) * Nn + n)) * 8192;
    for (int d0 = 0; d0 < 64; d0 += 16) {
#pragma unroll
        for (int li = 0; li < 8; li++) {
            int e = tid + li * 256;
            int dd = e >> 7, vv = e & 127;
            vt[dd][vv] = Sinit[sbase + (size_t)(d0 + dd) * 128 + vv];
        }
        __syncthreads();
#pragma unroll
        for (int dd = 0; dd < 16; dd++) {
            float qv = qe[c][d0 + dd];
#pragma unroll
            for (int i = 0; i < 32; i++) acc[i] += qv * vt[dd][vg + 4 * i];
        }
        __syncthreads();
    }
    // intra-chunk part: A @ v
    for (int e0 = 0; e0 < 64; e0 += 16) {
#pragma unroll
        for (int li = 0; li < 8; li++) {
            int e = tid + li * 256;
            int ee = e >> 7, vv = e & 127;
            vt[ee][vv] = v[(rowbase + e0 + ee) * 512 + h * 128 + vv];
        }
        __syncthreads();
#pragma unroll
        for (int ee = 0; ee < 16; ee++) {
            float a = Ash[c][e0 + ee];
#pragma unroll
            for (int i = 0; i < 32; i++) acc[i] += a * vt[ee][vg + 4 * i];
        }
        __syncthreads();
    }
    size_t obase = (rowbase + c) * 512 + h * 128 + vg;
#pragma unroll
    for (int i = 0; i < 32; i++) o[obase + 4 * i] = acc[i];
}

// ---------------- RMS-norm + SiLU gating (in place over o) -----------------
__global__ void gate_kernel(float* __restrict__ o, const float* __restrict__ g,
                            const float* __restrict__ gw) {
    int row = blockIdx.x;
    int tid = threadIdx.x;               // 512
    __shared__ float wsum[16];
    float ov = o[(size_t)row * 512 + tid];
    float sq = ov * ov;
#pragma unroll
    for (int off = 16; off; off >>= 1) sq += __shfl_down_sync(0xffffffffu, sq, off);
    if ((tid & 31) == 0) wsum[tid >> 5] = sq;
    __syncthreads();
    int h = tid >> 7;
    float ss = wsum[h * 4] + wsum[h * 4 + 1] + wsum[h * 4 + 2] + wsum[h * 4 + 3];
    float rms = rsqrtf(ss * (1.f / 128.f) + 1e-5f);
    float gv = g[(size_t)row * 512 + tid];
    float sig = 1.f / (1.f + expf(-gv));
    o[(size_t)row * 512 + tid] = ov * rms * gw[tid & 127] * gv * sig;
}

// ---------------- launcher --------------------------------------------------
extern "C" void kernel_launch(void* const* d_in, const int* in_sizes, int n_in,
                              void* d_out, int out_size) {
    const float* x    = (const float*)d_in[0];
    const float* Wq   = (const float*)d_in[1];
    const float* Wk   = (const float*)d_in[2];
    const float* Wv   = (const float*)d_in[3];
    const float* Wg   = (const float*)d_in[4];
    const float* Wgk1 = (const float*)d_in[5];
    const float* Wgk2 = (const float*)d_in[6];
    const float* bgk2 = (const float*)d_in[7];
    const float* gnw  = (const float*)d_in[8];
    const float* Wo   = (const float*)d_in[9];
    float* out = (float*)d_out;

    float *q, *k, *v, *g, *gk, *U, *dec, *o;
    cudaGetSymbolAddress((void**)&q,   g_q);
    cudaGetSymbolAddress((void**)&k,   g_k);
    cudaGetSymbolAddress((void**)&v,   g_v);
    cudaGetSymbolAddress((void**)&g,   g_g);
    cudaGetSymbolAddress((void**)&gk,  g_gk);
    cudaGetSymbolAddress((void**)&U,   g_U);
    cudaGetSymbolAddress((void**)&dec, g_dec);
    cudaGetSymbolAddress((void**)&o,   g_o);

    const int smem_out = (3 * 64 * 65 + 16 * 132) * 4;  // 58368 bytes
    cudaFuncSetAttribute(output_kernel, cudaFuncAttributeMaxDynamicSharedMemorySize, smem_out);

    // projections
    gemm_nt<<<dim3(BTn / 64, DKn / 64), 256>>>(x, Wq, q, BTn, DKn, Dn);
    gemm_nt<<<dim3(BTn / 64, DKn / 64), 256>>>(x, Wk, k, BTn, DKn, Dn);
    gemm_nt<<<dim3(BTn / 64, DVn / 64), 256>>>(x, Wv, v, BTn, DVn, Dn);
    gemm_nt<<<dim3(BTn / 64, DVn / 64), 256>>>(x, Wg, g, BTn, DVn, Dn);
    // low-rank log-sigmoid gate
    gk_kernel<<<BTn, 256>>>(x, Wgk1, Wgk2, bgk2, gk);
    // chunk-local state contributions + cumsum + decay
    chunk_state_kernel<<<Bn * Nn * Hn, 256>>>(k, v, gk, U, dec);
    // sequential inter-chunk scan (S_init stored in place over U)
    scan_kernel<<<Bn * Hn, 256>>>(U, dec);
    // chunk outputs
    output_kernel<<<Bn * Nn * Hn, 256, smem_out>>>(q, k, v, gk, U, o);
    // gating + RMS norm
    gate_kernel<<<BTn, 512>>>(o, g, gnw);
    // output projection
    gemm_nt<<<dim3(BTn / 64, DVn / 64), 256>>>(o, Wo, out, BTn, DVn, Dn);
}

// round 3
// speedup vs baseline: 2.8508x; 2.8508x over previous
#include <cuda_runtime.h>
#include <cuda_bf16.h>
#include <math.h>
#include <stdint.h>

// Problem constants
#define Bn 8
#define Tn 8192
#define Dn 512
#define Hn 4
#define DKn 256
#define DVn 512
#define HKn 64
#define HVn 128
#define Cn 64
#define Nn 128               // T / C
#define BTn (Bn * Tn)        // 65536
#define LOWn 16

// ---------------- scratch (device globals; no runtime allocation) ----------
__device__ float g_q[(size_t)BTn * DKn];
__device__ float g_k[(size_t)BTn * DKn];
__device__ float g_v[(size_t)BTn * DVn];
__device__ float g_g[(size_t)BTn * DVn];
__device__ float g_gk[(size_t)BTn * DKn];
__device__ float g_U[(size_t)Bn * Hn * Nn * HKn * HVn];
__device__ float g_dec[(size_t)Bn * Hn * Nn * HKn];
__device__ float g_o[(size_t)BTn * DVn];

// bf16 split buffers
__device__ __nv_bfloat16 g_xh[(size_t)BTn * Dn];
__device__ __nv_bfloat16 g_xl[(size_t)BTn * Dn];
__device__ __nv_bfloat16 g_oh[(size_t)BTn * DVn];
__device__ __nv_bfloat16 g_ol[(size_t)BTn * DVn];
__device__ __nv_bfloat16 g_wqh[DKn * Dn], g_wql[DKn * Dn];
__device__ __nv_bfloat16 g_wkh[DKn * Dn], g_wkl[DKn * Dn];
__device__ __nv_bfloat16 g_wvh[DVn * Dn], g_wvl[DVn * Dn];
__device__ __nv_bfloat16 g_wgh[DVn * Dn], g_wgl[DVn * Dn];
__device__ __nv_bfloat16 g_woh[Dn * DVn], g_wol[Dn * DVn];

// ================= warp-MMA helpers (baseline ISA: works on compute_103) ===
__device__ __forceinline__ uint32_t smem_u32(const void* p) {
    uint32_t a;
    asm("{ .reg .u64 t; cvta.to.shared.u64 t, %1; cvt.u32.u64 %0, t; }" : "=r"(a) : "l"(p));
    return a;
}
__device__ __forceinline__ void ldsm_x4(uint32_t addr, uint32_t* r) {
    asm volatile("ldmatrix.sync.aligned.m8n8.x4.shared.b16 {%0,%1,%2,%3}, [%4];"
                 : "=r"(r[0]), "=r"(r[1]), "=r"(r[2]), "=r"(r[3]) : "r"(addr));
}
__device__ __forceinline__ void mma16816(float* c, const uint32_t* a, const uint32_t* b) {
    asm volatile("mma.sync.aligned.m16n8k16.row.col.f32.bf16.bf16.f32 "
                 "{%0,%1,%2,%3}, {%4,%5,%6,%7}, {%8,%9}, {%0,%1,%2,%3};"
                 : "+f"(c[0]), "+f"(c[1]), "+f"(c[2]), "+f"(c[3])
                 : "r"(a[0]), "r"(a[1]), "r"(a[2]), "r"(a[3]), "r"(b[0]), "r"(b[1]));
}

// ============== tensor-core GEMM: C[m][n] = sum_k A[m][k]*B[n][k] ==========
// A,B are bf16 hi/lo splits, K-major row-major. CTA tile 128x128, BK=32.
// 8 warps: warp (mw = wid&1, nw = wid>>1) computes 64x32.
// 3-product split: Ah*Bh + Ah*Bl + Al*Bh with fp32 accumulation.
#define BKg 32
#define ASTR 40   // 32 + 8 pad (80B rows: 16B aligned, ldmatrix conflict-free)
__global__ void __launch_bounds__(256, 2) gemm_mma(
    const __nv_bfloat16* __restrict__ Ah, const __nv_bfloat16* __restrict__ Al,
    const __nv_bfloat16* __restrict__ Bh, const __nv_bfloat16* __restrict__ Bl,
    float* __restrict__ Cout, int M, int N, int K)
{
    __shared__ __nv_bfloat16 sAh[128][ASTR];
    __shared__ __nv_bfloat16 sAl[128][ASTR];
    __shared__ __nv_bfloat16 sBh[128][ASTR];
    __shared__ __nv_bfloat16 sBl[128][ASTR];

    int tid = threadIdx.x;
    int wid = tid >> 5, lane = tid & 31;
    int mw = wid & 1, nw = wid >> 1;          // warp tile: rows mw*64, cols nw*32
    int m0 = blockIdx.x * 128, n0 = blockIdx.y * 128;

    float acc[4][4][4];
#pragma unroll
    for (int i = 0; i < 4; i++)
#pragma unroll
        for (int j = 0; j < 4; j++)
#pragma unroll
            for (int t = 0; t < 4; t++) acc[i][j][t] = 0.f;

    // per-lane ldmatrix row/col geometry
    int a_row = mw * 64 + (lane & 7) + ((lane >> 3) & 1) * 8;    // + i*16
    int a_col = (lane >> 4) * 8;                                  // + kk
    int b_row = nw * 32 + (lane & 7) + ((lane >> 4) & 1) * 8;     // + p*16
    int b_col = ((lane >> 3) & 1) * 8;                            // + kk

    for (int kt = 0; kt < K; kt += BKg) {
        // ---- global -> smem: 4 tiles x 128 rows x 32 bf16 ----
#pragma unroll
        for (int j = 0; j < 8; j++) {
            int idx = tid + j * 256;
            int tile = idx >> 9;
            int ci = idx & 511;
            int row = ci >> 2;
            int cc = (ci & 3) * 8;
            if (tile == 0)
                *(uint4*)&sAh[row][cc] = *(const uint4*)(Ah + (size_t)(m0 + row) * K + kt + cc);
            else if (tile == 1)
                *(uint4*)&sAl[row][cc] = *(const uint4*)(Al + (size_t)(m0 + row) * K + kt + cc);
            else if (tile == 2)
                *(uint4*)&sBh[row][cc] = *(const uint4*)(Bh + (size_t)(n0 + row) * K + kt + cc);
            else
                *(uint4*)&sBl[row][cc] = *(const uint4*)(Bl + (size_t)(n0 + row) * K + kt + cc);
        }
        __syncthreads();

#pragma unroll
        for (int kk = 0; kk < BKg; kk += 16) {
            uint32_t af[4][4];
            // pass 1: A_hi x (B_hi + B_lo)
#pragma unroll
            for (int i = 0; i < 4; i++)
                ldsm_x4(smem_u32(&sAh[a_row + i * 16][a_col + kk]), af[i]);
#pragma unroll
            for (int p = 0; p < 2; p++) {
                uint32_t bh[4], bl[4];
                ldsm_x4(smem_u32(&sBh[b_row + p * 16][b_col + kk]), bh);
                ldsm_x4(smem_u32(&sBl[b_row + p * 16][b_col + kk]), bl);
#pragma unroll
                for (int i = 0; i < 4; i++) {
                    mma16816(acc[i][p * 2 + 0], af[i], bh);
                    mma16816(acc[i][p * 2 + 1], af[i], bh + 2);
                    mma16816(acc[i][p * 2 + 0], af[i], bl);
                    mma16816(acc[i][p * 2 + 1], af[i], bl + 2);
                }
            }
            // pass 2: A_lo x B_hi
#pragma unroll
            for (int i = 0; i < 4; i++)
                ldsm_x4(smem_u32(&sAl[a_row + i * 16][a_col + kk]), af[i]);
#pragma unroll
            for (int p = 0; p < 2; p++) {
                uint32_t bh[4];
                ldsm_x4(smem_u32(&sBh[b_row + p * 16][b_col + kk]), bh);
#pragma unroll
                for (int i = 0; i < 4; i++) {
                    mma16816(acc[i][p * 2 + 0], af[i], bh);
                    mma16816(acc[i][p * 2 + 1], af[i], bh + 2);
                }
            }
        }
        __syncthreads();
    }

    // ---- epilogue: c0,c1 -> row, c2,c3 -> row+8; cols (lane&3)*2 ----
    int erow = m0 + mw * 64 + (lane >> 2);
    int ecol = n0 + nw * 32 + (lane & 3) * 2;
#pragma unroll
    for (int i = 0; i < 4; i++) {
#pragma unroll
        for (int nt = 0; nt < 4; nt++) {
            float* c = acc[i][nt];
            float2 v01 = make_float2(c[0], c[1]);
            float2 v23 = make_float2(c[2], c[3]);
            size_t r0 = (size_t)(erow + i * 16) * N + ecol + nt * 8;
            size_t r1 = (size_t)(erow + i * 16 + 8) * N + ecol + nt * 8;
            *(float2*)(Cout + r0) = v01;
            *(float2*)(Cout + r1) = v23;
        }
    }
}

// ============== fp32 -> bf16 hi/lo split ===================================
__global__ void conv_split(const float* __restrict__ src, __nv_bfloat16* __restrict__ hi,
                           __nv_bfloat16* __restrict__ lo, size_t n) {
    size_t i = (size_t)blockIdx.x * blockDim.x + threadIdx.x;
    size_t stride = (size_t)gridDim.x * blockDim.x;
    for (; i < n; i += stride) {
        float v = src[i];
        __nv_bfloat16 h = __float2bfloat16(v);
        hi[i] = h;
        lo[i] = __float2bfloat16(v - __bfloat162float(h));
    }
}

// ---------------- low-rank gate: 16 rows per block -------------------------
__global__ void gk2_kernel(const float* __restrict__ x, const float* __restrict__ W1,
                           const float* __restrict__ W2, const float* __restrict__ bias,
                           float* __restrict__ gk) {
    extern __shared__ float sm[];
    float (*W1s)[516] = (float(*)[516])sm;
    float (*xs)[516]  = (float(*)[516])(sm + 16 * 516);
    float (*zs)[17]   = (float(*)[17])(sm + 32 * 516);
    int tid = threadIdx.x;                               // 256
    size_t row0 = (size_t)blockIdx.x * 16;

#pragma unroll
    for (int j = 0; j < 8; j++) {
        int e = (tid + j * 256) * 4;
        int r = e >> 9, c = e & 511;
        float4 w4 = *(const float4*)(W1 + (size_t)r * 512 + c);
        W1s[r][c] = w4.x; W1s[r][c + 1] = w4.y; W1s[r][c + 2] = w4.z; W1s[r][c + 3] = w4.w;
        float4 x4 = *(const float4*)(x + (row0 + r) * 512 + c);
        xs[r][c] = x4.x; xs[r][c + 1] = x4.y; xs[r][c + 2] = x4.z; xs[r][c + 3] = x4.w;
    }
    __syncthreads();
    {
        int r = tid >> 4, j = tid & 15;
        float s = 0.f;
#pragma unroll 8
        for (int i = 0; i < 512; i++) s += xs[r][i] * W1s[j][i];
        zs[r][j] = s;
    }
    __syncthreads();
    {
        int d = tid;
        float w2r[16];
#pragma unroll
        for (int q4 = 0; q4 < 4; q4++) {
            float4 w4 = *(const float4*)(W2 + (size_t)d * 16 + q4 * 4);
            w2r[q4 * 4] = w4.x; w2r[q4 * 4 + 1] = w4.y; w2r[q4 * 4 + 2] = w4.z; w2r[q4 * 4 + 3] = w4.w;
        }
        float b = bias[d];
#pragma unroll
        for (int r = 0; r < 16; r++) {
            float a = b;
#pragma unroll
            for (int j = 0; j < 16; j++) a += zs[r][j] * w2r[j];
            float ls = fminf(a, 0.f) - log1pf(expf(-fabsf(a)));
            gk[(row0 + r) * 256 + d] = ls * (1.f / 16.f);
        }
    }
}

// ---------------- per-chunk: cumsum gk (in place), decay, U = k_dec^T @ v --
__global__ void chunk_state_kernel(const float* __restrict__ k, const float* __restrict__ v,
                                   float* __restrict__ gk, float* __restrict__ U,
                                   float* __restrict__ decay) {
    __shared__ float bc[64][65];
    __shared__ float kd[64][65];
    __shared__ float vt[16][132];
    __shared__ float blast[64];
    int ch = blockIdx.x;                      // B*N*H = 4096
    int h = ch % Hn;
    int n = (ch / Hn) % Nn;
    int b = ch / (Hn * Nn);
    int tid = threadIdx.x;                    // 256
    size_t rowbase = (size_t)b * Tn + (size_t)n * 64;

#pragma unroll
    for (int i = 0; i < 16; i++) {
        int e = tid + i * 256;
        int c = e >> 6, d = e & 63;
        bc[c][d] = gk[(rowbase + c) * 256 + h * 64 + d];
    }
    __syncthreads();
    if (tid < 64) {
        float s = 0.f;
#pragma unroll
        for (int c = 0; c < 64; c++) { s += bc[c][tid]; bc[c][tid] = s; }
        blast[tid] = s;
        decay[((size_t)((b * Hn + h) * Nn + n)) * 64 + tid] = expf(s);
    }
    __syncthreads();
#pragma unroll
    for (int i = 0; i < 16; i++) {
        int e = tid + i * 256;
        int c = e >> 6, d = e & 63;
        float bcv = bc[c][d];
        gk[(rowbase + c) * 256 + h * 64 + d] = bcv;
        kd[c][d] = k[(rowbase + c) * 256 + h * 64 + d] * expf(blast[d] - bcv);
    }
    __syncthreads();

    int d = tid >> 2, vg = tid & 3;
    float acc[32];
#pragma unroll
    for (int i = 0; i < 32; i++) acc[i] = 0.f;
    for (int c0 = 0; c0 < 64; c0 += 16) {
#pragma unroll
        for (int li = 0; li < 8; li++) {
            int e = tid + li * 256;
            int cc = e >> 7, vv = e & 127;
            vt[cc][vv] = v[(rowbase + c0 + cc) * 512 + h * 128 + vv];
        }
        __syncthreads();
#pragma unroll
        for (int cc = 0; cc < 16; cc++) {
            float kval = kd[c0 + cc][d];
#pragma unroll
            for (int i = 0; i < 32; i++) acc[i] += kval * vt[cc][vg + 4 * i];
        }
        __syncthreads();
    }
    size_t ubase = ((size_t)((b * Hn + h) * Nn + n)) * 8192 + (size_t)d * 128 + vg;
#pragma unroll
    for (int i = 0; i < 32; i++) U[ubase + 4 * i] = acc[i];
}

// ---------------- inter-chunk scan (parallel over elements) ----------------
__global__ void scan_kernel(float* __restrict__ U, const float* __restrict__ decay) {
    int bh = blockIdx.x >> 5;                         // 32 bh, 32 parts each
    int e = ((blockIdx.x & 31) << 8) + threadIdx.x;   // 0..8191
    float s = 0.f;
    size_t base = (size_t)bh * Nn * 8192 + e;
    const float* dp = decay + (size_t)bh * Nn * 64 + (e >> 7);
    for (int n = 0; n < Nn; n++) {
        float u = U[base];
        U[base] = s;                                  // state BEFORE this chunk
        s = dp[0] * s + u;
        base += 8192; dp += 64;
    }
}

// ---------------- per-chunk output: o = tril(q_e k_e^T) v + q_e S_init -----
__global__ void output_kernel(const float* __restrict__ q, const float* __restrict__ k,
                              const float* __restrict__ v, const float* __restrict__ gk,
                              const float* __restrict__ Sinit, float* __restrict__ o) {
    extern __shared__ float smemf[];
    float (*qe)[65]  = (float(*)[65])smemf;
    float (*ke)[65]  = (float(*)[65])(smemf + 64 * 65);
    float (*Ash)[65] = (float(*)[65])(smemf + 2 * 64 * 65);
    float (*vt)[132] = (float(*)[132])(smemf + 3 * 64 * 65);
    int ch = blockIdx.x;
    int h = ch % Hn;
    int n = (ch / Hn) % Nn;
    int b = ch / (Hn * Nn);
    int tid = threadIdx.x;               // 256
    size_t rowbase = (size_t)b * Tn + (size_t)n * 64;
    const float scale = 0.125f;

#pragma unroll
    for (int i = 0; i < 16; i++) {
        int e = tid + i * 256;
        int c = e >> 6, d = e & 63;
        float bcv = gk[(rowbase + c) * 256 + h * 64 + d];
        float eb = expf(bcv);
        qe[c][d] = q[(rowbase + c) * 256 + h * 64 + d] * eb * scale;
        ke[c][d] = k[(rowbase + c) * 256 + h * 64 + d] * expf(-bcv);
    }
    __syncthreads();
    {
        int c = tid >> 2, eg = tid & 3;
#pragma unroll
        for (int j = 0; j < 16; j++) {
            int e = eg + 4 * j;
            float a = 0.f;
            if (e <= c) {
#pragma unroll
                for (int d = 0; d < 64; d++) a += qe[c][d] * ke[e][d];
            }
            Ash[c][e] = a;
        }
    }
    __syncthreads();

    int c = tid >> 2, vg = tid & 3;
    float acc[32];
#pragma unroll
    for (int i = 0; i < 32; i++) acc[i] = 0.f;

    size_t sbase = ((size_t)((b * Hn + h) * Nn + n)) * 8192;
    for (int d0 = 0; d0 < 64; d0 += 16) {
#pragma unroll
        for (int li = 0; li < 8; li++) {
            int e = tid + li * 256;
            int dd = e >> 7, vv = e & 127;
            vt[dd][vv] = Sinit[sbase + (size_t)(d0 + dd) * 128 + vv];
        }
        __syncthreads();
#pragma unroll
        for (int dd = 0; dd < 16; dd++) {
            float qv = qe[c][d0 + dd];
#pragma unroll
            for (int i = 0; i < 32; i++) acc[i] += qv * vt[dd][vg + 4 * i];
        }
        __syncthreads();
    }
    for (int e0 = 0; e0 < 64; e0 += 16) {
#pragma unroll
        for (int li = 0; li < 8; li++) {
            int e = tid + li * 256;
            int ee = e >> 7, vv = e & 127;
            vt[ee][vv] = v[(rowbase + e0 + ee) * 512 + h * 128 + vv];
        }
        __syncthreads();
#pragma unroll
        for (int ee = 0; ee < 16; ee++) {
            float a = Ash[c][e0 + ee];
#pragma unroll
            for (int i = 0; i < 32; i++) acc[i] += a * vt[ee][vg + 4 * i];
        }
        __syncthreads();
    }
    size_t obase = (rowbase + c) * 512 + h * 128 + vg;
#pragma unroll
    for (int i = 0; i < 32; i++) o[obase + 4 * i] = acc[i];
}

// ---------------- RMS-norm + SiLU gating -> bf16 hi/lo ---------------------
__global__ void gate_kernel(const float* __restrict__ o, const float* __restrict__ g,
                            const float* __restrict__ gw,
                            __nv_bfloat16* __restrict__ oh, __nv_bfloat16* __restrict__ ol) {
    int row = blockIdx.x;
    int tid = threadIdx.x;               // 512
    __shared__ float wsum[16];
    size_t idx = (size_t)row * 512 + tid;
    float ov = o[idx];
    float sq = ov * ov;
#pragma unroll
    for (int off = 16; off; off >>= 1) sq += __shfl_down_sync(0xffffffffu, sq, off);
    if ((tid & 31) == 0) wsum[tid >> 5] = sq;
    __syncthreads();
    int h = tid >> 7;
    float ss = wsum[h * 4] + wsum[h * 4 + 1] + wsum[h * 4 + 2] + wsum[h * 4 + 3];
    float rms = rsqrtf(ss * (1.f / 128.f) + 1e-5f);
    float gv = g[idx];
    float sig = 1.f / (1.f + expf(-gv));
    float val = ov * rms * gw[tid & 127] * gv * sig;
    __nv_bfloat16 hh = __float2bfloat16(val);
    oh[idx] = hh;
    ol[idx] = __float2bfloat16(val - __bfloat162float(hh));
}

// ---------------- launcher --------------------------------------------------
extern "C" void kernel_launch(void* const* d_in, const int* in_sizes, int n_in,
                              void* d_out, int out_size) {
    const float* x    = (const float*)d_in[0];
    const float* Wq   = (const float*)d_in[1];
    const float* Wk   = (const float*)d_in[2];
    const float* Wv   = (const float*)d_in[3];
    const float* Wg   = (const float*)d_in[4];
    const float* Wgk1 = (const float*)d_in[5];
    const float* Wgk2 = (const float*)d_in[6];
    const float* bgk2 = (const float*)d_in[7];
    const float* gnw  = (const float*)d_in[8];
    const float* Wo   = (const float*)d_in[9];
    float* out = (float*)d_out;

    float *q, *k, *v, *g, *gk, *U, *dec, *o;
    cudaGetSymbolAddress((void**)&q,   g_q);
    cudaGetSymbolAddress((void**)&k,   g_k);
    cudaGetSymbolAddress((void**)&v,   g_v);
    cudaGetSymbolAddress((void**)&g,   g_g);
    cudaGetSymbolAddress((void**)&gk,  g_gk);
    cudaGetSymbolAddress((void**)&U,   g_U);
    cudaGetSymbolAddress((void**)&dec, g_dec);
    cudaGetSymbolAddress((void**)&o,   g_o);

    __nv_bfloat16 *xh, *xl, *oh, *ol;
    __nv_bfloat16 *wqh, *wql, *wkh, *wkl, *wvh, *wvl, *wgh, *wgl, *woh, *wol;
    cudaGetSymbolAddress((void**)&xh, g_xh);   cudaGetSymbolAddress((void**)&xl, g_xl);
    cudaGetSymbolAddress((void**)&oh, g_oh);   cudaGetSymbolAddress((void**)&ol, g_ol);
    cudaGetSymbolAddress((void**)&wqh, g_wqh); cudaGetSymbolAddress((void**)&wql, g_wql);
    cudaGetSymbolAddress((void**)&wkh, g_wkh); cudaGetSymbolAddress((void**)&wkl, g_wkl);
    cudaGetSymbolAddress((void**)&wvh, g_wvh); cudaGetSymbolAddress((void**)&wvl, g_wvl);
    cudaGetSymbolAddress((void**)&wgh, g_wgh); cudaGetSymbolAddress((void**)&wgl, g_wgl);
    cudaGetSymbolAddress((void**)&woh, g_woh); cudaGetSymbolAddress((void**)&wol, g_wol);

    const int smem_out = (3 * 64 * 65 + 16 * 132) * 4;
    cudaFuncSetAttribute(output_kernel, cudaFuncAttributeMaxDynamicSharedMemorySize, smem_out);
    const int smem_gk = (32 * 516 + 16 * 17) * 4;
    cudaFuncSetAttribute(gk2_kernel, cudaFuncAttributeMaxDynamicSharedMemorySize, smem_gk);

    // bf16 splits
    conv_split<<<2048, 256>>>(x, xh, xl, (size_t)BTn * Dn);
    conv_split<<<256, 256>>>(Wq, wqh, wql, (size_t)DKn * Dn);
    conv_split<<<256, 256>>>(Wk, wkh, wkl, (size_t)DKn * Dn);
    conv_split<<<512, 256>>>(Wv, wvh, wvl, (size_t)DVn * Dn);
    conv_split<<<512, 256>>>(Wg, wgh, wgl, (size_t)DVn * Dn);
    conv_split<<<512, 256>>>(Wo, woh, wol, (size_t)Dn * DVn);

    // projections on tensor cores (HMMA)
    gemm_mma<<<dim3(BTn / 128, DKn / 128), 256>>>(xh, xl, wqh, wql, q, BTn, DKn, Dn);
    gemm_mma<<<dim3(BTn / 128, DKn / 128), 256>>>(xh, xl, wkh, wkl, k, BTn, DKn, Dn);
    gemm_mma<<<dim3(BTn / 128, DVn / 128), 256>>>(xh, xl, wvh, wvl, v, BTn, DVn, Dn);
    gemm_mma<<<dim3(BTn / 128, DVn / 128), 256>>>(xh, xl, wgh, wgl, g, BTn, DVn, Dn);

    // low-rank log-sigmoid gate
    gk2_kernel<<<BTn / 16, 256, smem_gk>>>(x, Wgk1, Wgk2, bgk2, gk);
    // chunk-local state contributions + cumsum + decay
    chunk_state_kernel<<<Bn * Nn * Hn, 256>>>(k, v, gk, U, dec);
    // parallel inter-chunk scan
    scan_kernel<<<Bn * Hn * 32, 256>>>(U, dec);
    // chunk outputs
    output_kernel<<<Bn * Nn * Hn, 256, smem_out>>>(q, k, v, gk, U, o);
    // gating + RMS norm -> bf16 split of o
    gate_kernel<<<BTn, 512>>>(o, g, gnw, oh, ol);
    // output projection on tensor cores
    gemm_mma<<<dim3(BTn / 128, DVn / 128), 256>>>(oh, ol, woh, wol, out, BTn, DVn, Dn);
}

// round 4
// speedup vs baseline: 3.1256x; 1.0964x over previous
#include <cuda_runtime.h>
#include <cuda_bf16.h>
#include <math.h>
#include <stdint.h>

// Problem constants
#define Bn 8
#define Tn 8192
#define Dn 512
#define Hn 4
#define DKn 256
#define DVn 512
#define HKn 64
#define HVn 128
#define Cn 64
#define Nn 128               // T / C
#define BTn (Bn * Tn)        // 65536
#define LOWn 16

// ---------------- scratch (device globals; no runtime allocation) ----------
__device__ float g_q[(size_t)BTn * DKn];
__device__ float g_k[(size_t)BTn * DKn];
__device__ float g_v[(size_t)BTn * DVn];
__device__ float g_g[(size_t)BTn * DVn];
__device__ float g_gk[(size_t)BTn * DKn];
__device__ float g_U[(size_t)Bn * Hn * Nn * HKn * HVn];
__device__ float g_dec[(size_t)Bn * Hn * Nn * HKn];
__device__ float g_o[(size_t)BTn * DVn];

// bf16 split buffers
__device__ __nv_bfloat16 g_xh[(size_t)BTn * Dn];
__device__ __nv_bfloat16 g_xl[(size_t)BTn * Dn];
__device__ __nv_bfloat16 g_oh[(size_t)BTn * DVn];
__device__ __nv_bfloat16 g_ol[(size_t)BTn * DVn];
__device__ __nv_bfloat16 g_wqh[DKn * Dn], g_wql[DKn * Dn];
__device__ __nv_bfloat16 g_wkh[DKn * Dn], g_wkl[DKn * Dn];
__device__ __nv_bfloat16 g_wvh[DVn * Dn], g_wvl[DVn * Dn];
__device__ __nv_bfloat16 g_wgh[DVn * Dn], g_wgl[DVn * Dn];
__device__ __nv_bfloat16 g_woh[Dn * DVn], g_wol[Dn * DVn];

// ================= warp-MMA helpers (baseline ISA: works on compute_103) ===
__device__ __forceinline__ uint32_t smem_u32(const void* p) {
    uint32_t a;
    asm("{ .reg .u64 t; cvta.to.shared.u64 t, %1; cvt.u32.u64 %0, t; }" : "=r"(a) : "l"(p));
    return a;
}
__device__ __forceinline__ void ldsm_x4(uint32_t addr, uint32_t* r) {
    asm volatile("ldmatrix.sync.aligned.m8n8.x4.shared.b16 {%0,%1,%2,%3}, [%4];"
                 : "=r"(r[0]), "=r"(r[1]), "=r"(r[2]), "=r"(r[3]) : "r"(addr));
}
__device__ __forceinline__ void mma16816(float* c, const uint32_t* a, const uint32_t* b) {
    asm volatile("mma.sync.aligned.m16n8k16.row.col.f32.bf16.bf16.f32 "
                 "{%0,%1,%2,%3}, {%4,%5,%6,%7}, {%8,%9}, {%0,%1,%2,%3};"
                 : "+f"(c[0]), "+f"(c[1]), "+f"(c[2]), "+f"(c[3])
                 : "r"(a[0]), "r"(a[1]), "r"(a[2]), "r"(a[3]), "r"(b[0]), "r"(b[1]));
}
__device__ __forceinline__ void cp16(uint32_t s, const void* g) {
    asm volatile("cp.async.cg.shared.global [%0], [%1], 16;" :: "r"(s), "l"(g));
}

// ============== tensor-core GEMM: C[m][n] = sum_k A[m][k]*B[n][k] ==========
// A,B bf16 hi/lo splits, K-major row-major. CTA tile 128x128, BK=32,
// cp.async 2-stage pipeline. 8 warps: warp (mw=wid&1, nw=wid>>1) = 64x32.
// 3-product split: Ah*Bh + Ah*Bl + Al*Bh with fp32 accumulation.
#define BKg 32
#define ROWB 80u                         // bytes per smem row (32 bf16 + 8 pad)
#define TILEB 10240u                     // 128 rows * 80B
#define STAGEB 40960u                    // 4 tiles
__global__ void __launch_bounds__(256, 2) gemm_mma(
    const __nv_bfloat16* __restrict__ Ah, const __nv_bfloat16* __restrict__ Al,
    const __nv_bfloat16* __restrict__ Bh, const __nv_bfloat16* __restrict__ Bl,
    float* __restrict__ Cout, int M, int N, int K)
{
    extern __shared__ char smem[];
    uint32_t sbase = smem_u32(smem);

    int tid = threadIdx.x;
    int wid = tid >> 5, lane = tid & 31;
    int mw = wid & 1, nw = wid >> 1;
    int m0 = blockIdx.x * 128, n0 = blockIdx.y * 128;

    float acc[4][4][4];
#pragma unroll
    for (int i = 0; i < 4; i++)
#pragma unroll
        for (int j = 0; j < 4; j++)
#pragma unroll
            for (int t = 0; t < 4; t++) acc[i][j][t] = 0.f;

    // per-thread load descriptors: 8 x 16B chunks per stage
    const __nv_bfloat16* gptr[8];
    uint32_t soff8[8];
#pragma unroll
    for (int j = 0; j < 8; j++) {
        int idx = tid + j * 256;
        int tile = idx >> 9;              // 0..3
        int ci = idx & 511;
        int row = ci >> 2;
        int c16 = ci & 3;                 // 16B chunk in row
        soff8[j] = (uint32_t)tile * TILEB + (uint32_t)row * ROWB + (uint32_t)c16 * 16u;
        const __nv_bfloat16* base = (tile == 0) ? Ah : (tile == 1) ? Al : (tile == 2) ? Bh : Bl;
        int grow = (tile < 2) ? (m0 + row) : (n0 + row);
        gptr[j] = base + (size_t)grow * K + c16 * 8;
    }

    // ldmatrix geometry
    int a_row = mw * 64 + (lane & 7) + ((lane >> 3) & 1) * 8;
    int a_col = (lane >> 4) * 8;
    int b_row = nw * 32 + (lane & 7) + ((lane >> 4) & 1) * 8;
    int b_col = ((lane >> 3) & 1) * 8;
    uint32_t a_off[4], b_off[2];
#pragma unroll
    for (int i = 0; i < 4; i++) a_off[i] = (uint32_t)(a_row + i * 16) * ROWB + (uint32_t)a_col * 2u;
#pragma unroll
    for (int p = 0; p < 2; p++) b_off[p] = (uint32_t)(b_row + p * 16) * ROWB + (uint32_t)b_col * 2u;

    const int nkt = K / BKg;

    // prologue: stage 0
#pragma unroll
    for (int j = 0; j < 8; j++) cp16(sbase + soff8[j], gptr[j]);
    asm volatile("cp.async.commit_group;" ::: "memory");

    for (int kt = 0; kt < nkt; kt++) {
        if (kt + 1 < nkt) {
            uint32_t sb2 = sbase + (uint32_t)((kt + 1) & 1) * STAGEB;
            int k0n = (kt + 1) * BKg;
#pragma unroll
            for (int j = 0; j < 8; j++) cp16(sb2 + soff8[j], gptr[j] + k0n);
            asm volatile("cp.async.commit_group;" ::: "memory");
            asm volatile("cp.async.wait_group 1;" ::: "memory");
        } else {
            asm volatile("cp.async.wait_group 0;" ::: "memory");
        }
        __syncthreads();

        uint32_t stB = sbase + (uint32_t)(kt & 1) * STAGEB;
#pragma unroll
        for (int kk = 0; kk < BKg; kk += 16) {
            uint32_t koff = (uint32_t)kk * 2u;
            uint32_t af[4][4];
            // pass 1: A_hi x (B_hi + B_lo)
#pragma unroll
            for (int i = 0; i < 4; i++)
                ldsm_x4(stB + 0 * TILEB + a_off[i] + koff, af[i]);
#pragma unroll
            for (int p = 0; p < 2; p++) {
                uint32_t bh[4], bl[4];
                ldsm_x4(stB + 2 * TILEB + b_off[p] + koff, bh);
                ldsm_x4(stB + 3 * TILEB + b_off[p] + koff, bl);
#pragma unroll
                for (int i = 0; i < 4; i++) {
                    mma16816(acc[i][p * 2 + 0], af[i], bh);
                    mma16816(acc[i][p * 2 + 1], af[i], bh + 2);
                    mma16816(acc[i][p * 2 + 0], af[i], bl);
                    mma16816(acc[i][p * 2 + 1], af[i], bl + 2);
                }
            }
            // pass 2: A_lo x B_hi
#pragma unroll
            for (int i = 0; i < 4; i++)
                ldsm_x4(stB + 1 * TILEB + a_off[i] + koff, af[i]);
#pragma unroll
            for (int p = 0; p < 2; p++) {
                uint32_t bh[4];
                ldsm_x4(stB + 2 * TILEB + b_off[p] + koff, bh);
#pragma unroll
                for (int i = 0; i < 4; i++) {
                    mma16816(acc[i][p * 2 + 0], af[i], bh);
                    mma16816(acc[i][p * 2 + 1], af[i], bh + 2);
                }
            }
        }
        __syncthreads();
    }

    // epilogue
    int erow = m0 + mw * 64 + (lane >> 2);
    int ecol = n0 + nw * 32 + (lane & 3) * 2;
#pragma unroll
    for (int i = 0; i < 4; i++) {
#pragma unroll
        for (int nt = 0; nt < 4; nt++) {
            float* c = acc[i][nt];
            size_t r0 = (size_t)(erow + i * 16) * N + ecol + nt * 8;
            size_t r1 = (size_t)(erow + i * 16 + 8) * N + ecol + nt * 8;
            *(float2*)(Cout + r0) = make_float2(c[0], c[1]);
            *(float2*)(Cout + r1) = make_float2(c[2], c[3]);
        }
    }
}

// ============== fp32 -> bf16 hi/lo split (vectorized) ======================
__device__ __forceinline__ void split4_store(float4 v, __nv_bfloat16* hi, __nv_bfloat16* lo,
                                             size_t i4) {
    __nv_bfloat16 h0 = __float2bfloat16(v.x), h1 = __float2bfloat16(v.y);
    __nv_bfloat16 h2 = __float2bfloat16(v.z), h3 = __float2bfloat16(v.w);
    __nv_bfloat16 l0 = __float2bfloat16(v.x - __bfloat162float(h0));
    __nv_bfloat16 l1 = __float2bfloat16(v.y - __bfloat162float(h1));
    __nv_bfloat16 l2 = __float2bfloat16(v.z - __bfloat162float(h2));
    __nv_bfloat16 l3 = __float2bfloat16(v.w - __bfloat162float(h3));
    uint2 ph, pl;
    ph.x = ((uint32_t)__bfloat16_as_ushort(h1) << 16) | __bfloat16_as_ushort(h0);
    ph.y = ((uint32_t)__bfloat16_as_ushort(h3) << 16) | __bfloat16_as_ushort(h2);
    pl.x = ((uint32_t)__bfloat16_as_ushort(l1) << 16) | __bfloat16_as_ushort(l0);
    pl.y = ((uint32_t)__bfloat16_as_ushort(l3) << 16) | __bfloat16_as_ushort(l2);
    *(uint2*)(hi + i4) = ph;
    *(uint2*)(lo + i4) = pl;
}

__global__ void conv_split4(const float* __restrict__ src, __nv_bfloat16* __restrict__ hi,
                            __nv_bfloat16* __restrict__ lo, size_t n4) {
    size_t i = (size_t)blockIdx.x * blockDim.x + threadIdx.x;
    size_t stride = (size_t)gridDim.x * blockDim.x;
    for (; i < n4; i += stride) {
        float4 v = *(const float4*)(src + i * 4);
        split4_store(v, hi, lo, i * 4);
    }
}

// all 5 weight matrices in one kernel (1,048,576 elems = 262,144 float4)
__global__ void conv_w_all(const float* __restrict__ Wq, const float* __restrict__ Wk,
                           const float* __restrict__ Wv, const float* __restrict__ Wg,
                           const float* __restrict__ Wo,
                           __nv_bfloat16* __restrict__ wqh, __nv_bfloat16* __restrict__ wql,
                           __nv_bfloat16* __restrict__ wkh, __nv_bfloat16* __restrict__ wkl,
                           __nv_bfloat16* __restrict__ wvh, __nv_bfloat16* __restrict__ wvl,
                           __nv_bfloat16* __restrict__ wgh, __nv_bfloat16* __restrict__ wgl,
                           __nv_bfloat16* __restrict__ woh, __nv_bfloat16* __restrict__ wol) {
    size_t i = (size_t)blockIdx.x * blockDim.x + threadIdx.x;   // float4 index, exact grid
    const float* src; __nv_bfloat16 *hi, *lo; size_t off;
    if (i < 32768)        { src = Wq; hi = wqh; lo = wql; off = i; }
    else if (i < 65536)   { src = Wk; hi = wkh; lo = wkl; off = i - 32768; }
    else if (i < 131072)  { src = Wv; hi = wvh; lo = wvl; off = i - 65536; }
    else if (i < 196608)  { src = Wg; hi = wgh; lo = wgl; off = i - 131072; }
    else                  { src = Wo; hi = woh; lo = wol; off = i - 196608; }
    float4 v = *(const float4*)(src + off * 4);
    split4_store(v, hi, lo, off * 4);
}

// ---------------- low-rank gate: 16 rows per block -------------------------
__global__ void gk2_kernel(const float* __restrict__ x, const float* __restrict__ W1,
                           const float* __restrict__ W2, const float* __restrict__ bias,
                           float* __restrict__ gk) {
    extern __shared__ float sm[];
    float (*W1s)[516] = (float(*)[516])sm;
    float (*xs)[516]  = (float(*)[516])(sm + 16 * 516);
    float (*zs)[17]   = (float(*)[17])(sm + 32 * 516);
    int tid = threadIdx.x;                               // 256
    size_t row0 = (size_t)blockIdx.x * 16;

#pragma unroll
    for (int j = 0; j < 8; j++) {
        int e = (tid + j * 256) * 4;
        int r = e >> 9, c = e & 511;
        float4 w4 = *(const float4*)(W1 + (size_t)r * 512 + c);
        W1s[r][c] = w4.x; W1s[r][c + 1] = w4.y; W1s[r][c + 2] = w4.z; W1s[r][c + 3] = w4.w;
        float4 x4 = *(const float4*)(x + (row0 + r) * 512 + c);
        xs[r][c] = x4.x; xs[r][c + 1] = x4.y; xs[r][c + 2] = x4.z; xs[r][c + 3] = x4.w;
    }
    __syncthreads();
    {
        int r = tid >> 4, j = tid & 15;
        float s = 0.f;
#pragma unroll 8
        for (int i = 0; i < 512; i++) s += xs[r][i] * W1s[j][i];
        zs[r][j] = s;
    }
    __syncthreads();
    {
        int d = tid;
        float w2r[16];
#pragma unroll
        for (int q4 = 0; q4 < 4; q4++) {
            float4 w4 = *(const float4*)(W2 + (size_t)d * 16 + q4 * 4);
            w2r[q4 * 4] = w4.x; w2r[q4 * 4 + 1] = w4.y; w2r[q4 * 4 + 2] = w4.z; w2r[q4 * 4 + 3] = w4.w;
        }
        float b = bias[d];
#pragma unroll
        for (int r = 0; r < 16; r++) {
            float a = b;
#pragma unroll
            for (int j = 0; j < 16; j++) a += zs[r][j] * w2r[j];
            float ls = fminf(a, 0.f) - log1pf(expf(-fabsf(a)));
            gk[(row0 + r) * 256 + d] = ls * (1.f / 16.f);
        }
    }
}

// ---------------- per-chunk: cumsum gk (in place), decay, U = k_dec^T @ v --
__global__ void chunk_state_kernel(const float* __restrict__ k, const float* __restrict__ v,
                                   float* __restrict__ gk, float* __restrict__ U,
                                   float* __restrict__ decay) {
    __shared__ float bc[64][65];
    __shared__ float kd[64][65];
    __shared__ float vt[16][132];
    __shared__ float blast[64];
    int ch = blockIdx.x;                      // B*N*H = 4096
    int h = ch % Hn;
    int n = (ch / Hn) % Nn;
    int b = ch / (Hn * Nn);
    int tid = threadIdx.x;                    // 256
    size_t rowbase = (size_t)b * Tn + (size_t)n * 64;

#pragma unroll
    for (int i = 0; i < 16; i++) {
        int e = tid + i * 256;
        int c = e >> 6, d = e & 63;
        bc[c][d] = gk[(rowbase + c) * 256 + h * 64 + d];
    }
    __syncthreads();
    if (tid < 64) {
        float s = 0.f;
#pragma unroll
        for (int c = 0; c < 64; c++) { s += bc[c][tid]; bc[c][tid] = s; }
        blast[tid] = s;
        decay[((size_t)((b * Hn + h) * Nn + n)) * 64 + tid] = expf(s);
    }
    __syncthreads();
#pragma unroll
    for (int i = 0; i < 16; i++) {
        int e = tid + i * 256;
        int c = e >> 6, d = e & 63;
        float bcv = bc[c][d];
        gk[(rowbase + c) * 256 + h * 64 + d] = bcv;
        kd[c][d] = k[(rowbase + c) * 256 + h * 64 + d] * expf(blast[d] - bcv);
    }
    __syncthreads();

    int d = tid >> 2, vg = tid & 3;
    float acc[32];
#pragma unroll
    for (int i = 0; i < 32; i++) acc[i] = 0.f;
    for (int c0 = 0; c0 < 64; c0 += 16) {
#pragma unroll
        for (int li = 0; li < 8; li++) {
            int e = tid + li * 256;
            int cc = e >> 7, vv = e & 127;
            vt[cc][vv] = v[(rowbase + c0 + cc) * 512 + h * 128 + vv];
        }
        __syncthreads();
#pragma unroll
        for (int cc = 0; cc < 16; cc++) {
            float kval = kd[c0 + cc][d];
#pragma unroll
            for (int i = 0; i < 32; i++) acc[i] += kval * vt[cc][vg + 4 * i];
        }
        __syncthreads();
    }
    size_t ubase = ((size_t)((b * Hn + h) * Nn + n)) * 8192 + (size_t)d * 128 + vg;
#pragma unroll
    for (int i = 0; i < 32; i++) U[ubase + 4 * i] = acc[i];
}

// ---------------- inter-chunk scan (parallel over elements) ----------------
__global__ void scan_kernel(float* __restrict__ U, const float* __restrict__ decay) {
    int bh = blockIdx.x >> 5;
    int e = ((blockIdx.x & 31) << 8) + threadIdx.x;   // 0..8191
    float s = 0.f;
    size_t base = (size_t)bh * Nn * 8192 + e;
    const float* dp = decay + (size_t)bh * Nn * 64 + (e >> 7);
    for (int n = 0; n < Nn; n++) {
        float u = U[base];
        U[base] = s;
        s = dp[0] * s + u;
        base += 8192; dp += 64;
    }
}

// ---------------- per-chunk output: o = tril(q_e k_e^T) v + q_e S_init -----
__global__ void output_kernel(const float* __restrict__ q, const float* __restrict__ k,
                              const float* __restrict__ v, const float* __restrict__ gk,
                              const float* __restrict__ Sinit, float* __restrict__ o) {
    extern __shared__ float smemf[];
    float (*qe)[65]  = (float(*)[65])smemf;
    float (*ke)[65]  = (float(*)[65])(smemf + 64 * 65);
    float (*Ash)[65] = (float(*)[65])(smemf + 2 * 64 * 65);
    float (*vt)[132] = (float(*)[132])(smemf + 3 * 64 * 65);
    int ch = blockIdx.x;
    int h = ch % Hn;
    int n = (ch / Hn) % Nn;
    int b = ch / (Hn * Nn);
    int tid = threadIdx.x;               // 256
    size_t rowbase = (size_t)b * Tn + (size_t)n * 64;
    const float scale = 0.125f;

#pragma unroll
    for (int i = 0; i < 16; i++) {
        int e = tid + i * 256;
        int c = e >> 6, d = e & 63;
        float bcv = gk[(rowbase + c) * 256 + h * 64 + d];
        float eb = expf(bcv);
        qe[c][d] = q[(rowbase + c) * 256 + h * 64 + d] * eb * scale;
        ke[c][d] = k[(rowbase + c) * 256 + h * 64 + d] * expf(-bcv);
    }
    __syncthreads();
    {
        int c = tid >> 2, eg = tid & 3;
#pragma unroll
        for (int j = 0; j < 16; j++) {
            int e = eg + 4 * j;
            float a = 0.f;
            if (e <= c) {
#pragma unroll
                for (int d = 0; d < 64; d++) a += qe[c][d] * ke[e][d];
            }
            Ash[c][e] = a;
        }
    }
    __syncthreads();

    int c = tid >> 2, vg = tid & 3;
    float acc[32];
#pragma unroll
    for (int i = 0; i < 32; i++) acc[i] = 0.f;

    size_t sbase = ((size_t)((b * Hn + h) * Nn + n)) * 8192;
    for (int d0 = 0; d0 < 64; d0 += 16) {
#pragma unroll
        for (int li = 0; li < 8; li++) {
            int e = tid + li * 256;
            int dd = e >> 7, vv = e & 127;
            vt[dd][vv] = Sinit[sbase + (size_t)(d0 + dd) * 128 + vv];
        }
        __syncthreads();
#pragma unroll
        for (int dd = 0; dd < 16; dd++) {
            float qv = qe[c][d0 + dd];
#pragma unroll
            for (int i = 0; i < 32; i++) acc[i] += qv * vt[dd][vg + 4 * i];
        }
        __syncthreads();
    }
    for (int e0 = 0; e0 < 64; e0 += 16) {
#pragma unroll
        for (int li = 0; li < 8; li++) {
            int e = tid + li * 256;
            int ee = e >> 7, vv = e & 127;
            vt[ee][vv] = v[(rowbase + e0 + ee) * 512 + h * 128 + vv];
        }
        __syncthreads();
#pragma unroll
        for (int ee = 0; ee < 16; ee++) {
            float a = Ash[c][e0 + ee];
#pragma unroll
            for (int i = 0; i < 32; i++) acc[i] += a * vt[ee][vg + 4 * i];
        }
        __syncthreads();
    }
    size_t obase = (rowbase + c) * 512 + h * 128 + vg;
#pragma unroll
    for (int i = 0; i < 32; i++) o[obase + 4 * i] = acc[i];
}

// ---------------- RMS-norm + SiLU gating -> bf16 hi/lo ---------------------
__global__ void gate_kernel(const float* __restrict__ o, const float* __restrict__ g,
                            const float* __restrict__ gw,
                            __nv_bfloat16* __restrict__ oh, __nv_bfloat16* __restrict__ ol) {
    int row = blockIdx.x;
    int tid = threadIdx.x;               // 512
    __shared__ float wsum[16];
    size_t idx = (size_t)row * 512 + tid;
    float ov = o[idx];
    float sq = ov * ov;
#pragma unroll
    for (int off = 16; off; off >>= 1) sq += __shfl_down_sync(0xffffffffu, sq, off);
    if ((tid & 31) == 0) wsum[tid >> 5] = sq;
    __syncthreads();
    int h = tid >> 7;
    float ss = wsum[h * 4] + wsum[h * 4 + 1] + wsum[h * 4 + 2] + wsum[h * 4 + 3];
    float rms = rsqrtf(ss * (1.f / 128.f) + 1e-5f);
    float gv = g[idx];
    float sig = 1.f / (1.f + expf(-gv));
    float val = ov * rms * gw[tid & 127] * gv * sig;
    __nv_bfloat16 hh = __float2bfloat16(val);
    oh[idx] = hh;
    ol[idx] = __float2bfloat16(val - __bfloat162float(hh));
}

// ---------------- launcher --------------------------------------------------
extern "C" void kernel_launch(void* const* d_in, const int* in_sizes, int n_in,
                              void* d_out, int out_size) {
    const float* x    = (const float*)d_in[0];
    const float* Wq   = (const float*)d_in[1];
    const float* Wk   = (const float*)d_in[2];
    const float* Wv   = (const float*)d_in[3];
    const float* Wg   = (const float*)d_in[4];
    const float* Wgk1 = (const float*)d_in[5];
    const float* Wgk2 = (const float*)d_in[6];
    const float* bgk2 = (const float*)d_in[7];
    const float* gnw  = (const float*)d_in[8];
    const float* Wo   = (const float*)d_in[9];
    float* out = (float*)d_out;

    float *q, *k, *v, *g, *gk, *U, *dec, *o;
    cudaGetSymbolAddress((void**)&q,   g_q);
    cudaGetSymbolAddress((void**)&k,   g_k);
    cudaGetSymbolAddress((void**)&v,   g_v);
    cudaGetSymbolAddress((void**)&g,   g_g);
    cudaGetSymbolAddress((void**)&gk,  g_gk);
    cudaGetSymbolAddress((void**)&U,   g_U);
    cudaGetSymbolAddress((void**)&dec, g_dec);
    cudaGetSymbolAddress((void**)&o,   g_o);

    __nv_bfloat16 *xh, *xl, *oh, *ol;
    __nv_bfloat16 *wqh, *wql, *wkh, *wkl, *wvh, *wvl, *wgh, *wgl, *woh, *wol;
    cudaGetSymbolAddress((void**)&xh, g_xh);   cudaGetSymbolAddress((void**)&xl, g_xl);
    cudaGetSymbolAddress((void**)&oh, g_oh);   cudaGetSymbolAddress((void**)&ol, g_ol);
    cudaGetSymbolAddress((void**)&wqh, g_wqh); cudaGetSymbolAddress((void**)&wql, g_wql);
    cudaGetSymbolAddress((void**)&wkh, g_wkh); cudaGetSymbolAddress((void**)&wkl, g_wkl);
    cudaGetSymbolAddress((void**)&wvh, g_wvh); cudaGetSymbolAddress((void**)&wvl, g_wvl);
    cudaGetSymbolAddress((void**)&wgh, g_wgh); cudaGetSymbolAddress((void**)&wgl, g_wgl);
    cudaGetSymbolAddress((void**)&woh, g_woh); cudaGetSymbolAddress((void**)&wol, g_wol);

    const int smem_gemm = 2 * (int)STAGEB;                  // 81920 bytes
    cudaFuncSetAttribute(gemm_mma, cudaFuncAttributeMaxDynamicSharedMemorySize, smem_gemm);
    const int smem_out = (3 * 64 * 65 + 16 * 132) * 4;
    cudaFuncSetAttribute(output_kernel, cudaFuncAttributeMaxDynamicSharedMemorySize, smem_out);
    const int smem_gk = (32 * 516 + 16 * 17) * 4;
    cudaFuncSetAttribute(gk2_kernel, cudaFuncAttributeMaxDynamicSharedMemorySize, smem_gk);

    // 1-2: bf16 splits
    conv_split4<<<2048, 256>>>(x, xh, xl, (size_t)BTn * Dn / 4);
    conv_w_all<<<1024, 256>>>(Wq, Wk, Wv, Wg, Wo, wqh, wql, wkh, wkl, wvh, wvl, wgh, wgl, woh, wol);

    // 3-6: projections on tensor cores (ncu -s5 captures launch #6 = g-proj GEMM)
    gemm_mma<<<dim3(BTn / 128, DKn / 128), 256, smem_gemm>>>(xh, xl, wqh, wql, q, BTn, DKn, Dn);
    gemm_mma<<<dim3(BTn / 128, DKn / 128), 256, smem_gemm>>>(xh, xl, wkh, wkl, k, BTn, DKn, Dn);
    gemm_mma<<<dim3(BTn / 128, DVn / 128), 256, smem_gemm>>>(xh, xl, wvh, wvl, v, BTn, DVn, Dn);
    gemm_mma<<<dim3(BTn / 128, DVn / 128), 256, smem_gemm>>>(xh, xl, wgh, wgl, g, BTn, DVn, Dn);

    // low-rank log-sigmoid gate
    gk2_kernel<<<BTn / 16, 256, smem_gk>>>(x, Wgk1, Wgk2, bgk2, gk);
    // chunk-local state contributions + cumsum + decay
    chunk_state_kernel<<<Bn * Nn * Hn, 256>>>(k, v, gk, U, dec);
    // parallel inter-chunk scan
    scan_kernel<<<Bn * Hn * 32, 256>>>(U, dec);
    // chunk outputs
    output_kernel<<<Bn * Nn * Hn, 256, smem_out>>>(q, k, v, gk, U, o);
    // gating + RMS norm -> bf16 split of o
    gate_kernel<<<BTn, 512>>>(o, g, gnw, oh, ol);
    // output projection on tensor cores
    gemm_mma<<<dim3(BTn / 128, DVn / 128), 256, smem_gemm>>>(oh, ol, woh, wol, out, BTn, DVn, Dn);
}

// round 5
// speedup vs baseline: 3.7776x; 1.2086x over previous
#include <cuda_runtime.h>
#include <cuda_bf16.h>
#include <math.h>
#include <stdint.h>

// Problem constants
#define Bn 8
#define Tn 8192
#define Dn 512
#define Hn 4
#define DKn 256
#define DVn 512
#define HKn 64
#define HVn 128
#define Cn 64
#define Nn 128               // T / C
#define BTn (Bn * Tn)        // 65536
#define LOWn 16

// ---------------- scratch (device globals; no runtime allocation) ----------
__device__ float g_q[(size_t)BTn * DKn];
__device__ float g_k[(size_t)BTn * DKn];
__device__ float g_v[(size_t)BTn * DVn];
__device__ float g_g[(size_t)BTn * DVn];
__device__ float g_gk[(size_t)BTn * DKn];
__device__ float g_U[(size_t)Bn * Hn * Nn * HKn * HVn];
__device__ float g_dec[(size_t)Bn * Hn * Nn * HKn];
__device__ float g_o[(size_t)BTn * DVn];

// bf16 split buffers
__device__ __nv_bfloat16 g_xh[(size_t)BTn * Dn];
__device__ __nv_bfloat16 g_xl[(size_t)BTn * Dn];
__device__ __nv_bfloat16 g_oh[(size_t)BTn * DVn];
__device__ __nv_bfloat16 g_ol[(size_t)BTn * DVn];
__device__ __nv_bfloat16 g_wqh[DKn * Dn], g_wql[DKn * Dn];
__device__ __nv_bfloat16 g_wkh[DKn * Dn], g_wkl[DKn * Dn];
__device__ __nv_bfloat16 g_wvh[DVn * Dn], g_wvl[DVn * Dn];
__device__ __nv_bfloat16 g_wgh[DVn * Dn], g_wgl[DVn * Dn];
__device__ __nv_bfloat16 g_woh[Dn * DVn], g_wol[Dn * DVn];

// ================= warp-MMA helpers =================
__device__ __forceinline__ uint32_t smem_u32(const void* p) {
    uint32_t a;
    asm("{ .reg .u64 t; cvta.to.shared.u64 t, %1; cvt.u32.u64 %0, t; }" : "=r"(a) : "l"(p));
    return a;
}
__device__ __forceinline__ void ldsm_x4(uint32_t addr, uint32_t* r) {
    asm volatile("ldmatrix.sync.aligned.m8n8.x4.shared.b16 {%0,%1,%2,%3}, [%4];"
                 : "=r"(r[0]), "=r"(r[1]), "=r"(r[2]), "=r"(r[3]) : "r"(addr));
}
__device__ __forceinline__ void mma16816(float* c, const uint32_t* a, const uint32_t* b) {
    asm volatile("mma.sync.aligned.m16n8k16.row.col.f32.bf16.bf16.f32 "
                 "{%0,%1,%2,%3}, {%4,%5,%6,%7}, {%8,%9}, {%0,%1,%2,%3};"
                 : "+f"(c[0]), "+f"(c[1]), "+f"(c[2]), "+f"(c[3])
                 : "r"(a[0]), "r"(a[1]), "r"(a[2]), "r"(a[3]), "r"(b[0]), "r"(b[1]));
}
__device__ __forceinline__ void cp16(uint32_t s, const void* g) {
    asm volatile("cp.async.cg.shared.global [%0], [%1], 16;" :: "r"(s), "l"(g));
}
__device__ __forceinline__ void split_bf(float v, __nv_bfloat16& h, __nv_bfloat16& l) {
    h = __float2bfloat16(v);
    l = __float2bfloat16(v - __bfloat162float(h));
}

// ============== tensor-core GEMM: C[m][n] = sum_k A[m][k]*B[n][k] ==========
#define BKg 32
#define ROWB 80u
#define TILEB 10240u
#define STAGEB 40960u
__global__ void __launch_bounds__(256, 2) gemm_mma(
    const __nv_bfloat16* __restrict__ Ah, const __nv_bfloat16* __restrict__ Al,
    const __nv_bfloat16* __restrict__ Bh, const __nv_bfloat16* __restrict__ Bl,
    float* __restrict__ Cout, int M, int N, int K)
{
    extern __shared__ char smem[];
    uint32_t sbase = smem_u32(smem);

    int tid = threadIdx.x;
    int wid = tid >> 5, lane = tid & 31;
    int mw = wid & 1, nw = wid >> 1;
    int m0 = blockIdx.x * 128, n0 = blockIdx.y * 128;

    float acc[4][4][4];
#pragma unroll
    for (int i = 0; i < 4; i++)
#pragma unroll
        for (int j = 0; j < 4; j++)
#pragma unroll
            for (int t = 0; t < 4; t++) acc[i][j][t] = 0.f;

    const __nv_bfloat16* gptr[8];
    uint32_t soff8[8];
#pragma unroll
    for (int j = 0; j < 8; j++) {
        int idx = tid + j * 256;
        int tile = idx >> 9;
        int ci = idx & 511;
        int row = ci >> 2;
        int c16 = ci & 3;
        soff8[j] = (uint32_t)tile * TILEB + (uint32_t)row * ROWB + (uint32_t)c16 * 16u;
        const __nv_bfloat16* base = (tile == 0) ? Ah : (tile == 1) ? Al : (tile == 2) ? Bh : Bl;
        int grow = (tile < 2) ? (m0 + row) : (n0 + row);
        gptr[j] = base + (size_t)grow * K + c16 * 8;
    }

    int a_row = mw * 64 + (lane & 7) + ((lane >> 3) & 1) * 8;
    int a_col = (lane >> 4) * 8;
    int b_row = nw * 32 + (lane & 7) + ((lane >> 4) & 1) * 8;
    int b_col = ((lane >> 3) & 1) * 8;
    uint32_t a_off[4], b_off[2];
#pragma unroll
    for (int i = 0; i < 4; i++) a_off[i] = (uint32_t)(a_row + i * 16) * ROWB + (uint32_t)a_col * 2u;
#pragma unroll
    for (int p = 0; p < 2; p++) b_off[p] = (uint32_t)(b_row + p * 16) * ROWB + (uint32_t)b_col * 2u;

    const int nkt = K / BKg;
#pragma unroll
    for (int j = 0; j < 8; j++) cp16(sbase + soff8[j], gptr[j]);
    asm volatile("cp.async.commit_group;" ::: "memory");

    for (int kt = 0; kt < nkt; kt++) {
        if (kt + 1 < nkt) {
            uint32_t sb2 = sbase + (uint32_t)((kt + 1) & 1) * STAGEB;
            int k0n = (kt + 1) * BKg;
#pragma unroll
            for (int j = 0; j < 8; j++) cp16(sb2 + soff8[j], gptr[j] + k0n);
            asm volatile("cp.async.commit_group;" ::: "memory");
            asm volatile("cp.async.wait_group 1;" ::: "memory");
        } else {
            asm volatile("cp.async.wait_group 0;" ::: "memory");
        }
        __syncthreads();

        uint32_t stB = sbase + (uint32_t)(kt & 1) * STAGEB;
#pragma unroll
        for (int kk = 0; kk < BKg; kk += 16) {
            uint32_t koff = (uint32_t)kk * 2u;
            uint32_t af[4][4];
            uint32_t b0[4], b1[4], c0[4], c1[4];
            ldsm_x4(stB + 2 * TILEB + b_off[0] + koff, b0);    // Bh p0
            ldsm_x4(stB + 2 * TILEB + b_off[1] + koff, b1);    // Bh p1
            ldsm_x4(stB + 3 * TILEB + b_off[0] + koff, c0);    // Bl p0
            ldsm_x4(stB + 3 * TILEB + b_off[1] + koff, c1);    // Bl p1
#pragma unroll
            for (int i = 0; i < 4; i++)
                ldsm_x4(stB + 0 * TILEB + a_off[i] + koff, af[i]);   // Ah
            // interleaved so each acc is revisited at distance >= 12 MMAs
#pragma unroll
            for (int i = 0; i < 4; i++) mma16816(acc[i][0], af[i], b0);
#pragma unroll
            for (int i = 0; i < 4; i++) mma16816(acc[i][1], af[i], b0 + 2);
#pragma unroll
            for (int i = 0; i < 4; i++) mma16816(acc[i][2], af[i], b1);
#pragma unroll
            for (int i = 0; i < 4; i++) mma16816(acc[i][3], af[i], b1 + 2);
#pragma unroll
            for (int i = 0; i < 4; i++) mma16816(acc[i][0], af[i], c0);
#pragma unroll
            for (int i = 0; i < 4; i++) mma16816(acc[i][1], af[i], c0 + 2);
#pragma unroll
            for (int i = 0; i < 4; i++) mma16816(acc[i][2], af[i], c1);
#pragma unroll
            for (int i = 0; i < 4; i++) mma16816(acc[i][3], af[i], c1 + 2);
#pragma unroll
            for (int i = 0; i < 4; i++)
                ldsm_x4(stB + 1 * TILEB + a_off[i] + koff, af[i]);   // Al
#pragma unroll
            for (int i = 0; i < 4; i++) mma16816(acc[i][0], af[i], b0);
#pragma unroll
            for (int i = 0; i < 4; i++) mma16816(acc[i][1], af[i], b0 + 2);
#pragma unroll
            for (int i = 0; i < 4; i++) mma16816(acc[i][2], af[i], b1);
#pragma unroll
            for (int i = 0; i < 4; i++) mma16816(acc[i][3], af[i], b1 + 2);
        }
        __syncthreads();
    }

    int erow = m0 + mw * 64 + (lane >> 2);
    int ecol = n0 + nw * 32 + (lane & 3) * 2;
#pragma unroll
    for (int i = 0; i < 4; i++) {
#pragma unroll
        for (int nt = 0; nt < 4; nt++) {
            float* c = acc[i][nt];
            size_t r0 = (size_t)(erow + i * 16) * N + ecol + nt * 8;
            size_t r1 = (size_t)(erow + i * 16 + 8) * N + ecol + nt * 8;
            *(float2*)(Cout + r0) = make_float2(c[0], c[1]);
            *(float2*)(Cout + r1) = make_float2(c[2], c[3]);
        }
    }
}

// ============== fp32 -> bf16 hi/lo split (vectorized) ======================
__device__ __forceinline__ void split4_store(float4 v, __nv_bfloat16* hi, __nv_bfloat16* lo,
                                             size_t i4) {
    __nv_bfloat16 h0, h1, h2, h3, l0, l1, l2, l3;
    split_bf(v.x, h0, l0); split_bf(v.y, h1, l1);
    split_bf(v.z, h2, l2); split_bf(v.w, h3, l3);
    uint2 ph, pl;
    ph.x = ((uint32_t)__bfloat16_as_ushort(h1) << 16) | __bfloat16_as_ushort(h0);
    ph.y = ((uint32_t)__bfloat16_as_ushort(h3) << 16) | __bfloat16_as_ushort(h2);
    pl.x = ((uint32_t)__bfloat16_as_ushort(l1) << 16) | __bfloat16_as_ushort(l0);
    pl.y = ((uint32_t)__bfloat16_as_ushort(l3) << 16) | __bfloat16_as_ushort(l2);
    *(uint2*)(hi + i4) = ph;
    *(uint2*)(lo + i4) = pl;
}

__global__ void conv_split4(const float* __restrict__ src, __nv_bfloat16* __restrict__ hi,
                            __nv_bfloat16* __restrict__ lo, size_t n4) {
    size_t i = (size_t)blockIdx.x * blockDim.x + threadIdx.x;
    size_t stride = (size_t)gridDim.x * blockDim.x;
    for (; i < n4; i += stride) {
        float4 v = *(const float4*)(src + i * 4);
        split4_store(v, hi, lo, i * 4);
    }
}

__global__ void conv_w_all(const float* __restrict__ Wq, const float* __restrict__ Wk,
                           const float* __restrict__ Wv, const float* __restrict__ Wg,
                           const float* __restrict__ Wo,
                           __nv_bfloat16* __restrict__ wqh, __nv_bfloat16* __restrict__ wql,
                           __nv_bfloat16* __restrict__ wkh, __nv_bfloat16* __restrict__ wkl,
                           __nv_bfloat16* __restrict__ wvh, __nv_bfloat16* __restrict__ wvl,
                           __nv_bfloat16* __restrict__ wgh, __nv_bfloat16* __restrict__ wgl,
                           __nv_bfloat16* __restrict__ woh, __nv_bfloat16* __restrict__ wol) {
    size_t i = (size_t)blockIdx.x * blockDim.x + threadIdx.x;
    const float* src; __nv_bfloat16 *hi, *lo; size_t off;
    if (i < 32768)        { src = Wq; hi = wqh; lo = wql; off = i; }
    else if (i < 65536)   { src = Wk; hi = wkh; lo = wkl; off = i - 32768; }
    else if (i < 131072)  { src = Wv; hi = wvh; lo = wvl; off = i - 65536; }
    else if (i < 196608)  { src = Wg; hi = wgh; lo = wgl; off = i - 131072; }
    else                  { src = Wo; hi = woh; lo = wol; off = i - 196608; }
    float4 v = *(const float4*)(src + off * 4);
    split4_store(v, hi, lo, off * 4);
}

// ---------------- low-rank gate: 16 rows per block (float4 LDS) ------------
__global__ void gk2_kernel(const float* __restrict__ x, const float* __restrict__ W1,
                           const float* __restrict__ W2, const float* __restrict__ bias,
                           float* __restrict__ gk) {
    extern __shared__ float sm[];
    float (*W1s)[516] = (float(*)[516])sm;
    float (*xs)[516]  = (float(*)[516])(sm + 16 * 516);
    float (*zs)[17]   = (float(*)[17])(sm + 32 * 516);
    int tid = threadIdx.x;                               // 256
    size_t row0 = (size_t)blockIdx.x * 16;

#pragma unroll
    for (int j = 0; j < 8; j++) {
        int e = (tid + j * 256) * 4;
        int r = e >> 9, c = e & 511;
        *(float4*)&W1s[r][c] = *(const float4*)(W1 + (size_t)r * 512 + c);
        *(float4*)&xs[r][c]  = *(const float4*)(x + (row0 + r) * 512 + c);
    }
    __syncthreads();
    {
        int r = tid >> 4, j = tid & 15;
        const float4* xr = (const float4*)&xs[r][0];
        const float4* wr = (const float4*)&W1s[j][0];
        float s = 0.f;
#pragma unroll 16
        for (int i = 0; i < 128; i++) {
            float4 a = xr[i], b = wr[i];
            s += a.x * b.x + a.y * b.y + a.z * b.z + a.w * b.w;
        }
        zs[r][j] = s;
    }
    __syncthreads();
    {
        int d = tid;
        float w2r[16];
#pragma unroll
        for (int q4 = 0; q4 < 4; q4++) {
            float4 w4 = *(const float4*)(W2 + (size_t)d * 16 + q4 * 4);
            w2r[q4 * 4] = w4.x; w2r[q4 * 4 + 1] = w4.y; w2r[q4 * 4 + 2] = w4.z; w2r[q4 * 4 + 3] = w4.w;
        }
        float b = bias[d];
#pragma unroll
        for (int r = 0; r < 16; r++) {
            float a = b;
#pragma unroll
            for (int j = 0; j < 16; j++) a += zs[r][j] * w2r[j];
            float ls = fminf(a, 0.f) - log1pf(expf(-fabsf(a)));
            gk[(row0 + r) * 256 + d] = ls * (1.f / 16.f);
        }
    }
}

// ======= chunk_state (tensor cores): cumsum gk, decay, U = k_dec^T @ v =====
// smem layout (bytes):
//   bc     @ 0      : 64*65*4 = 16640 (fp32 cumsum)
//   blast  @ 16640  : 256
//   kdTh   @ 16896  : 64*72*2 = 9216   [d][c] bf16 hi
//   kdTl   @ 26112  : 9216
//   vTh    @ 35328  : 128*72*2 = 18432 [vv][c] bf16 hi
//   vTl    @ 53760  : 18432  -> total 72192
#define CS_BC    0
#define CS_BLAST 16640
#define CS_KDH   16896
#define CS_KDL   26112
#define CS_VTH   35328
#define CS_VTL   53760
#define CS_SMEM  72192
__global__ void __launch_bounds__(256, 2) chunk_state_tc(
    const float* __restrict__ k, const float* __restrict__ v,
    float* __restrict__ gk, float* __restrict__ U, float* __restrict__ decay)
{
    extern __shared__ char smem[];
    float* bc = (float*)(smem + CS_BC);                  // [64][65]
    float* blast = (float*)(smem + CS_BLAST);
    __nv_bfloat16* kdTh = (__nv_bfloat16*)(smem + CS_KDH);
    __nv_bfloat16* kdTl = (__nv_bfloat16*)(smem + CS_KDL);
    __nv_bfloat16* vTh  = (__nv_bfloat16*)(smem + CS_VTH);
    __nv_bfloat16* vTl  = (__nv_bfloat16*)(smem + CS_VTL);
    uint32_t sb = smem_u32(smem);

    int ch = blockIdx.x;                      // B*N*H = 4096
    int h = ch % Hn;
    int n = (ch / Hn) % Nn;
    int b = ch / (Hn * Nn);
    int tid = threadIdx.x;
    int wid = tid >> 5, lane = tid & 31;
    size_t rowbase = (size_t)b * Tn + (size_t)n * 64;

    // phase 1: load gk, cumsum
#pragma unroll
    for (int i = 0; i < 16; i++) {
        int e = tid + i * 256;
        int c = e >> 6, d = e & 63;
        bc[c * 65 + d] = gk[(rowbase + c) * 256 + h * 64 + d];
    }
    __syncthreads();
    if (tid < 64) {
        float s = 0.f;
#pragma unroll
        for (int c = 0; c < 64; c++) { s += bc[c * 65 + tid]; bc[c * 65 + tid] = s; }
        blast[tid] = s;
        decay[((size_t)((b * Hn + h) * Nn + n)) * 64 + tid] = expf(s);
    }
    __syncthreads();

    // phase 2: gk writeback + kdT split (transposed [d][c])
#pragma unroll
    for (int i = 0; i < 16; i++) {
        int e = tid + i * 256;
        int c = e >> 6, d = e & 63;
        float bcv = bc[c * 65 + d];
        gk[(rowbase + c) * 256 + h * 64 + d] = bcv;
        float kd = k[(rowbase + c) * 256 + h * 64 + d] * expf(blast[d] - bcv);
        __nv_bfloat16 hh, ll; split_bf(kd, hh, ll);
        kdTh[d * 72 + c] = hh;
        kdTl[d * 72 + c] = ll;
    }
    // phase 3: v transposed split [vv][c]
#pragma unroll
    for (int it = 0; it < 8; it++) {
        int e4 = tid + it * 256;          // 0..2047
        int c = e4 >> 5, vv4 = (e4 & 31) * 4;
        float4 vv = *(const float4*)(v + (rowbase + c) * 512 + h * 128 + vv4);
        __nv_bfloat16 hh, ll;
        split_bf(vv.x, hh, ll); vTh[(vv4 + 0) * 72 + c] = hh; vTl[(vv4 + 0) * 72 + c] = ll;
        split_bf(vv.y, hh, ll); vTh[(vv4 + 1) * 72 + c] = hh; vTl[(vv4 + 1) * 72 + c] = ll;
        split_bf(vv.z, hh, ll); vTh[(vv4 + 2) * 72 + c] = hh; vTl[(vv4 + 2) * 72 + c] = ll;
        split_bf(vv.w, hh, ll); vTh[(vv4 + 3) * 72 + c] = hh; vTl[(vv4 + 3) * 72 + c] = ll;
    }
    __syncthreads();

    // phase 4: U[d][vv] = kdT @ vT^T, M=64 N=128 K=64
    int mw = wid & 3, nw = wid >> 2;
    float acc[8][4];
#pragma unroll
    for (int t = 0; t < 8; t++)
#pragma unroll
        for (int r = 0; r < 4; r++) acc[t][r] = 0.f;

    uint32_t a_base = sb + CS_KDH +
        ((uint32_t)(mw * 16 + (lane & 7) + ((lane >> 3) & 1) * 8) * 72u + (uint32_t)((lane >> 4) * 8)) * 2u;
    uint32_t b_rowoff = ((uint32_t)(nw * 64 + (lane & 7) + ((lane >> 4) & 1) * 8) * 72u +
                         (uint32_t)(((lane >> 3) & 1) * 8)) * 2u;
#pragma unroll
    for (int ks = 0; ks < 4; ks++) {
        uint32_t ko = (uint32_t)(ks * 16) * 2u;
        uint32_t ah[4], al[4], bh[4][4], bl[4][4];
        ldsm_x4(a_base + ko, ah);
        ldsm_x4(a_base + (CS_KDL - CS_KDH) + ko, al);
#pragma unroll
        for (int j = 0; j < 4; j++) {
            ldsm_x4(sb + CS_VTH + b_rowoff + (uint32_t)(j * 16 * 72 * 2) + ko, bh[j]);
            ldsm_x4(sb + CS_VTL + b_rowoff + (uint32_t)(j * 16 * 72 * 2) + ko, bl[j]);
        }
#pragma unroll
        for (int j = 0; j < 4; j++) mma16816(acc[j * 2 + 0], ah, bh[j]);
#pragma unroll
        for (int j = 0; j < 4; j++) mma16816(acc[j * 2 + 1], ah, bh[j] + 2);
#pragma unroll
        for (int j = 0; j < 4; j++) mma16816(acc[j * 2 + 0], ah, bl[j]);
#pragma unroll
        for (int j = 0; j < 4; j++) mma16816(acc[j * 2 + 1], ah, bl[j] + 2);
#pragma unroll
        for (int j = 0; j < 4; j++) mma16816(acc[j * 2 + 0], al, bh[j]);
#pragma unroll
        for (int j = 0; j < 4; j++) mma16816(acc[j * 2 + 1], al, bh[j] + 2);
    }

    size_t ubase = ((size_t)((b * Hn + h) * Nn + n)) * 8192;
    int d0 = mw * 16 + (lane >> 2);
#pragma unroll
    for (int j = 0; j < 4; j++) {
#pragma unroll
        for (int s = 0; s < 2; s++) {
            float* c = acc[j * 2 + s];
            int vv = nw * 64 + j * 16 + s * 8 + (lane & 3) * 2;
            *(float2*)(U + ubase + (size_t)d0 * 128 + vv) = make_float2(c[0], c[1]);
            *(float2*)(U + ubase + (size_t)(d0 + 8) * 128 + vv) = make_float2(c[2], c[3]);
        }
    }
}

// ---------------- inter-chunk scan (parallel over elements) ----------------
__global__ void scan_kernel(float* __restrict__ U, const float* __restrict__ decay) {
    int bh = blockIdx.x >> 5;
    int e = ((blockIdx.x & 31) << 8) + threadIdx.x;
    float s = 0.f;
    size_t base = (size_t)bh * Nn * 8192 + e;
    const float* dp = decay + (size_t)bh * Nn * 64 + (e >> 7);
    for (int n = 0; n < Nn; n++) {
        float u = U[base];
        U[base] = s;
        s = dp[0] * s + u;
        base += 8192; dp += 64;
    }
}

// ======= output (tensor cores): o = tril(qe ke^T) v + qe S_init ============
// smem layout (bytes):
//   qeh @ 0      9216   [c][d]
//   qel @ 9216   9216
//   keh @ 18432  9216   [e][d]   (overlaid by STh after mma1)
//   kel @ 27648  9216
//   Ash @ 36864  9216   [c][e]
//   Asl @ 46080  9216
//   vTh @ 55296  18432  [vv][e]
//   vTl @ 73728  18432
//   STh @ 18432  (overlay on keh+kel, 18432)  [vv][d]
//   STl @ 92160  18432  -> total 110592
#define OT_QEH 0
#define OT_QEL 9216
#define OT_KEH 18432
#define OT_KEL 27648
#define OT_ASH 36864
#define OT_ASL 46080
#define OT_VTH 55296
#define OT_VTL 73728
#define OT_STH 18432
#define OT_STL 92160
#define OT_SMEM 110592
__global__ void __launch_bounds__(256, 2) output_tc(
    const float* __restrict__ q, const float* __restrict__ k,
    const float* __restrict__ v, const float* __restrict__ gk,
    const float* __restrict__ Sinit, float* __restrict__ o)
{
    extern __shared__ char smem[];
    __nv_bfloat16* qeh = (__nv_bfloat16*)(smem + OT_QEH);
    __nv_bfloat16* qel = (__nv_bfloat16*)(smem + OT_QEL);
    __nv_bfloat16* keh = (__nv_bfloat16*)(smem + OT_KEH);
    __nv_bfloat16* kel = (__nv_bfloat16*)(smem + OT_KEL);
    __nv_bfloat16* Ash = (__nv_bfloat16*)(smem + OT_ASH);
    __nv_bfloat16* Asl = (__nv_bfloat16*)(smem + OT_ASL);
    __nv_bfloat16* vTh = (__nv_bfloat16*)(smem + OT_VTH);
    __nv_bfloat16* vTl = (__nv_bfloat16*)(smem + OT_VTL);
    __nv_bfloat16* STh = (__nv_bfloat16*)(smem + OT_STH);
    __nv_bfloat16* STl = (__nv_bfloat16*)(smem + OT_STL);
    uint32_t sb = smem_u32(smem);

    int ch = blockIdx.x;
    int h = ch % Hn;
    int n = (ch / Hn) % Nn;
    int b = ch / (Hn * Nn);
    int tid = threadIdx.x;
    int wid = tid >> 5, lane = tid & 31;
    size_t rowbase = (size_t)b * Tn + (size_t)n * 64;
    const float scale = 0.125f;

    // phase 1: qe/ke splits [c][d] and [e][d]; v transposed split [vv][e]
#pragma unroll
    for (int i = 0; i < 16; i++) {
        int e = tid + i * 256;
        int c = e >> 6, d = e & 63;
        float bcv = gk[(rowbase + c) * 256 + h * 64 + d];
        float eb = expf(bcv);
        float qe = q[(rowbase + c) * 256 + h * 64 + d] * eb * scale;
        float ke = k[(rowbase + c) * 256 + h * 64 + d] * expf(-bcv);
        __nv_bfloat16 hh, ll;
        split_bf(qe, hh, ll); qeh[c * 72 + d] = hh; qel[c * 72 + d] = ll;
        split_bf(ke, hh, ll); keh[c * 72 + d] = hh; kel[c * 72 + d] = ll;
    }
#pragma unroll
    for (int it = 0; it < 8; it++) {
        int e4 = tid + it * 256;
        int c = e4 >> 5, vv4 = (e4 & 31) * 4;
        float4 vv = *(const float4*)(v + (rowbase + c) * 512 + h * 128 + vv4);
        __nv_bfloat16 hh, ll;
        split_bf(vv.x, hh, ll); vTh[(vv4 + 0) * 72 + c] = hh; vTl[(vv4 + 0) * 72 + c] = ll;
        split_bf(vv.y, hh, ll); vTh[(vv4 + 1) * 72 + c] = hh; vTl[(vv4 + 1) * 72 + c] = ll;
        split_bf(vv.z, hh, ll); vTh[(vv4 + 2) * 72 + c] = hh; vTl[(vv4 + 2) * 72 + c] = ll;
        split_bf(vv.w, hh, ll); vTh[(vv4 + 3) * 72 + c] = hh; vTl[(vv4 + 3) * 72 + c] = ll;
    }
    __syncthreads();

    // phase 2: mma1 A = qe @ ke^T (M=64 N=64 K=64), warps 4x2
    {
        int mw = wid & 3, nw = wid >> 2 & 1;     // wid>>2 in 0..1 (nw 32-wide)
        // NOTE: 8 warps -> mw 0..3, nw 0..1
        nw = wid >> 2;
        float acc1[4][4];
#pragma unroll
        for (int t = 0; t < 4; t++)
#pragma unroll
            for (int r = 0; r < 4; r++) acc1[t][r] = 0.f;

        uint32_t a_base = sb + OT_QEH +
            ((uint32_t)(mw * 16 + (lane & 7) + ((lane >> 3) & 1) * 8) * 72u + (uint32_t)((lane >> 4) * 8)) * 2u;
        uint32_t b_base = sb + OT_KEH +
            ((uint32_t)(nw * 32 + (lane & 7) + ((lane >> 4) & 1) * 8) * 72u + (uint32_t)(((lane >> 3) & 1) * 8)) * 2u;
#pragma unroll
        for (int ks = 0; ks < 4; ks++) {
            uint32_t ko = (uint32_t)(ks * 16) * 2u;
            uint32_t ah[4], al[4], bh0[4], bh1[4], bl0[4], bl1[4];
            ldsm_x4(a_base + ko, ah);
            ldsm_x4(a_base + (OT_QEL - OT_QEH) + ko, al);
            ldsm_x4(b_base + ko, bh0);
            ldsm_x4(b_base + (uint32_t)(16 * 72 * 2) + ko, bh1);
            ldsm_x4(b_base + (OT_KEL - OT_KEH) + ko, bl0);
            ldsm_x4(b_base + (OT_KEL - OT_KEH) + (uint32_t)(16 * 72 * 2) + ko, bl1);
            mma16816(acc1[0], ah, bh0); mma16816(acc1[1], ah, bh0 + 2);
            mma16816(acc1[2], ah, bh1); mma16816(acc1[3], ah, bh1 + 2);
            mma16816(acc1[0], ah, bl0); mma16816(acc1[1], ah, bl0 + 2);
            mma16816(acc1[2], ah, bl1); mma16816(acc1[3], ah, bl1 + 2);
            mma16816(acc1[0], al, bh0); mma16816(acc1[1], al, bh0 + 2);
            mma16816(acc1[2], al, bh1); mma16816(acc1[3], al, bh1 + 2);
        }
        __syncthreads();    // all mma1 ldsm of ke done before ST overlay & Ash write race window

        // phase 3: mask + split-store A -> Ash/Asl [c][e]
        int r0 = mw * 16 + (lane >> 2);
#pragma unroll
        for (int p = 0; p < 2; p++) {
#pragma unroll
            for (int s = 0; s < 2; s++) {
                float* cfr = acc1[p * 2 + s];
                int e0 = nw * 32 + p * 16 + s * 8 + (lane & 3) * 2;
#pragma unroll
                for (int rr = 0; rr < 2; rr++) {
                    int c = r0 + rr * 8;
#pragma unroll
                    for (int cc = 0; cc < 2; cc++) {
                        int e = e0 + cc;
                        float val = (e <= c) ? cfr[rr * 2 + cc] : 0.f;
                        __nv_bfloat16 hh, ll; split_bf(val, hh, ll);
                        Ash[c * 72 + e] = hh;
                        Asl[c * 72 + e] = ll;
                    }
                }
            }
        }
    }

    // phase 3b: Sinit transposed split [vv][d] (overlays ke region)
    size_t sbase = ((size_t)((b * Hn + h) * Nn + n)) * 8192;
#pragma unroll
    for (int it = 0; it < 8; it++) {
        int e4 = tid + it * 256;
        int d = e4 >> 5, vv4 = (e4 & 31) * 4;
        float4 sv = *(const float4*)(Sinit + sbase + (size_t)d * 128 + vv4);
        __nv_bfloat16 hh, ll;
        split_bf(sv.x, hh, ll); STh[(vv4 + 0) * 72 + d] = hh; STl[(vv4 + 0) * 72 + d] = ll;
        split_bf(sv.y, hh, ll); STh[(vv4 + 1) * 72 + d] = hh; STl[(vv4 + 1) * 72 + d] = ll;
        split_bf(sv.z, hh, ll); STh[(vv4 + 2) * 72 + d] = hh; STl[(vv4 + 2) * 72 + d] = ll;
        split_bf(sv.w, hh, ll); STh[(vv4 + 3) * 72 + d] = hh; STl[(vv4 + 3) * 72 + d] = ll;
    }
    __syncthreads();

    // phase 4: o = A @ v + qe @ Sinit  (M=64 N=128 K=64 each), warps 4x2
    {
        int mw = wid & 3, nw = wid >> 2;
        float acc[8][4];
#pragma unroll
        for (int t = 0; t < 8; t++)
#pragma unroll
            for (int r = 0; r < 4; r++) acc[t][r] = 0.f;

        uint32_t arow = ((uint32_t)(mw * 16 + (lane & 7) + ((lane >> 3) & 1) * 8) * 72u +
                         (uint32_t)((lane >> 4) * 8)) * 2u;
        uint32_t brow = ((uint32_t)(nw * 64 + (lane & 7) + ((lane >> 4) & 1) * 8) * 72u +
                        (uint32_t)(((lane >> 3) & 1) * 8)) * 2u;

        // pass A: Ash @ vT (k = e)
#pragma unroll
        for (int ks = 0; ks < 4; ks++) {
            uint32_t ko = (uint32_t)(ks * 16) * 2u;
            uint32_t ah[4], al[4], bh[4][4], bl[4][4];
            ldsm_x4(sb + OT_ASH + arow + ko, ah);
            ldsm_x4(sb + OT_ASL + arow + ko, al);
#pragma unroll
            for (int j = 0; j < 4; j++) {
                ldsm_x4(sb + OT_VTH + brow + (uint32_t)(j * 16 * 72 * 2) + ko, bh[j]);
                ldsm_x4(sb + OT_VTL + brow + (uint32_t)(j * 16 * 72 * 2) + ko, bl[j]);
            }
#pragma unroll
            for (int j = 0; j < 4; j++) mma16816(acc[j * 2 + 0], ah, bh[j]);
#pragma unroll
            for (int j = 0; j < 4; j++) mma16816(acc[j * 2 + 1], ah, bh[j] + 2);
#pragma unroll
            for (int j = 0; j < 4; j++) mma16816(acc[j * 2 + 0], ah, bl[j]);
#pragma unroll
            for (int j = 0; j < 4; j++) mma16816(acc[j * 2 + 1], ah, bl[j] + 2);
#pragma unroll
            for (int j = 0; j < 4; j++) mma16816(acc[j * 2 + 0], al, bh[j]);
#pragma unroll
            for (int j = 0; j < 4; j++) mma16816(acc[j * 2 + 1], al, bh[j] + 2);
        }
        // pass B: qe @ ST (k = d)
#pragma unroll
        for (int ks = 0; ks < 4; ks++) {
            uint32_t ko = (uint32_t)(ks * 16) * 2u;
            uint32_t ah[4], al[4], bh[4][4], bl[4][4];
            ldsm_x4(sb + OT_QEH + arow + ko, ah);
            ldsm_x4(sb + OT_QEL + arow + ko, al);
#pragma unroll
            for (int j = 0; j < 4; j++) {
                ldsm_x4(sb + OT_STH + brow + (uint32_t)(j * 16 * 72 * 2) + ko, bh[j]);
                ldsm_x4(sb + OT_STL + brow + (uint32_t)(j * 16 * 72 * 2) + ko, bl[j]);
            }
#pragma unroll
            for (int j = 0; j < 4; j++) mma16816(acc[j * 2 + 0], ah, bh[j]);
#pragma unroll
            for (int j = 0; j < 4; j++) mma16816(acc[j * 2 + 1], ah, bh[j] + 2);
#pragma unroll
            for (int j = 0; j < 4; j++) mma16816(acc[j * 2 + 0], ah, bl[j]);
#pragma unroll
            for (int j = 0; j < 4; j++) mma16816(acc[j * 2 + 1], ah, bl[j] + 2);
#pragma unroll
            for (int j = 0; j < 4; j++) mma16816(acc[j * 2 + 0], al, bh[j]);
#pragma unroll
            for (int j = 0; j < 4; j++) mma16816(acc[j * 2 + 1], al, bh[j] + 2);
        }

        int c0 = mw * 16 + (lane >> 2);
#pragma unroll
        for (int j = 0; j < 4; j++) {
#pragma unroll
            for (int s = 0; s < 2; s++) {
                float* cf = acc[j * 2 + s];
                int vv = nw * 64 + j * 16 + s * 8 + (lane & 3) * 2;
                *(float2*)(o + (rowbase + c0) * 512 + h * 128 + vv) = make_float2(cf[0], cf[1]);
                *(float2*)(o + (rowbase + c0 + 8) * 512 + h * 128 + vv) = make_float2(cf[2], cf[3]);
            }
        }
    }
}

// ---------------- RMS-norm + SiLU gating -> bf16 hi/lo ---------------------
__global__ void gate_kernel(const float* __restrict__ o, const float* __restrict__ g,
                            const float* __restrict__ gw,
                            __nv_bfloat16* __restrict__ oh, __nv_bfloat16* __restrict__ ol) {
    int row = blockIdx.x;
    int tid = threadIdx.x;               // 512
    __shared__ float wsum[16];
    size_t idx = (size_t)row * 512 + tid;
    float ov = o[idx];
    float sq = ov * ov;
#pragma unroll
    for (int off = 16; off; off >>= 1) sq += __shfl_down_sync(0xffffffffu, sq, off);
    if ((tid & 31) == 0) wsum[tid >> 5] = sq;
    __syncthreads();
    int h = tid >> 7;
    float ss = wsum[h * 4] + wsum[h * 4 + 1] + wsum[h * 4 + 2] + wsum[h * 4 + 3];
    float rms = rsqrtf(ss * (1.f / 128.f) + 1e-5f);
    float gv = g[idx];
    float sig = 1.f / (1.f + expf(-gv));
    float val = ov * rms * gw[tid & 127] * gv * sig;
    __nv_bfloat16 hh, ll; split_bf(val, hh, ll);
    oh[idx] = hh;
    ol[idx] = ll;
}

// ---------------- launcher --------------------------------------------------
extern "C" void kernel_launch(void* const* d_in, const int* in_sizes, int n_in,
                              void* d_out, int out_size) {
    const float* x    = (const float*)d_in[0];
    const float* Wq   = (const float*)d_in[1];
    const float* Wk   = (const float*)d_in[2];
    const float* Wv   = (const float*)d_in[3];
    const float* Wg   = (const float*)d_in[4];
    const float* Wgk1 = (const float*)d_in[5];
    const float* Wgk2 = (const float*)d_in[6];
    const float* bgk2 = (const float*)d_in[7];
    const float* gnw  = (const float*)d_in[8];
    const float* Wo   = (const float*)d_in[9];
    float* out = (float*)d_out;

    float *q, *k, *v, *g, *gk, *U, *dec, *o;
    cudaGetSymbolAddress((void**)&q,   g_q);
    cudaGetSymbolAddress((void**)&k,   g_k);
    cudaGetSymbolAddress((void**)&v,   g_v);
    cudaGetSymbolAddress((void**)&g,   g_g);
    cudaGetSymbolAddress((void**)&gk,  g_gk);
    cudaGetSymbolAddress((void**)&U,   g_U);
    cudaGetSymbolAddress((void**)&dec, g_dec);
    cudaGetSymbolAddress((void**)&o,   g_o);

    __nv_bfloat16 *xh, *xl, *oh, *ol;
    __nv_bfloat16 *wqh, *wql, *wkh, *wkl, *wvh, *wvl, *wgh, *wgl, *woh, *wol;
    cudaGetSymbolAddress((void**)&xh, g_xh);   cudaGetSymbolAddress((void**)&xl, g_xl);
    cudaGetSymbolAddress((void**)&oh, g_oh);   cudaGetSymbolAddress((void**)&ol, g_ol);
    cudaGetSymbolAddress((void**)&wqh, g_wqh); cudaGetSymbolAddress((void**)&wql, g_wql);
    cudaGetSymbolAddress((void**)&wkh, g_wkh); cudaGetSymbolAddress((void**)&wkl, g_wkl);
    cudaGetSymbolAddress((void**)&wvh, g_wvh); cudaGetSymbolAddress((void**)&wvl, g_wvl);
    cudaGetSymbolAddress((void**)&wgh, g_wgh); cudaGetSymbolAddress((void**)&wgl, g_wgl);
    cudaGetSymbolAddress((void**)&woh, g_woh); cudaGetSymbolAddress((void**)&wol, g_wol);

    const int smem_gemm = 2 * (int)STAGEB;
    cudaFuncSetAttribute(gemm_mma, cudaFuncAttributeMaxDynamicSharedMemorySize, smem_gemm);
    cudaFuncSetAttribute(chunk_state_tc, cudaFuncAttributeMaxDynamicSharedMemorySize, CS_SMEM);
    cudaFuncSetAttribute(output_tc, cudaFuncAttributeMaxDynamicSharedMemorySize, OT_SMEM);
    const int smem_gk = (32 * 516 + 16 * 17) * 4;
    cudaFuncSetAttribute(gk2_kernel, cudaFuncAttributeMaxDynamicSharedMemorySize, smem_gk);

    conv_split4<<<2048, 256>>>(x, xh, xl, (size_t)BTn * Dn / 4);
    conv_w_all<<<1024, 256>>>(Wq, Wk, Wv, Wg, Wo, wqh, wql, wkh, wkl, wvh, wvl, wgh, wgl, woh, wol);

    gemm_mma<<<dim3(BTn / 128, DKn / 128), 256, smem_gemm>>>(xh, xl, wqh, wql, q, BTn, DKn, Dn);
    gemm_mma<<<dim3(BTn / 128, DKn / 128), 256, smem_gemm>>>(xh, xl, wkh, wkl, k, BTn, DKn, Dn);
    gemm_mma<<<dim3(BTn / 128, DVn / 128), 256, smem_gemm>>>(xh, xl, wvh, wvl, v, BTn, DVn, Dn);
    gemm_mma<<<dim3(BTn / 128, DVn / 128), 256, smem_gemm>>>(xh, xl, wgh, wgl, g, BTn, DVn, Dn);

    gk2_kernel<<<BTn / 16, 256, smem_gk>>>(x, Wgk1, Wgk2, bgk2, gk);
    chunk_state_tc<<<Bn * Nn * Hn, 256, CS_SMEM>>>(k, v, gk, U, dec);
    scan_kernel<<<Bn * Hn * 32, 256>>>(U, dec);
    output_tc<<<Bn * Nn * Hn, 256, OT_SMEM>>>(q, k, v, gk, U, o);
    gate_kernel<<<BTn, 512>>>(o, g, gnw, oh, ol);
    gemm_mma<<<dim3(BTn / 128, DVn / 128), 256, smem_gemm>>>(oh, ol, woh, wol, out, BTn, DVn, Dn);
}

// round 6
// speedup vs baseline: 4.4750x; 1.1846x over previous
#include <cuda_runtime.h>
#include <cuda_bf16.h>
#include <cuda_fp16.h>
#include <math.h>
#include <stdint.h>

// Problem constants
#define Bn 8
#define Tn 8192
#define Dn 512
#define Hn 4
#define DKn 256
#define DVn 512
#define HKn 64
#define HVn 128
#define Cn 64
#define Nn 128               // T / C
#define BTn (Bn * Tn)        // 65536
#define LOWn 16

// ---------------- scratch (device globals; no runtime allocation) ----------
__device__ float g_q[(size_t)BTn * DKn];
__device__ float g_k[(size_t)BTn * DKn];
__device__ float g_v[(size_t)BTn * DVn];
__device__ float g_g[(size_t)BTn * DVn];
__device__ float g_gk[(size_t)BTn * DKn];
__device__ float g_U[(size_t)Bn * Hn * Nn * HKn * HVn];
__device__ float g_dec[(size_t)Bn * Hn * Nn * HKn];
__device__ float g_o[(size_t)BTn * DVn];

// fp16 buffers for GEMMs
__device__ __half g_xh[(size_t)BTn * Dn];
__device__ __half g_xl[(size_t)BTn * Dn];
__device__ __half g_oh[(size_t)BTn * DVn];
__device__ __half g_ol[(size_t)BTn * DVn];
__device__ __half g_wcat[(size_t)(2 * DKn + 2 * DVn) * Dn];   // [1536][512] q|k|v|g
__device__ __half g_wo[(size_t)Dn * DVn];                     // [512][512]

// ================= warp-MMA helpers =================
__device__ __forceinline__ uint32_t smem_u32(const void* p) {
    uint32_t a;
    asm("{ .reg .u64 t; cvta.to.shared.u64 t, %1; cvt.u32.u64 %0, t; }" : "=r"(a) : "l"(p));
    return a;
}
__device__ __forceinline__ void ldsm_x4(uint32_t addr, uint32_t* r) {
    asm volatile("ldmatrix.sync.aligned.m8n8.x4.shared.b16 {%0,%1,%2,%3}, [%4];"
                 : "=r"(r[0]), "=r"(r[1]), "=r"(r[2]), "=r"(r[3]) : "r"(addr));
}
__device__ __forceinline__ void mma16816(float* c, const uint32_t* a, const uint32_t* b) {
    asm volatile("mma.sync.aligned.m16n8k16.row.col.f32.bf16.bf16.f32 "
                 "{%0,%1,%2,%3}, {%4,%5,%6,%7}, {%8,%9}, {%0,%1,%2,%3};"
                 : "+f"(c[0]), "+f"(c[1]), "+f"(c[2]), "+f"(c[3])
                 : "r"(a[0]), "r"(a[1]), "r"(a[2]), "r"(a[3]), "r"(b[0]), "r"(b[1]));
}
__device__ __forceinline__ void mma16816h(float* c, const uint32_t* a, const uint32_t* b) {
    asm volatile("mma.sync.aligned.m16n8k16.row.col.f32.f16.f16.f32 "
                 "{%0,%1,%2,%3}, {%4,%5,%6,%7}, {%8,%9}, {%0,%1,%2,%3};"
                 : "+f"(c[0]), "+f"(c[1]), "+f"(c[2]), "+f"(c[3])
                 : "r"(a[0]), "r"(a[1]), "r"(a[2]), "r"(a[3]), "r"(b[0]), "r"(b[1]));
}
__device__ __forceinline__ void cp16(uint32_t s, const void* g) {
    asm volatile("cp.async.cg.shared.global [%0], [%1], 16;" :: "r"(s), "l"(g));
}
__device__ __forceinline__ void split_bf(float v, __nv_bfloat16& h, __nv_bfloat16& l) {
    h = __float2bfloat16(v);
    l = __float2bfloat16(v - __bfloat162float(h));
}
__device__ __forceinline__ void split_h(float v, __half& h, __half& l) {
    h = __float2half_rn(v);
    l = __float2half_rn(v - __half2float(h));
}

// ============== fp16 tensor-core GEMM with 2-product split =================
// C[m][n] = sum_k A[m][k]*B[n][k];  A = Ah + Al (fp16 split), B fp16 single.
// CTA tile 128x128, BK=32, cp.async 2-stage. 8 warps = 2x4, each 64x32.
// router==1: N-space = [q(256) | k(256) | v(512) | g(512)], outputs routed.
// router==0: single output out_q with ldC = 512.
#define BKg 32
#define ROWB 80u
#define TILEB 10240u
#define STAGEB 30720u                    // 3 tiles
__global__ void __launch_bounds__(256, 2) gemm_f16(
    const __half* __restrict__ Ah, const __half* __restrict__ Al,
    const __half* __restrict__ B,
    float* __restrict__ out_q, float* __restrict__ out_k,
    float* __restrict__ out_v, float* __restrict__ out_g,
    int M, int K, int router)
{
    extern __shared__ char smem[];
    uint32_t sbase = smem_u32(smem);

    int tid = threadIdx.x;
    int wid = tid >> 5, lane = tid & 31;
    int mw = wid & 1, nw = wid >> 1;
    int m0 = blockIdx.x * 128, n0 = blockIdx.y * 128;

    float acc[4][4][4];
#pragma unroll
    for (int i = 0; i < 4; i++)
#pragma unroll
        for (int j = 0; j < 4; j++)
#pragma unroll
            for (int t = 0; t < 4; t++) acc[i][j][t] = 0.f;

    // per-thread load descriptors: 6 x 16B chunks per stage (3 tiles)
    const __half* gptr[6];
    uint32_t soff[6];
#pragma unroll
    for (int j = 0; j < 6; j++) {
        int idx = tid + j * 256;
        int tile = idx >> 9;              // 0..2
        int ci = idx & 511;
        int row = ci >> 2;
        int c16 = ci & 3;
        soff[j] = (uint32_t)tile * TILEB + (uint32_t)row * ROWB + (uint32_t)c16 * 16u;
        const __half* base = (tile == 0) ? Ah : (tile == 1) ? Al : B;
        int grow = (tile < 2) ? (m0 + row) : (n0 + row);
        gptr[j] = base + (size_t)grow * K + c16 * 8;
    }

    int a_row = mw * 64 + (lane & 7) + ((lane >> 3) & 1) * 8;
    int a_col = (lane >> 4) * 8;
    int b_row = nw * 32 + (lane & 7) + ((lane >> 4) & 1) * 8;
    int b_col = ((lane >> 3) & 1) * 8;
    uint32_t a_off[4], b_off[2];
#pragma unroll
    for (int i = 0; i < 4; i++) a_off[i] = (uint32_t)(a_row + i * 16) * ROWB + (uint32_t)a_col * 2u;
#pragma unroll
    for (int p = 0; p < 2; p++) b_off[p] = (uint32_t)(b_row + p * 16) * ROWB + (uint32_t)b_col * 2u;

    const int nkt = K / BKg;
#pragma unroll
    for (int j = 0; j < 6; j++) cp16(sbase + soff[j], gptr[j]);
    asm volatile("cp.async.commit_group;" ::: "memory");

    for (int kt = 0; kt < nkt; kt++) {
        if (kt + 1 < nkt) {
            uint32_t sb2 = sbase + (uint32_t)((kt + 1) & 1) * STAGEB;
            int k0n = (kt + 1) * BKg;
#pragma unroll
            for (int j = 0; j < 6; j++) cp16(sb2 + soff[j], gptr[j] + k0n);
            asm volatile("cp.async.commit_group;" ::: "memory");
            asm volatile("cp.async.wait_group 1;" ::: "memory");
        } else {
            asm volatile("cp.async.wait_group 0;" ::: "memory");
        }
        __syncthreads();

        uint32_t stB = sbase + (uint32_t)(kt & 1) * STAGEB;
#pragma unroll
        for (int kk = 0; kk < BKg; kk += 16) {
            uint32_t koff = (uint32_t)kk * 2u;
            uint32_t af[4][4];
            uint32_t b0[4], b1[4];
            ldsm_x4(stB + 2 * TILEB + b_off[0] + koff, b0);
            ldsm_x4(stB + 2 * TILEB + b_off[1] + koff, b1);
#pragma unroll
            for (int i = 0; i < 4; i++)
                ldsm_x4(stB + 0 * TILEB + a_off[i] + koff, af[i]);   // Ah
#pragma unroll
            for (int i = 0; i < 4; i++) mma16816h(acc[i][0], af[i], b0);
#pragma unroll
            for (int i = 0; i < 4; i++) mma16816h(acc[i][1], af[i], b0 + 2);
#pragma unroll
            for (int i = 0; i < 4; i++) mma16816h(acc[i][2], af[i], b1);
#pragma unroll
            for (int i = 0; i < 4; i++) mma16816h(acc[i][3], af[i], b1 + 2);
#pragma unroll
            for (int i = 0; i < 4; i++)
                ldsm_x4(stB + 1 * TILEB + a_off[i] + koff, af[i]);   // Al
#pragma unroll
            for (int i = 0; i < 4; i++) mma16816h(acc[i][0], af[i], b0);
#pragma unroll
            for (int i = 0; i < 4; i++) mma16816h(acc[i][1], af[i], b0 + 2);
#pragma unroll
            for (int i = 0; i < 4; i++) mma16816h(acc[i][2], af[i], b1);
#pragma unroll
            for (int i = 0; i < 4; i++) mma16816h(acc[i][3], af[i], b1 + 2);
        }
        __syncthreads();
    }

    // output routing
    float* Cp; int ldC, coff;
    if (router) {
        if (n0 < 512)       { Cp = (n0 < 256) ? out_q : out_k; ldC = 256; coff = n0 & 255; }
        else if (n0 < 1024) { Cp = out_v; ldC = 512; coff = n0 - 512; }
        else                { Cp = out_g; ldC = 512; coff = n0 - 1024; }
    } else {
        Cp = out_q; ldC = 512; coff = n0;
    }

    int erow = m0 + mw * 64 + (lane >> 2);
    int ecol = coff + nw * 32 + (lane & 3) * 2;
#pragma unroll
    for (int i = 0; i < 4; i++) {
#pragma unroll
        for (int nt = 0; nt < 4; nt++) {
            float* c = acc[i][nt];
            size_t r0 = (size_t)(erow + i * 16) * ldC + ecol + nt * 8;
            size_t r1 = (size_t)(erow + i * 16 + 8) * ldC + ecol + nt * 8;
            *(float2*)(Cp + r0) = make_float2(c[0], c[1]);
            *(float2*)(Cp + r1) = make_float2(c[2], c[3]);
        }
    }
}

// ============== fp32 -> fp16 conversions ===================================
__device__ __forceinline__ void split4h_store(float4 v, __half* hi, __half* lo, size_t i4) {
    __half h0, h1, h2, h3, l0, l1, l2, l3;
    split_h(v.x, h0, l0); split_h(v.y, h1, l1);
    split_h(v.z, h2, l2); split_h(v.w, h3, l3);
    uint2 ph, pl;
    ph.x = ((uint32_t)__half_as_ushort(h1) << 16) | __half_as_ushort(h0);
    ph.y = ((uint32_t)__half_as_ushort(h3) << 16) | __half_as_ushort(h2);
    pl.x = ((uint32_t)__half_as_ushort(l1) << 16) | __half_as_ushort(l0);
    pl.y = ((uint32_t)__half_as_ushort(l3) << 16) | __half_as_ushort(l2);
    *(uint2*)(hi + i4) = ph;
    *(uint2*)(lo + i4) = pl;
}
__device__ __forceinline__ void conv4h_store(float4 v, __half* dst, size_t i4) {
    uint2 p;
    p.x = ((uint32_t)__half_as_ushort(__float2half_rn(v.y)) << 16) |
          __half_as_ushort(__float2half_rn(v.x));
    p.y = ((uint32_t)__half_as_ushort(__float2half_rn(v.w)) << 16) |
          __half_as_ushort(__float2half_rn(v.z));
    *(uint2*)(dst + i4) = p;
}

__global__ void conv_split4h(const float* __restrict__ src, __half* __restrict__ hi,
                             __half* __restrict__ lo, size_t n4) {
    size_t i = (size_t)blockIdx.x * blockDim.x + threadIdx.x;
    size_t stride = (size_t)gridDim.x * blockDim.x;
    for (; i < n4; i += stride) {
        float4 v = *(const float4*)(src + i * 4);
        split4h_store(v, hi, lo, i * 4);
    }
}

// fused weight conversion: wcat[1536][512] = [Wq|Wk|Wv|Wg], plus Wo
__global__ void conv_w_fused(const float* __restrict__ Wq, const float* __restrict__ Wk,
                             const float* __restrict__ Wv, const float* __restrict__ Wg,
                             const float* __restrict__ Wo,
                             __half* __restrict__ wcat, __half* __restrict__ wo) {
    size_t i = (size_t)blockIdx.x * blockDim.x + threadIdx.x;   // float4 idx, 262144 total
    if (i < 196608) {
        size_t e = i * 4;
        int R = (int)(e >> 9), c = (int)(e & 511);
        const float* src;
        int r;
        if (R < 256)       { src = Wq; r = R; }
        else if (R < 512)  { src = Wk; r = R - 256; }
        else if (R < 1024) { src = Wv; r = R - 512; }
        else               { src = Wg; r = R - 1024; }
        float4 v = *(const float4*)(src + (size_t)r * 512 + c);
        conv4h_store(v, wcat, e);
    } else {
        size_t e = (i - 196608) * 4;
        float4 v = *(const float4*)(Wo + e);
        conv4h_store(v, wo, e);
    }
}

// ---------------- low-rank gate: 16 rows per block (float4 LDS) ------------
__global__ void gk2_kernel(const float* __restrict__ x, const float* __restrict__ W1,
                           const float* __restrict__ W2, const float* __restrict__ bias,
                           float* __restrict__ gk) {
    extern __shared__ float sm[];
    float (*W1s)[516] = (float(*)[516])sm;
    float (*xs)[516]  = (float(*)[516])(sm + 16 * 516);
    float (*zs)[17]   = (float(*)[17])(sm + 32 * 516);
    int tid = threadIdx.x;                               // 256
    size_t row0 = (size_t)blockIdx.x * 16;

#pragma unroll
    for (int j = 0; j < 8; j++) {
        int e = (tid + j * 256) * 4;
        int r = e >> 9, c = e & 511;
        *(float4*)&W1s[r][c] = *(const float4*)(W1 + (size_t)r * 512 + c);
        *(float4*)&xs[r][c]  = *(const float4*)(x + (row0 + r) * 512 + c);
    }
    __syncthreads();
    {
        int r = tid >> 4, j = tid & 15;
        const float4* xr = (const float4*)&xs[r][0];
        const float4* wr = (const float4*)&W1s[j][0];
        float s = 0.f;
#pragma unroll 16
        for (int i = 0; i < 128; i++) {
            float4 a = xr[i], b = wr[i];
            s += a.x * b.x + a.y * b.y + a.z * b.z + a.w * b.w;
        }
        zs[r][j] = s;
    }
    __syncthreads();
    {
        int d = tid;
        float w2r[16];
#pragma unroll
        for (int q4 = 0; q4 < 4; q4++) {
            float4 w4 = *(const float4*)(W2 + (size_t)d * 16 + q4 * 4);
            w2r[q4 * 4] = w4.x; w2r[q4 * 4 + 1] = w4.y; w2r[q4 * 4 + 2] = w4.z; w2r[q4 * 4 + 3] = w4.w;
        }
        float b = bias[d];
#pragma unroll
        for (int r = 0; r < 16; r++) {
            float a = b;
#pragma unroll
            for (int j = 0; j < 16; j++) a += zs[r][j] * w2r[j];
            float ls = fminf(a, 0.f) - log1pf(expf(-fabsf(a)));
            gk[(row0 + r) * 256 + d] = ls * (1.f / 16.f);
        }
    }
}

// ======= chunk_state (tensor cores): cumsum gk, decay, U = k_dec^T @ v =====
#define CS_BC    0
#define CS_BLAST 16640
#define CS_KDH   16896
#define CS_KDL   26112
#define CS_VTH   35328
#define CS_VTL   53760
#define CS_SMEM  72192
__global__ void __launch_bounds__(256, 2) chunk_state_tc(
    const float* __restrict__ k, const float* __restrict__ v,
    float* __restrict__ gk, float* __restrict__ U, float* __restrict__ decay)
{
    extern __shared__ char smem[];
    float* bc = (float*)(smem + CS_BC);                  // [64][65]
    float* blast = (float*)(smem + CS_BLAST);
    __nv_bfloat16* kdTh = (__nv_bfloat16*)(smem + CS_KDH);
    __nv_bfloat16* kdTl = (__nv_bfloat16*)(smem + CS_KDL);
    __nv_bfloat16* vTh  = (__nv_bfloat16*)(smem + CS_VTH);
    __nv_bfloat16* vTl  = (__nv_bfloat16*)(smem + CS_VTL);
    uint32_t sb = smem_u32(smem);

    int ch = blockIdx.x;                      // B*N*H = 4096
    int h = ch % Hn;
    int n = (ch / Hn) % Nn;
    int b = ch / (Hn * Nn);
    int tid = threadIdx.x;
    int wid = tid >> 5, lane = tid & 31;
    size_t rowbase = (size_t)b * Tn + (size_t)n * 64;

#pragma unroll
    for (int i = 0; i < 16; i++) {
        int e = tid + i * 256;
        int c = e >> 6, d = e & 63;
        bc[c * 65 + d] = gk[(rowbase + c) * 256 + h * 64 + d];
    }
    __syncthreads();
    if (tid < 64) {
        float s = 0.f;
#pragma unroll
        for (int c = 0; c < 64; c++) { s += bc[c * 65 + tid]; bc[c * 65 + tid] = s; }
        blast[tid] = s;
        decay[((size_t)((b * Hn + h) * Nn + n)) * 64 + tid] = expf(s);
    }
    __syncthreads();

#pragma unroll
    for (int i = 0; i < 16; i++) {
        int e = tid + i * 256;
        int c = e >> 6, d = e & 63;
        float bcv = bc[c * 65 + d];
        gk[(rowbase + c) * 256 + h * 64 + d] = bcv;
        float kd = k[(rowbase + c) * 256 + h * 64 + d] * expf(blast[d] - bcv);
        __nv_bfloat16 hh, ll; split_bf(kd, hh, ll);
        kdTh[d * 72 + c] = hh;
        kdTl[d * 72 + c] = ll;
    }
#pragma unroll
    for (int it = 0; it < 8; it++) {
        int e4 = tid + it * 256;
        int c = e4 >> 5, vv4 = (e4 & 31) * 4;
        float4 vv = *(const float4*)(v + (rowbase + c) * 512 + h * 128 + vv4);
        __nv_bfloat16 hh, ll;
        split_bf(vv.x, hh, ll); vTh[(vv4 + 0) * 72 + c] = hh; vTl[(vv4 + 0) * 72 + c] = ll;
        split_bf(vv.y, hh, ll); vTh[(vv4 + 1) * 72 + c] = hh; vTl[(vv4 + 1) * 72 + c] = ll;
        split_bf(vv.z, hh, ll); vTh[(vv4 + 2) * 72 + c] = hh; vTl[(vv4 + 2) * 72 + c] = ll;
        split_bf(vv.w, hh, ll); vTh[(vv4 + 3) * 72 + c] = hh; vTl[(vv4 + 3) * 72 + c] = ll;
    }
    __syncthreads();

    int mw = wid & 3, nw = wid >> 2;
    float acc[8][4];
#pragma unroll
    for (int t = 0; t < 8; t++)
#pragma unroll
        for (int r = 0; r < 4; r++) acc[t][r] = 0.f;

    uint32_t a_base = sb + CS_KDH +
        ((uint32_t)(mw * 16 + (lane & 7) + ((lane >> 3) & 1) * 8) * 72u + (uint32_t)((lane >> 4) * 8)) * 2u;
    uint32_t b_rowoff = ((uint32_t)(nw * 64 + (lane & 7) + ((lane >> 4) & 1) * 8) * 72u +
                         (uint32_t)(((lane >> 3) & 1) * 8)) * 2u;
#pragma unroll
    for (int ks = 0; ks < 4; ks++) {
        uint32_t ko = (uint32_t)(ks * 16) * 2u;
        uint32_t ah[4], al[4], bh[4][4], bl[4][4];
        ldsm_x4(a_base + ko, ah);
        ldsm_x4(a_base + (CS_KDL - CS_KDH) + ko, al);
#pragma unroll
        for (int j = 0; j < 4; j++) {
            ldsm_x4(sb + CS_VTH + b_rowoff + (uint32_t)(j * 16 * 72 * 2) + ko, bh[j]);
            ldsm_x4(sb + CS_VTL + b_rowoff + (uint32_t)(j * 16 * 72 * 2) + ko, bl[j]);
        }
#pragma unroll
        for (int j = 0; j < 4; j++) mma16816(acc[j * 2 + 0], ah, bh[j]);
#pragma unroll
        for (int j = 0; j < 4; j++) mma16816(acc[j * 2 + 1], ah, bh[j] + 2);
#pragma unroll
        for (int j = 0; j < 4; j++) mma16816(acc[j * 2 + 0], ah, bl[j]);
#pragma unroll
        for (int j = 0; j < 4; j++) mma16816(acc[j * 2 + 1], ah, bl[j] + 2);
#pragma unroll
        for (int j = 0; j < 4; j++) mma16816(acc[j * 2 + 0], al, bh[j]);
#pragma unroll
        for (int j = 0; j < 4; j++) mma16816(acc[j * 2 + 1], al, bh[j] + 2);
    }

    size_t ubase = ((size_t)((b * Hn + h) * Nn + n)) * 8192;
    int d0 = mw * 16 + (lane >> 2);
#pragma unroll
    for (int j = 0; j < 4; j++) {
#pragma unroll
        for (int s = 0; s < 2; s++) {
            float* c = acc[j * 2 + s];
            int vv = nw * 64 + j * 16 + s * 8 + (lane & 3) * 2;
            *(float2*)(U + ubase + (size_t)d0 * 128 + vv) = make_float2(c[0], c[1]);
            *(float2*)(U + ubase + (size_t)(d0 + 8) * 128 + vv) = make_float2(c[2], c[3]);
        }
    }
}

// ---------------- inter-chunk scan (parallel over elements) ----------------
__global__ void scan_kernel(float* __restrict__ U, const float* __restrict__ decay) {
    int bh = blockIdx.x >> 5;
    int e = ((blockIdx.x & 31) << 8) + threadIdx.x;
    float s = 0.f;
    size_t base = (size_t)bh * Nn * 8192 + e;
    const float* dp = decay + (size_t)bh * Nn * 64 + (e >> 7);
    for (int n = 0; n < Nn; n++) {
        float u = U[base];
        U[base] = s;
        s = dp[0] * s + u;
        base += 8192; dp += 64;
    }
}

// ======= output (tensor cores): o = tril(qe ke^T) v + qe S_init ============
#define OT_QEH 0
#define OT_QEL 9216
#define OT_KEH 18432
#define OT_KEL 27648
#define OT_ASH 36864
#define OT_ASL 46080
#define OT_VTH 55296
#define OT_VTL 73728
#define OT_STH 18432
#define OT_STL 92160
#define OT_SMEM 110592
__global__ void __launch_bounds__(256, 2) output_tc(
    const float* __restrict__ q, const float* __restrict__ k,
    const float* __restrict__ v, const float* __restrict__ gk,
    const float* __restrict__ Sinit, float* __restrict__ o)
{
    extern __shared__ char smem[];
    __nv_bfloat16* qeh = (__nv_bfloat16*)(smem + OT_QEH);
    __nv_bfloat16* qel = (__nv_bfloat16*)(smem + OT_QEL);
    __nv_bfloat16* keh = (__nv_bfloat16*)(smem + OT_KEH);
    __nv_bfloat16* kel = (__nv_bfloat16*)(smem + OT_KEL);
    __nv_bfloat16* Ash = (__nv_bfloat16*)(smem + OT_ASH);
    __nv_bfloat16* Asl = (__nv_bfloat16*)(smem + OT_ASL);
    __nv_bfloat16* vTh = (__nv_bfloat16*)(smem + OT_VTH);
    __nv_bfloat16* vTl = (__nv_bfloat16*)(smem + OT_VTL);
    __nv_bfloat16* STh = (__nv_bfloat16*)(smem + OT_STH);
    __nv_bfloat16* STl = (__nv_bfloat16*)(smem + OT_STL);
    uint32_t sb = smem_u32(smem);

    int ch = blockIdx.x;
    int h = ch % Hn;
    int n = (ch / Hn) % Nn;
    int b = ch / (Hn * Nn);
    int tid = threadIdx.x;
    int wid = tid >> 5, lane = tid & 31;
    size_t rowbase = (size_t)b * Tn + (size_t)n * 64;
    const float scale = 0.125f;

#pragma unroll
    for (int i = 0; i < 16; i++) {
        int e = tid + i * 256;
        int c = e >> 6, d = e & 63;
        float bcv = gk[(rowbase + c) * 256 + h * 64 + d];
        float eb = expf(bcv);
        float qe = q[(rowbase + c) * 256 + h * 64 + d] * eb * scale;
        float ke = k[(rowbase + c) * 256 + h * 64 + d] * expf(-bcv);
        __nv_bfloat16 hh, ll;
        split_bf(qe, hh, ll); qeh[c * 72 + d] = hh; qel[c * 72 + d] = ll;
        split_bf(ke, hh, ll); keh[c * 72 + d] = hh; kel[c * 72 + d] = ll;
    }
#pragma unroll
    for (int it = 0; it < 8; it++) {
        int e4 = tid + it * 256;
        int c = e4 >> 5, vv4 = (e4 & 31) * 4;
        float4 vv = *(const float4*)(v + (rowbase + c) * 512 + h * 128 + vv4);
        __nv_bfloat16 hh, ll;
        split_bf(vv.x, hh, ll); vTh[(vv4 + 0) * 72 + c] = hh; vTl[(vv4 + 0) * 72 + c] = ll;
        split_bf(vv.y, hh, ll); vTh[(vv4 + 1) * 72 + c] = hh; vTl[(vv4 + 1) * 72 + c] = ll;
        split_bf(vv.z, hh, ll); vTh[(vv4 + 2) * 72 + c] = hh; vTl[(vv4 + 2) * 72 + c] = ll;
        split_bf(vv.w, hh, ll); vTh[(vv4 + 3) * 72 + c] = hh; vTl[(vv4 + 3) * 72 + c] = ll;
    }
    __syncthreads();

    {
        int mw = wid & 3, nw = wid >> 2;
        float acc1[4][4];
#pragma unroll
        for (int t = 0; t < 4; t++)
#pragma unroll
            for (int r = 0; r < 4; r++) acc1[t][r] = 0.f;

        uint32_t a_base = sb + OT_QEH +
            ((uint32_t)(mw * 16 + (lane & 7) + ((lane >> 3) & 1) * 8) * 72u + (uint32_t)((lane >> 4) * 8)) * 2u;
        uint32_t b_base = sb + OT_KEH +
            ((uint32_t)(nw * 32 + (lane & 7) + ((lane >> 4) & 1) * 8) * 72u + (uint32_t)(((lane >> 3) & 1) * 8)) * 2u;
#pragma unroll
        for (int ks = 0; ks < 4; ks++) {
            uint32_t ko = (uint32_t)(ks * 16) * 2u;
            uint32_t ah[4], al[4], bh0[4], bh1[4], bl0[4], bl1[4];
            ldsm_x4(a_base + ko, ah);
            ldsm_x4(a_base + (OT_QEL - OT_QEH) + ko, al);
            ldsm_x4(b_base + ko, bh0);
            ldsm_x4(b_base + (uint32_t)(16 * 72 * 2) + ko, bh1);
            ldsm_x4(b_base + (OT_KEL - OT_KEH) + ko, bl0);
            ldsm_x4(b_base + (OT_KEL - OT_KEH) + (uint32_t)(16 * 72 * 2) + ko, bl1);
            mma16816(acc1[0], ah, bh0); mma16816(acc1[1], ah, bh0 + 2);
            mma16816(acc1[2], ah, bh1); mma16816(acc1[3], ah, bh1 + 2);
            mma16816(acc1[0], ah, bl0); mma16816(acc1[1], ah, bl0 + 2);
            mma16816(acc1[2], ah, bl1); mma16816(acc1[3], ah, bl1 + 2);
            mma16816(acc1[0], al, bh0); mma16816(acc1[1], al, bh0 + 2);
            mma16816(acc1[2], al, bh1); mma16816(acc1[3], al, bh1 + 2);
        }
        __syncthreads();

        int r0 = mw * 16 + (lane >> 2);
#pragma unroll
        for (int p = 0; p < 2; p++) {
#pragma unroll
            for (int s = 0; s < 2; s++) {
                float* cfr = acc1[p * 2 + s];
                int e0 = nw * 32 + p * 16 + s * 8 + (lane & 3) * 2;
#pragma unroll
                for (int rr = 0; rr < 2; rr++) {
                    int c = r0 + rr * 8;
#pragma unroll
                    for (int cc = 0; cc < 2; cc++) {
                        int e = e0 + cc;
                        float val = (e <= c) ? cfr[rr * 2 + cc] : 0.f;
                        __nv_bfloat16 hh, ll; split_bf(val, hh, ll);
                        Ash[c * 72 + e] = hh;
                        Asl[c * 72 + e] = ll;
                    }
                }
            }
        }
    }

    size_t sbase = ((size_t)((b * Hn + h) * Nn + n)) * 8192;
#pragma unroll
    for (int it = 0; it < 8; it++) {
        int e4 = tid + it * 256;
        int d = e4 >> 5, vv4 = (e4 & 31) * 4;
        float4 sv = *(const float4*)(Sinit + sbase + (size_t)d * 128 + vv4);
        __nv_bfloat16 hh, ll;
        split_bf(sv.x, hh, ll); STh[(vv4 + 0) * 72 + d] = hh; STl[(vv4 + 0) * 72 + d] = ll;
        split_bf(sv.y, hh, ll); STh[(vv4 + 1) * 72 + d] = hh; STl[(vv4 + 1) * 72 + d] = ll;
        split_bf(sv.z, hh, ll); STh[(vv4 + 2) * 72 + d] = hh; STl[(vv4 + 2) * 72 + d] = ll;
        split_bf(sv.w, hh, ll); STh[(vv4 + 3) * 72 + d] = hh; STl[(vv4 + 3) * 72 + d] = ll;
    }
    __syncthreads();

    {
        int mw = wid & 3, nw = wid >> 2;
        float acc[8][4];
#pragma unroll
        for (int t = 0; t < 8; t++)
#pragma unroll
            for (int r = 0; r < 4; r++) acc[t][r] = 0.f;

        uint32_t arow = ((uint32_t)(mw * 16 + (lane & 7) + ((lane >> 3) & 1) * 8) * 72u +
                         (uint32_t)((lane >> 4) * 8)) * 2u;
        uint32_t brow = ((uint32_t)(nw * 64 + (lane & 7) + ((lane >> 4) & 1) * 8) * 72u +
                        (uint32_t)(((lane >> 3) & 1) * 8)) * 2u;

#pragma unroll
        for (int ks = 0; ks < 4; ks++) {
            uint32_t ko = (uint32_t)(ks * 16) * 2u;
            uint32_t ah[4], al[4], bh[4][4], bl[4][4];
            ldsm_x4(sb + OT_ASH + arow + ko, ah);
            ldsm_x4(sb + OT_ASL + arow + ko, al);
#pragma unroll
            for (int j = 0; j < 4; j++) {
                ldsm_x4(sb + OT_VTH + brow + (uint32_t)(j * 16 * 72 * 2) + ko, bh[j]);
                ldsm_x4(sb + OT_VTL + brow + (uint32_t)(j * 16 * 72 * 2) + ko, bl[j]);
            }
#pragma unroll
            for (int j = 0; j < 4; j++) mma16816(acc[j * 2 + 0], ah, bh[j]);
#pragma unroll
            for (int j = 0; j < 4; j++) mma16816(acc[j * 2 + 1], ah, bh[j] + 2);
#pragma unroll
            for (int j = 0; j < 4; j++) mma16816(acc[j * 2 + 0], ah, bl[j]);
#pragma unroll
            for (int j = 0; j < 4; j++) mma16816(acc[j * 2 + 1], ah, bl[j] + 2);
#pragma unroll
            for (int j = 0; j < 4; j++) mma16816(acc[j * 2 + 0], al, bh[j]);
#pragma unroll
            for (int j = 0; j < 4; j++) mma16816(acc[j * 2 + 1], al, bh[j] + 2);
        }
#pragma unroll
        for (int ks = 0; ks < 4; ks++) {
            uint32_t ko = (uint32_t)(ks * 16) * 2u;
            uint32_t ah[4], al[4], bh[4][4], bl[4][4];
            ldsm_x4(sb + OT_QEH + arow + ko, ah);
            ldsm_x4(sb + OT_QEL + arow + ko, al);
#pragma unroll
            for (int j = 0; j < 4; j++) {
                ldsm_x4(sb + OT_STH + brow + (uint32_t)(j * 16 * 72 * 2) + ko, bh[j]);
                ldsm_x4(sb + OT_STL + brow + (uint32_t)(j * 16 * 72 * 2) + ko, bl[j]);
            }
#pragma unroll
            for (int j = 0; j < 4; j++) mma16816(acc[j * 2 + 0], ah, bh[j]);
#pragma unroll
            for (int j = 0; j < 4; j++) mma16816(acc[j * 2 + 1], ah, bh[j] + 2);
#pragma unroll
            for (int j = 0; j < 4; j++) mma16816(acc[j * 2 + 0], ah, bl[j]);
#pragma unroll
            for (int j = 0; j < 4; j++) mma16816(acc[j * 2 + 1], ah, bl[j] + 2);
#pragma unroll
            for (int j = 0; j < 4; j++) mma16816(acc[j * 2 + 0], al, bh[j]);
#pragma unroll
            for (int j = 0; j < 4; j++) mma16816(acc[j * 2 + 1], al, bh[j] + 2);
        }

        int c0 = mw * 16 + (lane >> 2);
#pragma unroll
        for (int j = 0; j < 4; j++) {
#pragma unroll
            for (int s = 0; s < 2; s++) {
                float* cf = acc[j * 2 + s];
                int vv = nw * 64 + j * 16 + s * 8 + (lane & 3) * 2;
                *(float2*)(o + (rowbase + c0) * 512 + h * 128 + vv) = make_float2(cf[0], cf[1]);
                *(float2*)(o + (rowbase + c0 + 8) * 512 + h * 128 + vv) = make_float2(cf[2], cf[3]);
            }
        }
    }
}

// ---------------- RMS-norm + SiLU gating -> fp16 hi/lo ---------------------
__global__ void gate_kernel(const float* __restrict__ o, const float* __restrict__ g,
                            const float* __restrict__ gw,
                            __half* __restrict__ oh, __half* __restrict__ ol) {
    int row = blockIdx.x;
    int tid = threadIdx.x;               // 512
    __shared__ float wsum[16];
    size_t idx = (size_t)row * 512 + tid;
    float ov = o[idx];
    float sq = ov * ov;
#pragma unroll
    for (int off = 16; off; off >>= 1) sq += __shfl_down_sync(0xffffffffu, sq, off);
    if ((tid & 31) == 0) wsum[tid >> 5] = sq;
    __syncthreads();
    int h = tid >> 7;
    float ss = wsum[h * 4] + wsum[h * 4 + 1] + wsum[h * 4 + 2] + wsum[h * 4 + 3];
    float rms = rsqrtf(ss * (1.f / 128.f) + 1e-5f);
    float gv = g[idx];
    float sig = 1.f / (1.f + expf(-gv));
    float val = ov * rms * gw[tid & 127] * gv * sig;
    __half hh, ll; split_h(val, hh, ll);
    oh[idx] = hh;
    ol[idx] = ll;
}

// ---------------- launcher --------------------------------------------------
extern "C" void kernel_launch(void* const* d_in, const int* in_sizes, int n_in,
                              void* d_out, int out_size) {
    const float* x    = (const float*)d_in[0];
    const float* Wq   = (const float*)d_in[1];
    const float* Wk   = (const float*)d_in[2];
    const float* Wv   = (const float*)d_in[3];
    const float* Wg   = (const float*)d_in[4];
    const float* Wgk1 = (const float*)d_in[5];
    const float* Wgk2 = (const float*)d_in[6];
    const float* bgk2 = (const float*)d_in[7];
    const float* gnw  = (const float*)d_in[8];
    const float* Wo   = (const float*)d_in[9];
    float* out = (float*)d_out;

    float *q, *k, *v, *g, *gk, *U, *dec, *o;
    cudaGetSymbolAddress((void**)&q,   g_q);
    cudaGetSymbolAddress((void**)&k,   g_k);
    cudaGetSymbolAddress((void**)&v,   g_v);
    cudaGetSymbolAddress((void**)&g,   g_g);
    cudaGetSymbolAddress((void**)&gk,  g_gk);
    cudaGetSymbolAddress((void**)&U,   g_U);
    cudaGetSymbolAddress((void**)&dec, g_dec);
    cudaGetSymbolAddress((void**)&o,   g_o);

    __half *xh, *xl, *oh, *ol, *wcat, *wo;
    cudaGetSymbolAddress((void**)&xh, g_xh);     cudaGetSymbolAddress((void**)&xl, g_xl);
    cudaGetSymbolAddress((void**)&oh, g_oh);     cudaGetSymbolAddress((void**)&ol, g_ol);
    cudaGetSymbolAddress((void**)&wcat, g_wcat); cudaGetSymbolAddress((void**)&wo, g_wo);

    const int smem_gemm = 2 * (int)STAGEB;                  // 61440
    cudaFuncSetAttribute(gemm_f16, cudaFuncAttributeMaxDynamicSharedMemorySize, smem_gemm);
    cudaFuncSetAttribute(chunk_state_tc, cudaFuncAttributeMaxDynamicSharedMemorySize, CS_SMEM);
    cudaFuncSetAttribute(output_tc, cudaFuncAttributeMaxDynamicSharedMemorySize, OT_SMEM);
    const int smem_gk = (32 * 516 + 16 * 17) * 4;
    cudaFuncSetAttribute(gk2_kernel, cudaFuncAttributeMaxDynamicSharedMemorySize, smem_gk);

    conv_split4h<<<2048, 256>>>(x, xh, xl, (size_t)BTn * Dn / 4);
    conv_w_fused<<<1024, 256>>>(Wq, Wk, Wv, Wg, Wo, wcat, wo);

    // fused qkvg projection (N = 1536)
    gemm_f16<<<dim3(BTn / 128, 12), 256, smem_gemm>>>(xh, xl, wcat, q, k, v, g, BTn, Dn, 1);

    gk2_kernel<<<BTn / 16, 256, smem_gk>>>(x, Wgk1, Wgk2, bgk2, gk);
    chunk_state_tc<<<Bn * Nn * Hn, 256, CS_SMEM>>>(k, v, gk, U, dec);
    scan_kernel<<<Bn * Hn * 32, 256>>>(U, dec);
    output_tc<<<Bn * Nn * Hn, 256, OT_SMEM>>>(q, k, v, gk, U, o);
    gate_kernel<<<BTn, 512>>>(o, g, gnw, oh, ol);

    // output projection (N = 512)
    gemm_f16<<<dim3(BTn / 128, 4), 256, smem_gemm>>>(oh, ol, wo, out, 0, 0, 0, BTn, Dn, 0);
}

// round 7
// speedup vs baseline: 4.8405x; 1.0817x over previous
#include <cuda_runtime.h>
#include <cuda_bf16.h>
#include <cuda_fp16.h>
#include <math.h>
#include <stdint.h>

// Problem constants
#define Bn 8
#define Tn 8192
#define Dn 512
#define Hn 4
#define DKn 256
#define DVn 512
#define HKn 64
#define HVn 128
#define Cn 64
#define Nn 128               // T / C
#define BTn (Bn * Tn)        // 65536
#define LOWn 16

// ---------------- scratch (device globals; no runtime allocation) ----------
__device__ float g_q[(size_t)BTn * DKn];
__device__ float g_k[(size_t)BTn * DKn];
__device__ float g_v[(size_t)BTn * DVn];
__device__ float g_g[(size_t)BTn * DVn];
__device__ float g_gk[(size_t)BTn * DKn];      // cumsummed gk (written by chunk_state)
__device__ float g_z[(size_t)BTn * LOWn];      // low-rank intermediate
__device__ float g_U[(size_t)Bn * Hn * Nn * HKn * HVn];
__device__ float g_dec[(size_t)Bn * Hn * Nn * HKn];
__device__ float g_o[(size_t)BTn * DVn];

// fp16 buffers for GEMMs
__device__ __half g_xh[(size_t)BTn * Dn];
__device__ __half g_xl[(size_t)BTn * Dn];
__device__ __half g_oh[(size_t)BTn * DVn];
__device__ __half g_ol[(size_t)BTn * DVn];
#define WCATR 1664                                   // q|k|v|g|W1(16)+pad(112)
__device__ __half g_wcat[(size_t)WCATR * Dn];
__device__ __half g_wo[(size_t)Dn * DVn];

// ================= warp-MMA helpers =================
__device__ __forceinline__ uint32_t smem_u32(const void* p) {
    uint32_t a;
    asm("{ .reg .u64 t; cvta.to.shared.u64 t, %1; cvt.u32.u64 %0, t; }" : "=r"(a) : "l"(p));
    return a;
}
__device__ __forceinline__ void ldsm_x4(uint32_t addr, uint32_t* r) {
    asm volatile("ldmatrix.sync.aligned.m8n8.x4.shared.b16 {%0,%1,%2,%3}, [%4];"
                 : "=r"(r[0]), "=r"(r[1]), "=r"(r[2]), "=r"(r[3]) : "r"(addr));
}
__device__ __forceinline__ void mma16816(float* c, const uint32_t* a, const uint32_t* b) {
    asm volatile("mma.sync.aligned.m16n8k16.row.col.f32.bf16.bf16.f32 "
                 "{%0,%1,%2,%3}, {%4,%5,%6,%7}, {%8,%9}, {%0,%1,%2,%3};"
                 : "+f"(c[0]), "+f"(c[1]), "+f"(c[2]), "+f"(c[3])
                 : "r"(a[0]), "r"(a[1]), "r"(a[2]), "r"(a[3]), "r"(b[0]), "r"(b[1]));
}
__device__ __forceinline__ void mma16816h(float* c, const uint32_t* a, const uint32_t* b) {
    asm volatile("mma.sync.aligned.m16n8k16.row.col.f32.f16.f16.f32 "
                 "{%0,%1,%2,%3}, {%4,%5,%6,%7}, {%8,%9}, {%0,%1,%2,%3};"
                 : "+f"(c[0]), "+f"(c[1]), "+f"(c[2]), "+f"(c[3])
                 : "r"(a[0]), "r"(a[1]), "r"(a[2]), "r"(a[3]), "r"(b[0]), "r"(b[1]));
}
__device__ __forceinline__ void cp16(uint32_t s, const void* g) {
    asm volatile("cp.async.cg.shared.global [%0], [%1], 16;" :: "r"(s), "l"(g));
}
__device__ __forceinline__ void split_bf(float v, __nv_bfloat16& h, __nv_bfloat16& l) {
    h = __float2bfloat16(v);
    l = __float2bfloat16(v - __bfloat162float(h));
}
__device__ __forceinline__ void split_h(float v, __half& h, __half& l) {
    h = __float2half_rn(v);
    l = __float2half_rn(v - __half2float(h));
}

// ============== fp16 tensor-core GEMM with 2-product split =================
// C[m][n] = sum_k A[m][k]*B[n][k];  A = Ah + Al (fp16 split), B fp16 single.
// CTA tile 128x128, BK=32, cp.async 3-stage. 8 warps = 2x4, each 64x32.
// router==1: N-space = [q(256)|k(256)|v(512)|g(512)|z(16+pad)], outputs routed.
// router==0: single output out_q with ldC = 512.
#define BKg 32
#define ROWB 80u
#define TILEB 10240u
#define STAGEB 30720u                    // 3 tiles
__global__ void __launch_bounds__(256, 2) gemm_f16(
    const __half* __restrict__ Ah, const __half* __restrict__ Al,
    const __half* __restrict__ B,
    float* __restrict__ out_q, float* __restrict__ out_k,
    float* __restrict__ out_v, float* __restrict__ out_g,
    float* __restrict__ out_z,
    int M, int K, int router)
{
    extern __shared__ char smem[];
    uint32_t sbase = smem_u32(smem);

    int tid = threadIdx.x;
    int wid = tid >> 5, lane = tid & 31;
    int mw = wid & 1, nw = wid >> 1;
    int m0 = blockIdx.x * 128, n0 = blockIdx.y * 128;

    float acc[4][4][4];
#pragma unroll
    for (int i = 0; i < 4; i++)
#pragma unroll
        for (int j = 0; j < 4; j++)
#pragma unroll
            for (int t = 0; t < 4; t++) acc[i][j][t] = 0.f;

    // per-thread load descriptors: 6 x 16B chunks per stage (3 tiles)
    const __half* gptr[6];
    uint32_t soff[6];
#pragma unroll
    for (int j = 0; j < 6; j++) {
        int idx = tid + j * 256;
        int tile = idx >> 9;              // 0..2
        int ci = idx & 511;
        int row = ci >> 2;
        int c16 = ci & 3;
        soff[j] = (uint32_t)tile * TILEB + (uint32_t)row * ROWB + (uint32_t)c16 * 16u;
        const __half* base = (tile == 0) ? Ah : (tile == 1) ? Al : B;
        int grow = (tile < 2) ? (m0 + row) : (n0 + row);
        gptr[j] = base + (size_t)grow * K + c16 * 8;
    }

    int a_row = mw * 64 + (lane & 7) + ((lane >> 3) & 1) * 8;
    int a_col = (lane >> 4) * 8;
    int b_row = nw * 32 + (lane & 7) + ((lane >> 4) & 1) * 8;
    int b_col = ((lane >> 3) & 1) * 8;
    uint32_t a_off[4], b_off[2];
#pragma unroll
    for (int i = 0; i < 4; i++) a_off[i] = (uint32_t)(a_row + i * 16) * ROWB + (uint32_t)a_col * 2u;
#pragma unroll
    for (int p = 0; p < 2; p++) b_off[p] = (uint32_t)(b_row + p * 16) * ROWB + (uint32_t)b_col * 2u;

    const int nkt = K / BKg;
    // prologue: stages 0 and 1
#pragma unroll
    for (int j = 0; j < 6; j++) cp16(sbase + soff[j], gptr[j]);
    asm volatile("cp.async.commit_group;" ::: "memory");
#pragma unroll
    for (int j = 0; j < 6; j++) cp16(sbase + STAGEB + soff[j], gptr[j] + BKg);
    asm volatile("cp.async.commit_group;" ::: "memory");

    for (int kt = 0; kt < nkt; kt++) {
        asm volatile("cp.async.wait_group 1;" ::: "memory");
        __syncthreads();
        if (kt + 2 < nkt) {
            uint32_t sb2 = sbase + (uint32_t)((kt + 2) % 3) * STAGEB;
            int k0n = (kt + 2) * BKg;
#pragma unroll
            for (int j = 0; j < 6; j++) cp16(sb2 + soff[j], gptr[j] + k0n);
        }
        asm volatile("cp.async.commit_group;" ::: "memory");

        uint32_t stB = sbase + (uint32_t)(kt % 3) * STAGEB;
#pragma unroll
        for (int kk = 0; kk < BKg; kk += 16) {
            uint32_t koff = (uint32_t)kk * 2u;
            uint32_t af[4][4];
            uint32_t b0[4], b1[4];
            ldsm_x4(stB + 2 * TILEB + b_off[0] + koff, b0);
            ldsm_x4(stB + 2 * TILEB + b_off[1] + koff, b1);
#pragma unroll
            for (int i = 0; i < 4; i++)
                ldsm_x4(stB + 0 * TILEB + a_off[i] + koff, af[i]);   // Ah
#pragma unroll
            for (int i = 0; i < 4; i++) mma16816h(acc[i][0], af[i], b0);
#pragma unroll
            for (int i = 0; i < 4; i++) mma16816h(acc[i][1], af[i], b0 + 2);
#pragma unroll
            for (int i = 0; i < 4; i++) mma16816h(acc[i][2], af[i], b1);
#pragma unroll
            for (int i = 0; i < 4; i++) mma16816h(acc[i][3], af[i], b1 + 2);
#pragma unroll
            for (int i = 0; i < 4; i++)
                ldsm_x4(stB + 1 * TILEB + a_off[i] + koff, af[i]);   // Al
#pragma unroll
            for (int i = 0; i < 4; i++) mma16816h(acc[i][0], af[i], b0);
#pragma unroll
            for (int i = 0; i < 4; i++) mma16816h(acc[i][1], af[i], b0 + 2);
#pragma unroll
            for (int i = 0; i < 4; i++) mma16816h(acc[i][2], af[i], b1);
#pragma unroll
            for (int i = 0; i < 4; i++) mma16816h(acc[i][3], af[i], b1 + 2);
        }
    }

    // z tile: only cols 0..15 valid
    if (router && n0 == 1536) {
        if (nw == 0) {
            int erow = m0 + mw * 64 + (lane >> 2);
            int ecol = (lane & 3) * 2;
#pragma unroll
            for (int i = 0; i < 4; i++) {
#pragma unroll
                for (int nt = 0; nt < 2; nt++) {
                    float* c = acc[i][nt];
                    size_t r0 = (size_t)(erow + i * 16) * 16 + ecol + nt * 8;
                    size_t r1 = (size_t)(erow + i * 16 + 8) * 16 + ecol + nt * 8;
                    *(float2*)(out_z + r0) = make_float2(c[0], c[1]);
                    *(float2*)(out_z + r1) = make_float2(c[2], c[3]);
                }
            }
        }
        return;
    }

    float* Cp; int ldC, coff;
    if (router) {
        if (n0 < 512)       { Cp = (n0 < 256) ? out_q : out_k; ldC = 256; coff = n0 & 255; }
        else if (n0 < 1024) { Cp = out_v; ldC = 512; coff = n0 - 512; }
        else                { Cp = out_g; ldC = 512; coff = n0 - 1024; }
    } else {
        Cp = out_q; ldC = 512; coff = n0;
    }

    int erow = m0 + mw * 64 + (lane >> 2);
    int ecol = coff + nw * 32 + (lane & 3) * 2;
#pragma unroll
    for (int i = 0; i < 4; i++) {
#pragma unroll
        for (int nt = 0; nt < 4; nt++) {
            float* c = acc[i][nt];
            size_t r0 = (size_t)(erow + i * 16) * ldC + ecol + nt * 8;
            size_t r1 = (size_t)(erow + i * 16 + 8) * ldC + ecol + nt * 8;
            *(float2*)(Cp + r0) = make_float2(c[0], c[1]);
            *(float2*)(Cp + r1) = make_float2(c[2], c[3]);
        }
    }
}

// ============== fp32 -> fp16 conversions ===================================
__device__ __forceinline__ void split4h_store(float4 v, __half* hi, __half* lo, size_t i4) {
    __half h0, h1, h2, h3, l0, l1, l2, l3;
    split_h(v.x, h0, l0); split_h(v.y, h1, l1);
    split_h(v.z, h2, l2); split_h(v.w, h3, l3);
    uint2 ph, pl;
    ph.x = ((uint32_t)__half_as_ushort(h1) << 16) | __half_as_ushort(h0);
    ph.y = ((uint32_t)__half_as_ushort(h3) << 16) | __half_as_ushort(h2);
    pl.x = ((uint32_t)__half_as_ushort(l1) << 16) | __half_as_ushort(l0);
    pl.y = ((uint32_t)__half_as_ushort(l3) << 16) | __half_as_ushort(l2);
    *(uint2*)(hi + i4) = ph;
    *(uint2*)(lo + i4) = pl;
}
__device__ __forceinline__ void conv4h_store(float4 v, __half* dst, size_t i4) {
    uint2 p;
    p.x = ((uint32_t)__half_as_ushort(__float2half_rn(v.y)) << 16) |
          __half_as_ushort(__float2half_rn(v.x));
    p.y = ((uint32_t)__half_as_ushort(__float2half_rn(v.w)) << 16) |
          __half_as_ushort(__float2half_rn(v.z));
    *(uint2*)(dst + i4) = p;
}

__global__ void conv_split4h(const float* __restrict__ src, __half* __restrict__ hi,
                             __half* __restrict__ lo, size_t n4) {
    size_t i = (size_t)blockIdx.x * blockDim.x + threadIdx.x;
    size_t stride = (size_t)gridDim.x * blockDim.x;
    for (; i < n4; i += stride) {
        float4 v = *(const float4*)(src + i * 4);
        split4h_store(v, hi, lo, i * 4);
    }
}

// fused weight conversion: wcat[1664][512] = [Wq|Wk|Wv|Wg|W1|zeros], plus Wo
// total float4: wcat 212992 + Wo 65536 = 278528 = 1088 * 256
__global__ void conv_w_fused(const float* __restrict__ Wq, const float* __restrict__ Wk,
                             const float* __restrict__ Wv, const float* __restrict__ Wg,
                             const float* __restrict__ W1, const float* __restrict__ Wo,
                             __half* __restrict__ wcat, __half* __restrict__ wo) {
    size_t i = (size_t)blockIdx.x * blockDim.x + threadIdx.x;
    if (i < 212992) {
        size_t e = i * 4;
        int R = (int)(e >> 9), c = (int)(e & 511);
        if (R >= 1552) {                       // zero padding rows
            *(uint2*)(wcat + e) = make_uint2(0u, 0u);
            return;
        }
        const float* src; int r;
        if (R < 256)       { src = Wq; r = R; }
        else if (R < 512)  { src = Wk; r = R - 256; }
        else if (R < 1024) { src = Wv; r = R - 512; }
        else if (R < 1536) { src = Wg; r = R - 1024; }
        else               { src = W1; r = R - 1536; }
        float4 v = *(const float4*)(src + (size_t)r * 512 + c);
        conv4h_store(v, wcat, e);
    } else if (i < 278528) {
        size_t e = (i - 212992) * 4;
        float4 v = *(const float4*)(Wo + e);
        conv4h_store(v, wo, e);
    }
}

// ======= chunk_state: gk from z (low-rank stage 2), cumsum, U = k_dec^T @ v
#define CS_BC    0
#define CS_BLAST 16640
#define CS_Z     16896
#define CS_W2    21248
#define CS_BS    25600
#define CS_KDH   25856
#define CS_KDL   35072
#define CS_VTH   44288
#define CS_VTL   62720
#define CS_SMEM  81152
__global__ void __launch_bounds__(256, 2) chunk_state_tc(
    const float* __restrict__ k, const float* __restrict__ v,
    const float* __restrict__ z, const float* __restrict__ W2,
    const float* __restrict__ bias,
    float* __restrict__ gk, float* __restrict__ U, float* __restrict__ decay)
{
    extern __shared__ char smem[];
    float* bc = (float*)(smem + CS_BC);                  // [64][65]
    float* blast = (float*)(smem + CS_BLAST);
    float* zed = (float*)(smem + CS_Z);                  // [64][17]
    float* w2s = (float*)(smem + CS_W2);                 // [64][17]
    float* bs  = (float*)(smem + CS_BS);
    __nv_bfloat16* kdTh = (__nv_bfloat16*)(smem + CS_KDH);
    __nv_bfloat16* kdTl = (__nv_bfloat16*)(smem + CS_KDL);
    __nv_bfloat16* vTh  = (__nv_bfloat16*)(smem + CS_VTH);
    __nv_bfloat16* vTl  = (__nv_bfloat16*)(smem + CS_VTL);
    uint32_t sb = smem_u32(smem);

    int ch = blockIdx.x;                      // B*N*H = 4096
    int h = ch % Hn;
    int n = (ch / Hn) % Nn;
    int b = ch / (Hn * Nn);
    int tid = threadIdx.x;
    int wid = tid >> 5, lane = tid & 31;
    size_t rowbase = (size_t)b * Tn + (size_t)n * 64;

    // phase 0: load z rows, W2 rows for this head, bias
    {
        int r = tid >> 2, j4 = (tid & 3) * 4;
        float4 zv = *(const float4*)(z + (rowbase + r) * 16 + j4);
        zed[r * 17 + j4] = zv.x; zed[r * 17 + j4 + 1] = zv.y;
        zed[r * 17 + j4 + 2] = zv.z; zed[r * 17 + j4 + 3] = zv.w;
        float4 wv = *(const float4*)(W2 + (size_t)(h * 64 + r) * 16 + j4);
        w2s[r * 17 + j4] = wv.x; w2s[r * 17 + j4 + 1] = wv.y;
        w2s[r * 17 + j4 + 2] = wv.z; w2s[r * 17 + j4 + 3] = wv.w;
        if (tid < 64) bs[tid] = bias[h * 64 + tid];
    }
    __syncthreads();

    // phase 1: bc[c][d] = logsigmoid(z[c]·W2[d] + bias[d]) / 16
#pragma unroll
    for (int i = 0; i < 16; i++) {
        int e = tid + i * 256;
        int c = e >> 6, d = e & 63;
        float a = bs[d];
#pragma unroll
        for (int j = 0; j < 16; j++) a += zed[c * 17 + j] * w2s[d * 17 + j];
        float ls = fminf(a, 0.f) - log1pf(expf(-fabsf(a)));
        bc[c * 65 + d] = ls * (1.f / 16.f);
    }
    __syncthreads();
    if (tid < 64) {
        float s = 0.f;
#pragma unroll
        for (int c = 0; c < 64; c++) { s += bc[c * 65 + tid]; bc[c * 65 + tid] = s; }
        blast[tid] = s;
        decay[((size_t)((b * Hn + h) * Nn + n)) * 64 + tid] = expf(s);
    }
    __syncthreads();

    // phase 2: write cumsum to gmem + kdT split (transposed [d][c])
#pragma unroll
    for (int i = 0; i < 16; i++) {
        int e = tid + i * 256;
        int c = e >> 6, d = e & 63;
        float bcv = bc[c * 65 + d];
        gk[(rowbase + c) * 256 + h * 64 + d] = bcv;
        float kd = k[(rowbase + c) * 256 + h * 64 + d] * expf(blast[d] - bcv);
        __nv_bfloat16 hh, ll; split_bf(kd, hh, ll);
        kdTh[d * 72 + c] = hh;
        kdTl[d * 72 + c] = ll;
    }
    // phase 3: v transposed split [vv][c]
#pragma unroll
    for (int it = 0; it < 8; it++) {
        int e4 = tid + it * 256;
        int c = e4 >> 5, vv4 = (e4 & 31) * 4;
        float4 vv = *(const float4*)(v + (rowbase + c) * 512 + h * 128 + vv4);
        __nv_bfloat16 hh, ll;
        split_bf(vv.x, hh, ll); vTh[(vv4 + 0) * 72 + c] = hh; vTl[(vv4 + 0) * 72 + c] = ll;
        split_bf(vv.y, hh, ll); vTh[(vv4 + 1) * 72 + c] = hh; vTl[(vv4 + 1) * 72 + c] = ll;
        split_bf(vv.z, hh, ll); vTh[(vv4 + 2) * 72 + c] = hh; vTl[(vv4 + 2) * 72 + c] = ll;
        split_bf(vv.w, hh, ll); vTh[(vv4 + 3) * 72 + c] = hh; vTl[(vv4 + 3) * 72 + c] = ll;
    }
    __syncthreads();

    // phase 4: U[d][vv] = kdT @ vT^T, M=64 N=128 K=64
    int mw = wid & 3, nw = wid >> 2;
    float acc[8][4];
#pragma unroll
    for (int t = 0; t < 8; t++)
#pragma unroll
        for (int r = 0; r < 4; r++) acc[t][r] = 0.f;

    uint32_t a_base = sb + CS_KDH +
        ((uint32_t)(mw * 16 + (lane & 7) + ((lane >> 3) & 1) * 8) * 72u + (uint32_t)((lane >> 4) * 8)) * 2u;
    uint32_t b_rowoff = ((uint32_t)(nw * 64 + (lane & 7) + ((lane >> 4) & 1) * 8) * 72u +
                         (uint32_t)(((lane >> 3) & 1) * 8)) * 2u;
#pragma unroll
    for (int ks = 0; ks < 4; ks++) {
        uint32_t ko = (uint32_t)(ks * 16) * 2u;
        uint32_t ah[4], al[4], bh[4][4], bl[4][4];
        ldsm_x4(a_base + ko, ah);
        ldsm_x4(a_base + (CS_KDL - CS_KDH) + ko, al);
#pragma unroll
        for (int j = 0; j < 4; j++) {
            ldsm_x4(sb + CS_VTH + b_rowoff + (uint32_t)(j * 16 * 72 * 2) + ko, bh[j]);
            ldsm_x4(sb + CS_VTL + b_rowoff + (uint32_t)(j * 16 * 72 * 2) + ko, bl[j]);
        }
#pragma unroll
        for (int j = 0; j < 4; j++) mma16816(acc[j * 2 + 0], ah, bh[j]);
#pragma unroll
        for (int j = 0; j < 4; j++) mma16816(acc[j * 2 + 1], ah, bh[j] + 2);
#pragma unroll
        for (int j = 0; j < 4; j++) mma16816(acc[j * 2 + 0], ah, bl[j]);
#pragma unroll
        for (int j = 0; j < 4; j++) mma16816(acc[j * 2 + 1], ah, bl[j] + 2);
#pragma unroll
        for (int j = 0; j < 4; j++) mma16816(acc[j * 2 + 0], al, bh[j]);
#pragma unroll
        for (int j = 0; j < 4; j++) mma16816(acc[j * 2 + 1], al, bh[j] + 2);
    }

    size_t ubase = ((size_t)((b * Hn + h) * Nn + n)) * 8192;
    int d0 = mw * 16 + (lane >> 2);
#pragma unroll
    for (int j = 0; j < 4; j++) {
#pragma unroll
        for (int s = 0; s < 2; s++) {
            float* c = acc[j * 2 + s];
            int vv = nw * 64 + j * 16 + s * 8 + (lane & 3) * 2;
            *(float2*)(U + ubase + (size_t)d0 * 128 + vv) = make_float2(c[0], c[1]);
            *(float2*)(U + ubase + (size_t)(d0 + 8) * 128 + vv) = make_float2(c[2], c[3]);
        }
    }
}

// ---------------- inter-chunk scan (parallel over elements) ----------------
__global__ void scan_kernel(float* __restrict__ U, const float* __restrict__ decay) {
    int bh = blockIdx.x >> 5;
    int e = ((blockIdx.x & 31) << 8) + threadIdx.x;
    float s = 0.f;
    size_t base = (size_t)bh * Nn * 8192 + e;
    const float* dp = decay + (size_t)bh * Nn * 64 + (e >> 7);
    for (int n = 0; n < Nn; n++) {
        float u = U[base];
        U[base] = s;
        s = dp[0] * s + u;
        base += 8192; dp += 64;
    }
}

// ======= output (tensor cores): o = tril(qe ke^T) v + qe S_init ============
// smem (bytes): qeh 0 (9216), qel 9216 (9216),
//   X1 18432 (18432): keh/kel -> Ash/Asl
//   X2 36864 (36864): STh/STl -> vTh/vTl       total 73728
#define OT_QEH 0
#define OT_QEL 9216
#define OT_X1  18432
#define OT_X1L 27648
#define OT_X2  36864
#define OT_X2L 55296
#define OT_SMEM 73728
__global__ void __launch_bounds__(256, 2) output_tc(
    const float* __restrict__ q, const float* __restrict__ k,
    const float* __restrict__ v, const float* __restrict__ gk,
    const float* __restrict__ Sinit, float* __restrict__ o)
{
    extern __shared__ char smem[];
    __nv_bfloat16* qeh = (__nv_bfloat16*)(smem + OT_QEH);
    __nv_bfloat16* qel = (__nv_bfloat16*)(smem + OT_QEL);
    __nv_bfloat16* x1h = (__nv_bfloat16*)(smem + OT_X1);    // ke -> Ash
    __nv_bfloat16* x1l = (__nv_bfloat16*)(smem + OT_X1L);
    __nv_bfloat16* x2h = (__nv_bfloat16*)(smem + OT_X2);    // ST -> vT
    __nv_bfloat16* x2l = (__nv_bfloat16*)(smem + OT_X2L);
    uint32_t sb = smem_u32(smem);

    int ch = blockIdx.x;
    int h = ch % Hn;
    int n = (ch / Hn) % Nn;
    int b = ch / (Hn * Nn);
    int tid = threadIdx.x;
    int wid = tid >> 5, lane = tid & 31;
    size_t rowbase = (size_t)b * Tn + (size_t)n * 64;
    const float scale = 0.125f;

    int mw = wid & 3, nw = wid >> 2;
    // warp-level addressing (M=64 rows / N=128 cols mapping)
    uint32_t arow = ((uint32_t)(mw * 16 + (lane & 7) + ((lane >> 3) & 1) * 8) * 72u +
                     (uint32_t)((lane >> 4) * 8)) * 2u;
    uint32_t brow = ((uint32_t)(nw * 64 + (lane & 7) + ((lane >> 4) & 1) * 8) * 72u +
                    (uint32_t)(((lane >> 3) & 1) * 8)) * 2u;

    float acc[8][4];
#pragma unroll
    for (int t = 0; t < 8; t++)
#pragma unroll
        for (int r = 0; r < 4; r++) acc[t][r] = 0.f;

    // phase 1: qe split [c][d] + ST split [vv][d] (X2)
#pragma unroll
    for (int i = 0; i < 16; i++) {
        int e = tid + i * 256;
        int c = e >> 6, d = e & 63;
        float bcv = gk[(rowbase + c) * 256 + h * 64 + d];
        float qe = q[(rowbase + c) * 256 + h * 64 + d] * expf(bcv) * scale;
        __nv_bfloat16 hh, ll;
        split_bf(qe, hh, ll); qeh[c * 72 + d] = hh; qel[c * 72 + d] = ll;
    }
    size_t sbase = ((size_t)((b * Hn + h) * Nn + n)) * 8192;
#pragma unroll
    for (int it = 0; it < 8; it++) {
        int e4 = tid + it * 256;
        int d = e4 >> 5, vv4 = (e4 & 31) * 4;
        float4 sv = *(const float4*)(Sinit + sbase + (size_t)d * 128 + vv4);
        __nv_bfloat16 hh, ll;
        split_bf(sv.x, hh, ll); x2h[(vv4 + 0) * 72 + d] = hh; x2l[(vv4 + 0) * 72 + d] = ll;
        split_bf(sv.y, hh, ll); x2h[(vv4 + 1) * 72 + d] = hh; x2l[(vv4 + 1) * 72 + d] = ll;
        split_bf(sv.z, hh, ll); x2h[(vv4 + 2) * 72 + d] = hh; x2l[(vv4 + 2) * 72 + d] = ll;
        split_bf(sv.w, hh, ll); x2h[(vv4 + 3) * 72 + d] = hh; x2l[(vv4 + 3) * 72 + d] = ll;
    }
    __syncthreads();

    // phase 2: acc += qe @ ST  (M=64 N=128 K=64)
#pragma unroll
    for (int ks = 0; ks < 4; ks++) {
        uint32_t ko = (uint32_t)(ks * 16) * 2u;
        uint32_t ah[4], al[4], bh[4][4], bl[4][4];
        ldsm_x4(sb + OT_QEH + arow + ko, ah);
        ldsm_x4(sb + OT_QEL + arow + ko, al);
#pragma unroll
        for (int j = 0; j < 4; j++) {
            ldsm_x4(sb + OT_X2 + brow + (uint32_t)(j * 16 * 72 * 2) + ko, bh[j]);
            ldsm_x4(sb + OT_X2L + brow + (uint32_t)(j * 16 * 72 * 2) + ko, bl[j]);
        }
#pragma unroll
        for (int j = 0; j < 4; j++) mma16816(acc[j * 2 + 0], ah, bh[j]);
#pragma unroll
        for (int j = 0; j < 4; j++) mma16816(acc[j * 2 + 1], ah, bh[j] + 2);
#pragma unroll
        for (int j = 0; j < 4; j++) mma16816(acc[j * 2 + 0], ah, bl[j]);
#pragma unroll
        for (int j = 0; j < 4; j++) mma16816(acc[j * 2 + 1], ah, bl[j] + 2);
#pragma unroll
        for (int j = 0; j < 4; j++) mma16816(acc[j * 2 + 0], al, bh[j]);
#pragma unroll
        for (int j = 0; j < 4; j++) mma16816(acc[j * 2 + 1], al, bh[j] + 2);
    }
    __syncthreads();     // ST reads complete before vT overwrites X2

    // phase 3: ke split [e][d] -> X1 ; vT split [vv][c] -> X2
#pragma unroll
    for (int i = 0; i < 16; i++) {
        int e = tid + i * 256;
        int c = e >> 6, d = e & 63;
        float bcv = gk[(rowbase + c) * 256 + h * 64 + d];
        float ke = k[(rowbase + c) * 256 + h * 64 + d] * expf(-bcv);
        __nv_bfloat16 hh, ll;
        split_bf(ke, hh, ll); x1h[c * 72 + d] = hh; x1l[c * 72 + d] = ll;
    }
#pragma unroll
    for (int it = 0; it < 8; it++) {
        int e4 = tid + it * 256;
        int c = e4 >> 5, vv4 = (e4 & 31) * 4;
        float4 vv = *(const float4*)(v + (rowbase + c) * 512 + h * 128 + vv4);
        __nv_bfloat16 hh, ll;
        split_bf(vv.x, hh, ll); x2h[(vv4 + 0) * 72 + c] = hh; x2l[(vv4 + 0) * 72 + c] = ll;
        split_bf(vv.y, hh, ll); x2h[(vv4 + 1) * 72 + c] = hh; x2l[(vv4 + 1) * 72 + c] = ll;
        split_bf(vv.z, hh, ll); x2h[(vv4 + 2) * 72 + c] = hh; x2l[(vv4 + 2) * 72 + c] = ll;
        split_bf(vv.w, hh, ll); x2h[(vv4 + 3) * 72 + c] = hh; x2l[(vv4 + 3) * 72 + c] = ll;
    }
    __syncthreads();

    // phase 4: acc1 = qe @ ke^T  (M=64 N=64 K=64), warp map 4x2
    float acc1[4][4];
#pragma unroll
    for (int t = 0; t < 4; t++)
#pragma unroll
        for (int r = 0; r < 4; r++) acc1[t][r] = 0.f;
    {
        uint32_t b_base = sb + OT_X1 +
            ((uint32_t)(nw * 32 + (lane & 7) + ((lane >> 4) & 1) * 8) * 72u + (uint32_t)(((lane >> 3) & 1) * 8)) * 2u;
        uint32_t a_base = sb + OT_QEH + arow;
#pragma unroll
        for (int ks = 0; ks < 4; ks++) {
            uint32_t ko = (uint32_t)(ks * 16) * 2u;
            uint32_t ah[4], al[4], bh0[4], bh1[4], bl0[4], bl1[4];
            ldsm_x4(a_base + ko, ah);
            ldsm_x4(a_base + (OT_QEL - OT_QEH) + ko, al);
            ldsm_x4(b_base + ko, bh0);
            ldsm_x4(b_base + (uint32_t)(16 * 72 * 2) + ko, bh1);
            ldsm_x4(b_base + (OT_X1L - OT_X1) + ko, bl0);
            ldsm_x4(b_base + (OT_X1L - OT_X1) + (uint32_t)(16 * 72 * 2) + ko, bl1);
            mma16816(acc1[0], ah, bh0); mma16816(acc1[1], ah, bh0 + 2);
            mma16816(acc1[2], ah, bh1); mma16816(acc1[3], ah, bh1 + 2);
            mma16816(acc1[0], ah, bl0); mma16816(acc1[1], ah, bl0 + 2);
            mma16816(acc1[2], ah, bl1); mma16816(acc1[3], ah, bl1 + 2);
            mma16816(acc1[0], al, bh0); mma16816(acc1[1], al, bh0 + 2);
            mma16816(acc1[2], al, bh1); mma16816(acc1[3], al, bh1 + 2);
        }
    }
    __syncthreads();     // ke reads done before Ash overlay

    // phase 5: mask + split-store A -> X1 [c][e]
    {
        int r0 = mw * 16 + (lane >> 2);
#pragma unroll
        for (int p = 0; p < 2; p++) {
#pragma unroll
            for (int s = 0; s < 2; s++) {
                float* cfr = acc1[p * 2 + s];
                int e0 = nw * 32 + p * 16 + s * 8 + (lane & 3) * 2;
#pragma unroll
                for (int rr = 0; rr < 2; rr++) {
                    int c = r0 + rr * 8;
#pragma unroll
                    for (int cc = 0; cc < 2; cc++) {
                        int e = e0 + cc;
                        float val = (e <= c) ? cfr[rr * 2 + cc] : 0.f;
                        __nv_bfloat16 hh, ll; split_bf(val, hh, ll);
                        x1h[c * 72 + e] = hh;
                        x1l[c * 72 + e] = ll;
                    }
                }
            }
        }
    }
    __syncthreads();

    // phase 6: acc += A @ vT  (M=64 N=128 K=64)
#pragma unroll
    for (int ks = 0; ks < 4; ks++) {
        uint32_t ko = (uint32_t)(ks * 16) * 2u;
        uint32_t ah[4], al[4], bh[4][4], bl[4][4];
        ldsm_x4(sb + OT_X1 + arow + ko, ah);
        ldsm_x4(sb + OT_X1L + arow + ko, al);
#pragma unroll
        for (int j = 0; j < 4; j++) {
            ldsm_x4(sb + OT_X2 + brow + (uint32_t)(j * 16 * 72 * 2) + ko, bh[j]);
            ldsm_x4(sb + OT_X2L + brow + (uint32_t)(j * 16 * 72 * 2) + ko, bl[j]);
        }
#pragma unroll
        for (int j = 0; j < 4; j++) mma16816(acc[j * 2 + 0], ah, bh[j]);
#pragma unroll
        for (int j = 0; j < 4; j++) mma16816(acc[j * 2 + 1], ah, bh[j] + 2);
#pragma unroll
        for (int j = 0; j < 4; j++) mma16816(acc[j * 2 + 0], ah, bl[j]);
#pragma unroll
        for (int j = 0; j < 4; j++) mma16816(acc[j * 2 + 1], ah, bl[j] + 2);
#pragma unroll
        for (int j = 0; j < 4; j++) mma16816(acc[j * 2 + 0], al, bh[j]);
#pragma unroll
        for (int j = 0; j < 4; j++) mma16816(acc[j * 2 + 1], al, bh[j] + 2);
    }

    int c0 = mw * 16 + (lane >> 2);
#pragma unroll
    for (int j = 0; j < 4; j++) {
#pragma unroll
        for (int s = 0; s < 2; s++) {
            float* cf = acc[j * 2 + s];
            int vv = nw * 64 + j * 16 + s * 8 + (lane & 3) * 2;
            *(float2*)(o + (rowbase + c0) * 512 + h * 128 + vv) = make_float2(cf[0], cf[1]);
            *(float2*)(o + (rowbase + c0 + 8) * 512 + h * 128 + vv) = make_float2(cf[2], cf[3]);
        }
    }
}

// ---------------- RMS-norm + SiLU gating -> fp16 hi/lo ---------------------
__global__ void gate_kernel(const float* __restrict__ o, const float* __restrict__ g,
                            const float* __restrict__ gw,
                            __half* __restrict__ oh, __half* __restrict__ ol) {
    int row = blockIdx.x;
    int tid = threadIdx.x;               // 512
    __shared__ float wsum[16];
    size_t idx = (size_t)row * 512 + tid;
    float ov = o[idx];
    float sq = ov * ov;
#pragma unroll
    for (int off = 16; off; off >>= 1) sq += __shfl_down_sync(0xffffffffu, sq, off);
    if ((tid & 31) == 0) wsum[tid >> 5] = sq;
    __syncthreads();
    int h = tid >> 7;
    float ss = wsum[h * 4] + wsum[h * 4 + 1] + wsum[h * 4 + 2] + wsum[h * 4 + 3];
    float rms = rsqrtf(ss * (1.f / 128.f) + 1e-5f);
    float gv = g[idx];
    float sig = 1.f / (1.f + expf(-gv));
    float val = ov * rms * gw[tid & 127] * gv * sig;
    __half hh, ll; split_h(val, hh, ll);
    oh[idx] = hh;
    ol[idx] = ll;
}

// ---------------- launcher --------------------------------------------------
extern "C" void kernel_launch(void* const* d_in, const int* in_sizes, int n_in,
                              void* d_out, int out_size) {
    const float* x    = (const float*)d_in[0];
    const float* Wq   = (const float*)d_in[1];
    const float* Wk   = (const float*)d_in[2];
    const float* Wv   = (const float*)d_in[3];
    const float* Wg   = (const float*)d_in[4];
    const float* Wgk1 = (const float*)d_in[5];
    const float* Wgk2 = (const float*)d_in[6];
    const float* bgk2 = (const float*)d_in[7];
    const float* gnw  = (const float*)d_in[8];
    const float* Wo   = (const float*)d_in[9];
    float* out = (float*)d_out;

    float *q, *k, *v, *g, *gk, *z, *U, *dec, *o;
    cudaGetSymbolAddress((void**)&q,   g_q);
    cudaGetSymbolAddress((void**)&k,   g_k);
    cudaGetSymbolAddress((void**)&v,   g_v);
    cudaGetSymbolAddress((void**)&g,   g_g);
    cudaGetSymbolAddress((void**)&gk,  g_gk);
    cudaGetSymbolAddress((void**)&z,   g_z);
    cudaGetSymbolAddress((void**)&U,   g_U);
    cudaGetSymbolAddress((void**)&dec, g_dec);
    cudaGetSymbolAddress((void**)&o,   g_o);

    __half *xh, *xl, *oh, *ol, *wcat, *wo;
    cudaGetSymbolAddress((void**)&xh, g_xh);     cudaGetSymbolAddress((void**)&xl, g_xl);
    cudaGetSymbolAddress((void**)&oh, g_oh);     cudaGetSymbolAddress((void**)&ol, g_ol);
    cudaGetSymbolAddress((void**)&wcat, g_wcat); cudaGetSymbolAddress((void**)&wo, g_wo);

    const int smem_gemm = 3 * (int)STAGEB;                  // 92160
    cudaFuncSetAttribute(gemm_f16, cudaFuncAttributeMaxDynamicSharedMemorySize, smem_gemm);
    cudaFuncSetAttribute(chunk_state_tc, cudaFuncAttributeMaxDynamicSharedMemorySize, CS_SMEM);
    cudaFuncSetAttribute(output_tc, cudaFuncAttributeMaxDynamicSharedMemorySize, OT_SMEM);

    conv_split4h<<<2048, 256>>>(x, xh, xl, (size_t)BTn * Dn / 4);
    conv_w_fused<<<1088, 256>>>(Wq, Wk, Wv, Wg, Wgk1, Wo, wcat, wo);

    // fused qkvg + z projection (N = 1664 -> 13 tiles)
    gemm_f16<<<dim3(BTn / 128, 13), 256, smem_gemm>>>(xh, xl, wcat, q, k, v, g, z, BTn, Dn, 1);

    chunk_state_tc<<<Bn * Nn * Hn, 256, CS_SMEM>>>(k, v, z, Wgk2, bgk2, gk, U, dec);
    scan_kernel<<<Bn * Hn * 32, 256>>>(U, dec);
    output_tc<<<Bn * Nn * Hn, 256, OT_SMEM>>>(q, k, v, gk, U, o);
    gate_kernel<<<BTn, 512>>>(o, g, gnw, oh, ol);

    // output projection (N = 512)
    gemm_f16<<<dim3(BTn / 128, 4), 256, smem_gemm>>>(oh, ol, wo, out, 0, 0, 0, 0, BTn, Dn, 0);
}

// round 8
// speedup vs baseline: 4.8729x; 1.0067x over previous
#include <cuda_runtime.h>
#include <cuda_bf16.h>
#include <cuda_fp16.h>
#include <math.h>
#include <stdint.h>

// Problem constants
#define Bn 8
#define Tn 8192
#define Dn 512
#define Hn 4
#define DKn 256
#define DVn 512
#define HKn 64
#define HVn 128
#define Cn 64
#define Nn 128               // T / C
#define BTn (Bn * Tn)        // 65536
#define LOWn 16

// ---------------- scratch (device globals; no runtime allocation) ----------
__device__ float g_q[(size_t)BTn * DKn];
__device__ float g_k[(size_t)BTn * DKn];
__device__ float g_v[(size_t)BTn * DVn];
__device__ float g_g[(size_t)BTn * DVn];
__device__ float g_gk[(size_t)BTn * DKn];      // cumsummed gk (written by chunk_state)
__device__ float g_z[(size_t)BTn * LOWn];      // low-rank intermediate
__device__ float g_U[(size_t)Bn * Hn * Nn * HKn * HVn];
__device__ float g_dec[(size_t)Bn * Hn * Nn * HKn];
__device__ float g_o[(size_t)BTn * DVn];

// fp16 buffers for GEMMs
__device__ __half g_xh[(size_t)BTn * Dn];
__device__ __half g_xl[(size_t)BTn * Dn];
__device__ __half g_oh[(size_t)BTn * DVn];
__device__ __half g_ol[(size_t)BTn * DVn];
#define WCATR 1664                                   // q|k|v|g|W1(16)+pad(112)
__device__ __half g_wcat[(size_t)WCATR * Dn];
__device__ __half g_wo[(size_t)Dn * DVn];

// ================= warp-MMA helpers =================
__device__ __forceinline__ uint32_t smem_u32(const void* p) {
    uint32_t a;
    asm("{ .reg .u64 t; cvta.to.shared.u64 t, %1; cvt.u32.u64 %0, t; }" : "=r"(a) : "l"(p));
    return a;
}
__device__ __forceinline__ void ldsm_x4(uint32_t addr, uint32_t* r) {
    asm volatile("ldmatrix.sync.aligned.m8n8.x4.shared.b16 {%0,%1,%2,%3}, [%4];"
                 : "=r"(r[0]), "=r"(r[1]), "=r"(r[2]), "=r"(r[3]) : "r"(addr));
}
__device__ __forceinline__ void mma16816(float* c, const uint32_t* a, const uint32_t* b) {
    asm volatile("mma.sync.aligned.m16n8k16.row.col.f32.bf16.bf16.f32 "
                 "{%0,%1,%2,%3}, {%4,%5,%6,%7}, {%8,%9}, {%0,%1,%2,%3};"
                 : "+f"(c[0]), "+f"(c[1]), "+f"(c[2]), "+f"(c[3])
                 : "r"(a[0]), "r"(a[1]), "r"(a[2]), "r"(a[3]), "r"(b[0]), "r"(b[1]));
}
__device__ __forceinline__ void mma16816h(float* c, const uint32_t* a, const uint32_t* b) {
    asm volatile("mma.sync.aligned.m16n8k16.row.col.f32.f16.f16.f32 "
                 "{%0,%1,%2,%3}, {%4,%5,%6,%7}, {%8,%9}, {%0,%1,%2,%3};"
                 : "+f"(c[0]), "+f"(c[1]), "+f"(c[2]), "+f"(c[3])
                 : "r"(a[0]), "r"(a[1]), "r"(a[2]), "r"(a[3]), "r"(b[0]), "r"(b[1]));
}
__device__ __forceinline__ void cp16(uint32_t s, const void* g) {
    asm volatile("cp.async.cg.shared.global [%0], [%1], 16;" :: "r"(s), "l"(g));
}
__device__ __forceinline__ void split_bf(float v, __nv_bfloat16& h, __nv_bfloat16& l) {
    h = __float2bfloat16(v);
    l = __float2bfloat16(v - __bfloat162float(h));
}
__device__ __forceinline__ void split_h(float v, __half& h, __half& l) {
    h = __float2half_rn(v);
    l = __float2half_rn(v - __half2float(h));
}

// ============== fp16 tensor-core GEMM with 2-product split =================
// C[m][n] = sum_k A[m][k]*B[n][k];  A = Ah + Al (fp16 split), B fp16 single.
// CTA tile 128x128, BK=32, cp.async 3-stage. 8 warps = 2x4, each 64x32.
#define BKg 32
#define ROWB 80u
#define TILEB 10240u
#define STAGEB 30720u                    // 3 tiles
__global__ void __launch_bounds__(256, 2) gemm_f16(
    const __half* __restrict__ Ah, const __half* __restrict__ Al,
    const __half* __restrict__ B,
    float* __restrict__ out_q, float* __restrict__ out_k,
    float* __restrict__ out_v, float* __restrict__ out_g,
    float* __restrict__ out_z,
    int M, int K, int router)
{
    extern __shared__ char smem[];
    uint32_t sbase = smem_u32(smem);

    int tid = threadIdx.x;
    int wid = tid >> 5, lane = tid & 31;
    int mw = wid & 1, nw = wid >> 1;
    int m0 = blockIdx.x * 128, n0 = blockIdx.y * 128;

    float acc[4][4][4];
#pragma unroll
    for (int i = 0; i < 4; i++)
#pragma unroll
        for (int j = 0; j < 4; j++)
#pragma unroll
            for (int t = 0; t < 4; t++) acc[i][j][t] = 0.f;

    const __half* gptr[6];
    uint32_t soff[6];
#pragma unroll
    for (int j = 0; j < 6; j++) {
        int idx = tid + j * 256;
        int tile = idx >> 9;              // 0..2
        int ci = idx & 511;
        int row = ci >> 2;
        int c16 = ci & 3;
        soff[j] = (uint32_t)tile * TILEB + (uint32_t)row * ROWB + (uint32_t)c16 * 16u;
        const __half* base = (tile == 0) ? Ah : (tile == 1) ? Al : B;
        int grow = (tile < 2) ? (m0 + row) : (n0 + row);
        gptr[j] = base + (size_t)grow * K + c16 * 8;
    }

    int a_row = mw * 64 + (lane & 7) + ((lane >> 3) & 1) * 8;
    int a_col = (lane >> 4) * 8;
    int b_row = nw * 32 + (lane & 7) + ((lane >> 4) & 1) * 8;
    int b_col = ((lane >> 3) & 1) * 8;
    uint32_t a_off[4], b_off[2];
#pragma unroll
    for (int i = 0; i < 4; i++) a_off[i] = (uint32_t)(a_row + i * 16) * ROWB + (uint32_t)a_col * 2u;
#pragma unroll
    for (int p = 0; p < 2; p++) b_off[p] = (uint32_t)(b_row + p * 16) * ROWB + (uint32_t)b_col * 2u;

    const int nkt = K / BKg;
#pragma unroll
    for (int j = 0; j < 6; j++) cp16(sbase + soff[j], gptr[j]);
    asm volatile("cp.async.commit_group;" ::: "memory");
#pragma unroll
    for (int j = 0; j < 6; j++) cp16(sbase + STAGEB + soff[j], gptr[j] + BKg);
    asm volatile("cp.async.commit_group;" ::: "memory");

    for (int kt = 0; kt < nkt; kt++) {
        asm volatile("cp.async.wait_group 1;" ::: "memory");
        __syncthreads();
        if (kt + 2 < nkt) {
            uint32_t sb2 = sbase + (uint32_t)((kt + 2) % 3) * STAGEB;
            int k0n = (kt + 2) * BKg;
#pragma unroll
            for (int j = 0; j < 6; j++) cp16(sb2 + soff[j], gptr[j] + k0n);
        }
        asm volatile("cp.async.commit_group;" ::: "memory");

        uint32_t stB = sbase + (uint32_t)(kt % 3) * STAGEB;
#pragma unroll
        for (int kk = 0; kk < BKg; kk += 16) {
            uint32_t koff = (uint32_t)kk * 2u;
            uint32_t af[4][4];
            uint32_t b0[4], b1[4];
            ldsm_x4(stB + 2 * TILEB + b_off[0] + koff, b0);
            ldsm_x4(stB + 2 * TILEB + b_off[1] + koff, b1);
#pragma unroll
            for (int i = 0; i < 4; i++)
                ldsm_x4(stB + 0 * TILEB + a_off[i] + koff, af[i]);   // Ah
#pragma unroll
            for (int i = 0; i < 4; i++) mma16816h(acc[i][0], af[i], b0);
#pragma unroll
            for (int i = 0; i < 4; i++) mma16816h(acc[i][1], af[i], b0 + 2);
#pragma unroll
            for (int i = 0; i < 4; i++) mma16816h(acc[i][2], af[i], b1);
#pragma unroll
            for (int i = 0; i < 4; i++) mma16816h(acc[i][3], af[i], b1 + 2);
#pragma unroll
            for (int i = 0; i < 4; i++)
                ldsm_x4(stB + 1 * TILEB + a_off[i] + koff, af[i]);   // Al
#pragma unroll
            for (int i = 0; i < 4; i++) mma16816h(acc[i][0], af[i], b0);
#pragma unroll
            for (int i = 0; i < 4; i++) mma16816h(acc[i][1], af[i], b0 + 2);
#pragma unroll
            for (int i = 0; i < 4; i++) mma16816h(acc[i][2], af[i], b1);
#pragma unroll
            for (int i = 0; i < 4; i++) mma16816h(acc[i][3], af[i], b1 + 2);
        }
    }

    // z tile: only cols 0..15 valid
    if (router && n0 == 1536) {
        if (nw == 0) {
            int erow = m0 + mw * 64 + (lane >> 2);
            int ecol = (lane & 3) * 2;
#pragma unroll
            for (int i = 0; i < 4; i++) {
#pragma unroll
                for (int nt = 0; nt < 2; nt++) {
                    float* c = acc[i][nt];
                    size_t r0 = (size_t)(erow + i * 16) * 16 + ecol + nt * 8;
                    size_t r1 = (size_t)(erow + i * 16 + 8) * 16 + ecol + nt * 8;
                    *(float2*)(out_z + r0) = make_float2(c[0], c[1]);
                    *(float2*)(out_z + r1) = make_float2(c[2], c[3]);
                }
            }
        }
        return;
    }

    float* Cp; int ldC, coff;
    if (router) {
        if (n0 < 512)       { Cp = (n0 < 256) ? out_q : out_k; ldC = 256; coff = n0 & 255; }
        else if (n0 < 1024) { Cp = out_v; ldC = 512; coff = n0 - 512; }
        else                { Cp = out_g; ldC = 512; coff = n0 - 1024; }
    } else {
        Cp = out_q; ldC = 512; coff = n0;
    }

    int erow = m0 + mw * 64 + (lane >> 2);
    int ecol = coff + nw * 32 + (lane & 3) * 2;
#pragma unroll
    for (int i = 0; i < 4; i++) {
#pragma unroll
        for (int nt = 0; nt < 4; nt++) {
            float* c = acc[i][nt];
            size_t r0 = (size_t)(erow + i * 16) * ldC + ecol + nt * 8;
            size_t r1 = (size_t)(erow + i * 16 + 8) * ldC + ecol + nt * 8;
            *(float2*)(Cp + r0) = make_float2(c[0], c[1]);
            *(float2*)(Cp + r1) = make_float2(c[2], c[3]);
        }
    }
}

// ============== fp32 -> fp16 conversions ===================================
__device__ __forceinline__ void split4h_store(float4 v, __half* hi, __half* lo, size_t i4) {
    __half h0, h1, h2, h3, l0, l1, l2, l3;
    split_h(v.x, h0, l0); split_h(v.y, h1, l1);
    split_h(v.z, h2, l2); split_h(v.w, h3, l3);
    uint2 ph, pl;
    ph.x = ((uint32_t)__half_as_ushort(h1) << 16) | __half_as_ushort(h0);
    ph.y = ((uint32_t)__half_as_ushort(h3) << 16) | __half_as_ushort(h2);
    pl.x = ((uint32_t)__half_as_ushort(l1) << 16) | __half_as_ushort(l0);
    pl.y = ((uint32_t)__half_as_ushort(l3) << 16) | __half_as_ushort(l2);
    *(uint2*)(hi + i4) = ph;
    *(uint2*)(lo + i4) = pl;
}
__device__ __forceinline__ void conv4h_store(float4 v, __half* dst, size_t i4) {
    uint2 p;
    p.x = ((uint32_t)__half_as_ushort(__float2half_rn(v.y)) << 16) |
          __half_as_ushort(__float2half_rn(v.x));
    p.y = ((uint32_t)__half_as_ushort(__float2half_rn(v.w)) << 16) |
          __half_as_ushort(__float2half_rn(v.z));
    *(uint2*)(dst + i4) = p;
}

__global__ void conv_split4h(const float* __restrict__ src, __half* __restrict__ hi,
                             __half* __restrict__ lo, size_t n4) {
    size_t i = (size_t)blockIdx.x * blockDim.x + threadIdx.x;
    size_t stride = (size_t)gridDim.x * blockDim.x;
    for (; i < n4; i += stride) {
        float4 v = *(const float4*)(src + i * 4);
        split4h_store(v, hi, lo, i * 4);
    }
}

// fused weight conversion: wcat[1664][512] = [Wq|Wk|Wv|Wg|W1|zeros], plus Wo
__global__ void conv_w_fused(const float* __restrict__ Wq, const float* __restrict__ Wk,
                             const float* __restrict__ Wv, const float* __restrict__ Wg,
                             const float* __restrict__ W1, const float* __restrict__ Wo,
                             __half* __restrict__ wcat, __half* __restrict__ wo) {
    size_t i = (size_t)blockIdx.x * blockDim.x + threadIdx.x;
    if (i < 212992) {
        size_t e = i * 4;
        int R = (int)(e >> 9), c = (int)(e & 511);
        if (R >= 1552) {
            *(uint2*)(wcat + e) = make_uint2(0u, 0u);
            return;
        }
        const float* src; int r;
        if (R < 256)       { src = Wq; r = R; }
        else if (R < 512)  { src = Wk; r = R - 256; }
        else if (R < 1024) { src = Wv; r = R - 512; }
        else if (R < 1536) { src = Wg; r = R - 1024; }
        else               { src = W1; r = R - 1536; }
        float4 v = *(const float4*)(src + (size_t)r * 512 + c);
        conv4h_store(v, wcat, e);
    } else if (i < 278528) {
        size_t e = (i - 212992) * 4;
        float4 v = *(const float4*)(Wo + e);
        conv4h_store(v, wo, e);
    }
}

// ======= chunk_state: gk from z (low-rank stage 2), cumsum, U = k_dec^T @ v
#define CS_BC    0
#define CS_BLAST 16640
#define CS_Z     16896
#define CS_W2    21248
#define CS_BS    25600
#define CS_PSUM  25856           // 256 floats (segmented cumsum partials)
#define CS_KDH   26880
#define CS_KDL   36096
#define CS_VTH   45312
#define CS_VTL   63744
#define CS_SMEM  82176
__global__ void __launch_bounds__(256, 2) chunk_state_tc(
    const float* __restrict__ k, const float* __restrict__ v,
    const float* __restrict__ z, const float* __restrict__ W2,
    const float* __restrict__ bias,
    float* __restrict__ gk, float* __restrict__ U, float* __restrict__ decay)
{
    extern __shared__ char smem[];
    float* bc = (float*)(smem + CS_BC);                  // [64][65]
    float* blast = (float*)(smem + CS_BLAST);
    float* zed = (float*)(smem + CS_Z);                  // [64][17]
    float* w2s = (float*)(smem + CS_W2);                 // [64][17]
    float* bs  = (float*)(smem + CS_BS);
    float* psum = (float*)(smem + CS_PSUM);              // [4][64]
    __nv_bfloat16* kdTh = (__nv_bfloat16*)(smem + CS_KDH);
    __nv_bfloat16* kdTl = (__nv_bfloat16*)(smem + CS_KDL);
    __nv_bfloat16* vTh  = (__nv_bfloat16*)(smem + CS_VTH);
    __nv_bfloat16* vTl  = (__nv_bfloat16*)(smem + CS_VTL);
    uint32_t sb = smem_u32(smem);

    int ch = blockIdx.x;                      // B*N*H = 4096
    int h = ch % Hn;
    int n = (ch / Hn) % Nn;
    int b = ch / (Hn * Nn);
    int tid = threadIdx.x;
    int wid = tid >> 5, lane = tid & 31;
    size_t rowbase = (size_t)b * Tn + (size_t)n * 64;

    // phase 0: load z rows, W2 rows for this head, bias
    {
        int r = tid >> 2, j4 = (tid & 3) * 4;
        float4 zv = *(const float4*)(z + (rowbase + r) * 16 + j4);
        zed[r * 17 + j4] = zv.x; zed[r * 17 + j4 + 1] = zv.y;
        zed[r * 17 + j4 + 2] = zv.z; zed[r * 17 + j4 + 3] = zv.w;
        float4 wv = *(const float4*)(W2 + (size_t)(h * 64 + r) * 16 + j4);
        w2s[r * 17 + j4] = wv.x; w2s[r * 17 + j4 + 1] = wv.y;
        w2s[r * 17 + j4 + 2] = wv.z; w2s[r * 17 + j4 + 3] = wv.w;
        if (tid < 64) bs[tid] = bias[h * 64 + tid];
    }
    __syncthreads();

    // phase 1: bc[c][d] = logsigmoid(z[c]·W2[d] + bias[d]) / 16  (fast intrinsics)
#pragma unroll
    for (int i = 0; i < 16; i++) {
        int e = tid + i * 256;
        int c = e >> 6, d = e & 63;
        float a = bs[d];
#pragma unroll
        for (int j = 0; j < 16; j++) a += zed[c * 17 + j] * w2s[d * 17 + j];
        float ea = __expf(-fabsf(a));
        float ls = fminf(a, 0.f) - __logf(1.f + ea);
        bc[c * 65 + d] = ls * (1.f / 16.f);
    }
    __syncthreads();

    // parallel segmented cumsum: 4 segments x 64 columns (all 256 threads)
    {
        int seg = tid >> 6, d = tid & 63;
        int c0 = seg * 16;
        float part = 0.f;
#pragma unroll
        for (int c = 0; c < 16; c++) part += bc[(c0 + c) * 65 + d];
        psum[seg * 64 + d] = part;
        __syncthreads();
        float base = 0.f;
#pragma unroll
        for (int s = 0; s < 3; s++) if (s < seg) base += psum[s * 64 + d];
        if (seg == 3) {
            float tot = base + part;
            blast[d] = tot;
            decay[((size_t)((b * Hn + h) * Nn + n)) * 64 + d] = __expf(tot);
        }
        float run = base;
#pragma unroll
        for (int c = 0; c < 16; c++) {
            run += bc[(c0 + c) * 65 + d];
            bc[(c0 + c) * 65 + d] = run;
        }
    }
    __syncthreads();

    // phase 2: write cumsum to gmem + kdT split (transposed [d][c])
#pragma unroll
    for (int i = 0; i < 16; i++) {
        int e = tid + i * 256;
        int c = e >> 6, d = e & 63;
        float bcv = bc[c * 65 + d];
        gk[(rowbase + c) * 256 + h * 64 + d] = bcv;
        float kd = k[(rowbase + c) * 256 + h * 64 + d] * __expf(blast[d] - bcv);
        __nv_bfloat16 hh, ll; split_bf(kd, hh, ll);
        kdTh[d * 72 + c] = hh;
        kdTl[d * 72 + c] = ll;
    }
    // phase 3: v transposed split [vv][c]
#pragma unroll
    for (int it = 0; it < 8; it++) {
        int e4 = tid + it * 256;
        int c = e4 >> 5, vv4 = (e4 & 31) * 4;
        float4 vv = *(const float4*)(v + (rowbase + c) * 512 + h * 128 + vv4);
        __nv_bfloat16 hh, ll;
        split_bf(vv.x, hh, ll); vTh[(vv4 + 0) * 72 + c] = hh; vTl[(vv4 + 0) * 72 + c] = ll;
        split_bf(vv.y, hh, ll); vTh[(vv4 + 1) * 72 + c] = hh; vTl[(vv4 + 1) * 72 + c] = ll;
        split_bf(vv.z, hh, ll); vTh[(vv4 + 2) * 72 + c] = hh; vTl[(vv4 + 2) * 72 + c] = ll;
        split_bf(vv.w, hh, ll); vTh[(vv4 + 3) * 72 + c] = hh; vTl[(vv4 + 3) * 72 + c] = ll;
    }
    __syncthreads();

    // phase 4: U[d][vv] = kdT @ vT^T, M=64 N=128 K=64
    int mw = wid & 3, nw = wid >> 2;
    float acc[8][4];
#pragma unroll
    for (int t = 0; t < 8; t++)
#pragma unroll
        for (int r = 0; r < 4; r++) acc[t][r] = 0.f;

    uint32_t a_base = sb + CS_KDH +
        ((uint32_t)(mw * 16 + (lane & 7) + ((lane >> 3) & 1) * 8) * 72u + (uint32_t)((lane >> 4) * 8)) * 2u;
    uint32_t b_rowoff = ((uint32_t)(nw * 64 + (lane & 7) + ((lane >> 4) & 1) * 8) * 72u +
                         (uint32_t)(((lane >> 3) & 1) * 8)) * 2u;
#pragma unroll
    for (int ks = 0; ks < 4; ks++) {
        uint32_t ko = (uint32_t)(ks * 16) * 2u;
        uint32_t ah[4], al[4], bh[4][4], bl[4][4];
        ldsm_x4(a_base + ko, ah);
        ldsm_x4(a_base + (CS_KDL - CS_KDH) + ko, al);
#pragma unroll
        for (int j = 0; j < 4; j++) {
            ldsm_x4(sb + CS_VTH + b_rowoff + (uint32_t)(j * 16 * 72 * 2) + ko, bh[j]);
            ldsm_x4(sb + CS_VTL + b_rowoff + (uint32_t)(j * 16 * 72 * 2) + ko, bl[j]);
        }
#pragma unroll
        for (int j = 0; j < 4; j++) mma16816(acc[j * 2 + 0], ah, bh[j]);
#pragma unroll
        for (int j = 0; j < 4; j++) mma16816(acc[j * 2 + 1], ah, bh[j] + 2);
#pragma unroll
        for (int j = 0; j < 4; j++) mma16816(acc[j * 2 + 0], ah, bl[j]);
#pragma unroll
        for (int j = 0; j < 4; j++) mma16816(acc[j * 2 + 1], ah, bl[j] + 2);
#pragma unroll
        for (int j = 0; j < 4; j++) mma16816(acc[j * 2 + 0], al, bh[j]);
#pragma unroll
        for (int j = 0; j < 4; j++) mma16816(acc[j * 2 + 1], al, bh[j] + 2);
    }

    size_t ubase = ((size_t)((b * Hn + h) * Nn + n)) * 8192;
    int d0 = mw * 16 + (lane >> 2);
#pragma unroll
    for (int j = 0; j < 4; j++) {
#pragma unroll
        for (int s = 0; s < 2; s++) {
            float* c = acc[j * 2 + s];
            int vv = nw * 64 + j * 16 + s * 8 + (lane & 3) * 2;
            *(float2*)(U + ubase + (size_t)d0 * 128 + vv) = make_float2(c[0], c[1]);
            *(float2*)(U + ubase + (size_t)(d0 + 8) * 128 + vv) = make_float2(c[2], c[3]);
        }
    }
}

// ---------------- inter-chunk scan (parallel over elements) ----------------
__global__ void scan_kernel(float* __restrict__ U, const float* __restrict__ decay) {
    int bh = blockIdx.x >> 5;
    int e = ((blockIdx.x & 31) << 8) + threadIdx.x;
    float s = 0.f;
    size_t base = (size_t)bh * Nn * 8192 + e;
    const float* dp = decay + (size_t)bh * Nn * 64 + (e >> 7);
    for (int n = 0; n < Nn; n++) {
        float u = U[base];
        U[base] = s;
        s = dp[0] * s + u;
        base += 8192; dp += 64;
    }
}

// ======= output (tensor cores): o = tril(qe ke^T) v + qe S_init ============
#define OT_QEH 0
#define OT_QEL 9216
#define OT_X1  18432
#define OT_X1L 27648
#define OT_X2  36864
#define OT_X2L 55296
#define OT_SMEM 73728
__global__ void __launch_bounds__(256, 2) output_tc(
    const float* __restrict__ q, const float* __restrict__ k,
    const float* __restrict__ v, const float* __restrict__ gk,
    const float* __restrict__ Sinit, float* __restrict__ o)
{
    extern __shared__ char smem[];
    __nv_bfloat16* qeh = (__nv_bfloat16*)(smem + OT_QEH);
    __nv_bfloat16* qel = (__nv_bfloat16*)(smem + OT_QEL);
    __nv_bfloat16* x1h = (__nv_bfloat16*)(smem + OT_X1);    // ke -> Ash
    __nv_bfloat16* x1l = (__nv_bfloat16*)(smem + OT_X1L);
    __nv_bfloat16* x2h = (__nv_bfloat16*)(smem + OT_X2);    // ST -> vT
    __nv_bfloat16* x2l = (__nv_bfloat16*)(smem + OT_X2L);
    uint32_t sb = smem_u32(smem);

    int ch = blockIdx.x;
    int h = ch % Hn;
    int n = (ch / Hn) % Nn;
    int b = ch / (Hn * Nn);
    int tid = threadIdx.x;
    int wid = tid >> 5, lane = tid & 31;
    size_t rowbase = (size_t)b * Tn + (size_t)n * 64;
    const float scale = 0.125f;

    int mw = wid & 3, nw = wid >> 2;
    uint32_t arow = ((uint32_t)(mw * 16 + (lane & 7) + ((lane >> 3) & 1) * 8) * 72u +
                     (uint32_t)((lane >> 4) * 8)) * 2u;
    uint32_t brow = ((uint32_t)(nw * 64 + (lane & 7) + ((lane >> 4) & 1) * 8) * 72u +
                    (uint32_t)(((lane >> 3) & 1) * 8)) * 2u;

    float acc[8][4];
#pragma unroll
    for (int t = 0; t < 8; t++)
#pragma unroll
        for (int r = 0; r < 4; r++) acc[t][r] = 0.f;

    // phase 1: qe split [c][d] + ST split [vv][d] (X2)
#pragma unroll
    for (int i = 0; i < 16; i++) {
        int e = tid + i * 256;
        int c = e >> 6, d = e & 63;
        float bcv = gk[(rowbase + c) * 256 + h * 64 + d];
        float qe = q[(rowbase + c) * 256 + h * 64 + d] * __expf(bcv) * scale;
        __nv_bfloat16 hh, ll;
        split_bf(qe, hh, ll); qeh[c * 72 + d] = hh; qel[c * 72 + d] = ll;
    }
    size_t sbase = ((size_t)((b * Hn + h) * Nn + n)) * 8192;
#pragma unroll
    for (int it = 0; it < 8; it++) {
        int e4 = tid + it * 256;
        int d = e4 >> 5, vv4 = (e4 & 31) * 4;
        float4 sv = *(const float4*)(Sinit + sbase + (size_t)d * 128 + vv4);
        __nv_bfloat16 hh, ll;
        split_bf(sv.x, hh, ll); x2h[(vv4 + 0) * 72 + d] = hh; x2l[(vv4 + 0) * 72 + d] = ll;
        split_bf(sv.y, hh, ll); x2h[(vv4 + 1) * 72 + d] = hh; x2l[(vv4 + 1) * 72 + d] = ll;
        split_bf(sv.z, hh, ll); x2h[(vv4 + 2) * 72 + d] = hh; x2l[(vv4 + 2) * 72 + d] = ll;
        split_bf(sv.w, hh, ll); x2h[(vv4 + 3) * 72 + d] = hh; x2l[(vv4 + 3) * 72 + d] = ll;
    }
    __syncthreads();

    // phase 2: acc += qe @ ST  (M=64 N=128 K=64)
#pragma unroll
    for (int ks = 0; ks < 4; ks++) {
        uint32_t ko = (uint32_t)(ks * 16) * 2u;
        uint32_t ah[4], al[4], bh[4][4], bl[4][4];
        ldsm_x4(sb + OT_QEH + arow + ko, ah);
        ldsm_x4(sb + OT_QEL + arow + ko, al);
#pragma unroll
        for (int j = 0; j < 4; j++) {
            ldsm_x4(sb + OT_X2 + brow + (uint32_t)(j * 16 * 72 * 2) + ko, bh[j]);
            ldsm_x4(sb + OT_X2L + brow + (uint32_t)(j * 16 * 72 * 2) + ko, bl[j]);
        }
#pragma unroll
        for (int j = 0; j < 4; j++) mma16816(acc[j * 2 + 0], ah, bh[j]);
#pragma unroll
        for (int j = 0; j < 4; j++) mma16816(acc[j * 2 + 1], ah, bh[j] + 2);
#pragma unroll
        for (int j = 0; j < 4; j++) mma16816(acc[j * 2 + 0], ah, bl[j]);
#pragma unroll
        for (int j = 0; j < 4; j++) mma16816(acc[j * 2 + 1], ah, bl[j] + 2);
#pragma unroll
        for (int j = 0; j < 4; j++) mma16816(acc[j * 2 + 0], al, bh[j]);
#pragma unroll
        for (int j = 0; j < 4; j++) mma16816(acc[j * 2 + 1], al, bh[j] + 2);
    }
    __syncthreads();     // ST reads complete before vT overwrites X2

    // phase 3: ke split [e][d] -> X1 ; vT split [vv][c] -> X2
#pragma unroll
    for (int i = 0; i < 16; i++) {
        int e = tid + i * 256;
        int c = e >> 6, d = e & 63;
        float bcv = gk[(rowbase + c) * 256 + h * 64 + d];
        float ke = k[(rowbase + c) * 256 + h * 64 + d] * __expf(-bcv);
        __nv_bfloat16 hh, ll;
        split_bf(ke, hh, ll); x1h[c * 72 + d] = hh; x1l[c * 72 + d] = ll;
    }
#pragma unroll
    for (int it = 0; it < 8; it++) {
        int e4 = tid + it * 256;
        int c = e4 >> 5, vv4 = (e4 & 31) * 4;
        float4 vv = *(const float4*)(v + (rowbase + c) * 512 + h * 128 + vv4);
        __nv_bfloat16 hh, ll;
        split_bf(vv.x, hh, ll); x2h[(vv4 + 0) * 72 + c] = hh; x2l[(vv4 + 0) * 72 + c] = ll;
        split_bf(vv.y, hh, ll); x2h[(vv4 + 1) * 72 + c] = hh; x2l[(vv4 + 1) * 72 + c] = ll;
        split_bf(vv.z, hh, ll); x2h[(vv4 + 2) * 72 + c] = hh; x2l[(vv4 + 2) * 72 + c] = ll;
        split_bf(vv.w, hh, ll); x2h[(vv4 + 3) * 72 + c] = hh; x2l[(vv4 + 3) * 72 + c] = ll;
    }
    __syncthreads();

    // phase 4: acc1 = qe @ ke^T  (M=64 N=64 K=64), warp map 4x2
    float acc1[4][4];
#pragma unroll
    for (int t = 0; t < 4; t++)
#pragma unroll
        for (int r = 0; r < 4; r++) acc1[t][r] = 0.f;
    {
        uint32_t b_base = sb + OT_X1 +
            ((uint32_t)(nw * 32 + (lane & 7) + ((lane >> 4) & 1) * 8) * 72u + (uint32_t)(((lane >> 3) & 1) * 8)) * 2u;
        uint32_t a_base = sb + OT_QEH + arow;
#pragma unroll
        for (int ks = 0; ks < 4; ks++) {
            uint32_t ko = (uint32_t)(ks * 16) * 2u;
            uint32_t ah[4], al[4], bh0[4], bh1[4], bl0[4], bl1[4];
            ldsm_x4(a_base + ko, ah);
            ldsm_x4(a_base + (OT_QEL - OT_QEH) + ko, al);
            ldsm_x4(b_base + ko, bh0);
            ldsm_x4(b_base + (uint32_t)(16 * 72 * 2) + ko, bh1);
            ldsm_x4(b_base + (OT_X1L - OT_X1) + ko, bl0);
            ldsm_x4(b_base + (OT_X1L - OT_X1) + (uint32_t)(16 * 72 * 2) + ko, bl1);
            mma16816(acc1[0], ah, bh0); mma16816(acc1[1], ah, bh0 + 2);
            mma16816(acc1[2], ah, bh1); mma16816(acc1[3], ah, bh1 + 2);
            mma16816(acc1[0], ah, bl0); mma16816(acc1[1], ah, bl0 + 2);
            mma16816(acc1[2], ah, bl1); mma16816(acc1[3], ah, bl1 + 2);
            mma16816(acc1[0], al, bh0); mma16816(acc1[1], al, bh0 + 2);
            mma16816(acc1[2], al, bh1); mma16816(acc1[3], al, bh1 + 2);
        }
    }
    __syncthreads();     // ke reads done before Ash overlay

    // phase 5: mask + split-store A -> X1 [c][e]
    {
        int r0 = mw * 16 + (lane >> 2);
#pragma unroll
        for (int p = 0; p < 2; p++) {
#pragma unroll
            for (int s = 0; s < 2; s++) {
                float* cfr = acc1[p * 2 + s];
                int e0 = nw * 32 + p * 16 + s * 8 + (lane & 3) * 2;
#pragma unroll
                for (int rr = 0; rr < 2; rr++) {
                    int c = r0 + rr * 8;
#pragma unroll
                    for (int cc = 0; cc < 2; cc++) {
                        int e = e0 + cc;
                        float val = (e <= c) ? cfr[rr * 2 + cc] : 0.f;
                        __nv_bfloat16 hh, ll; split_bf(val, hh, ll);
                        x1h[c * 72 + e] = hh;
                        x1l[c * 72 + e] = ll;
                    }
                }
            }
        }
    }
    __syncthreads();

    // phase 6: acc += A @ vT  (M=64 N=128 K=64)
#pragma unroll
    for (int ks = 0; ks < 4; ks++) {
        uint32_t ko = (uint32_t)(ks * 16) * 2u;
        uint32_t ah[4], al[4], bh[4][4], bl[4][4];
        ldsm_x4(sb + OT_X1 + arow + ko, ah);
        ldsm_x4(sb + OT_X1L + arow + ko, al);
#pragma unroll
        for (int j = 0; j < 4; j++) {
            ldsm_x4(sb + OT_X2 + brow + (uint32_t)(j * 16 * 72 * 2) + ko, bh[j]);
            ldsm_x4(sb + OT_X2L + brow + (uint32_t)(j * 16 * 72 * 2) + ko, bl[j]);
        }
#pragma unroll
        for (int j = 0; j < 4; j++) mma16816(acc[j * 2 + 0], ah, bh[j]);
#pragma unroll
        for (int j = 0; j < 4; j++) mma16816(acc[j * 2 + 1], ah, bh[j] + 2);
#pragma unroll
        for (int j = 0; j < 4; j++) mma16816(acc[j * 2 + 0], ah, bl[j]);
#pragma unroll
        for (int j = 0; j < 4; j++) mma16816(acc[j * 2 + 1], ah, bl[j] + 2);
#pragma unroll
        for (int j = 0; j < 4; j++) mma16816(acc[j * 2 + 0], al, bh[j]);
#pragma unroll
        for (int j = 0; j < 4; j++) mma16816(acc[j * 2 + 1], al, bh[j] + 2);
    }

    int c0 = mw * 16 + (lane >> 2);
#pragma unroll
    for (int j = 0; j < 4; j++) {
#pragma unroll
        for (int s = 0; s < 2; s++) {
            float* cf = acc[j * 2 + s];
            int vv = nw * 64 + j * 16 + s * 8 + (lane & 3) * 2;
            *(float2*)(o + (rowbase + c0) * 512 + h * 128 + vv) = make_float2(cf[0], cf[1]);
            *(float2*)(o + (rowbase + c0 + 8) * 512 + h * 128 + vv) = make_float2(cf[2], cf[3]);
        }
    }
}

// ---------------- RMS-norm + SiLU gating -> fp16 hi/lo ---------------------
__global__ void gate_kernel(const float* __restrict__ o, const float* __restrict__ g,
                            const float* __restrict__ gw,
                            __half* __restrict__ oh, __half* __restrict__ ol) {
    int row = blockIdx.x;
    int tid = threadIdx.x;               // 512
    __shared__ float wsum[16];
    size_t idx = (size_t)row * 512 + tid;
    float ov = o[idx];
    float sq = ov * ov;
#pragma unroll
    for (int off = 16; off; off >>= 1) sq += __shfl_down_sync(0xffffffffu, sq, off);
    if ((tid & 31) == 0) wsum[tid >> 5] = sq;
    __syncthreads();
    int h = tid >> 7;
    float ss = wsum[h * 4] + wsum[h * 4 + 1] + wsum[h * 4 + 2] + wsum[h * 4 + 3];
    float rms = rsqrtf(ss * (1.f / 128.f) + 1e-5f);
    float gv = g[idx];
    float sig = 1.f / (1.f + __expf(-gv));
    float val = ov * rms * gw[tid & 127] * gv * sig;
    __half hh, ll; split_h(val, hh, ll);
    oh[idx] = hh;
    ol[idx] = ll;
}

// ---------------- launcher --------------------------------------------------
extern "C" void kernel_launch(void* const* d_in, const int* in_sizes, int n_in,
                              void* d_out, int out_size) {
    const float* x    = (const float*)d_in[0];
    const float* Wq   = (const float*)d_in[1];
    const float* Wk   = (const float*)d_in[2];
    const float* Wv   = (const float*)d_in[3];
    const float* Wg   = (const float*)d_in[4];
    const float* Wgk1 = (const float*)d_in[5];
    const float* Wgk2 = (const float*)d_in[6];
    const float* bgk2 = (const float*)d_in[7];
    const float* gnw  = (const float*)d_in[8];
    const float* Wo   = (const float*)d_in[9];
    float* out = (float*)d_out;

    float *q, *k, *v, *g, *gk, *z, *U, *dec, *o;
    cudaGetSymbolAddress((void**)&q,   g_q);
    cudaGetSymbolAddress((void**)&k,   g_k);
    cudaGetSymbolAddress((void**)&v,   g_v);
    cudaGetSymbolAddress((void**)&g,   g_g);
    cudaGetSymbolAddress((void**)&gk,  g_gk);
    cudaGetSymbolAddress((void**)&z,   g_z);
    cudaGetSymbolAddress((void**)&U,   g_U);
    cudaGetSymbolAddress((void**)&dec, g_dec);
    cudaGetSymbolAddress((void**)&o,   g_o);

    __half *xh, *xl, *oh, *ol, *wcat, *wo;
    cudaGetSymbolAddress((void**)&xh, g_xh);     cudaGetSymbolAddress((void**)&xl, g_xl);
    cudaGetSymbolAddress((void**)&oh, g_oh);     cudaGetSymbolAddress((void**)&ol, g_ol);
    cudaGetSymbolAddress((void**)&wcat, g_wcat); cudaGetSymbolAddress((void**)&wo, g_wo);

    const int smem_gemm = 3 * (int)STAGEB;                  // 92160
    cudaFuncSetAttribute(gemm_f16, cudaFuncAttributeMaxDynamicSharedMemorySize, smem_gemm);
    cudaFuncSetAttribute(chunk_state_tc, cudaFuncAttributeMaxDynamicSharedMemorySize, CS_SMEM);
    cudaFuncSetAttribute(output_tc, cudaFuncAttributeMaxDynamicSharedMemorySize, OT_SMEM);

    conv_split4h<<<2048, 256>>>(x, xh, xl, (size_t)BTn * Dn / 4);
    conv_w_fused<<<1088, 256>>>(Wq, Wk, Wv, Wg, Wgk1, Wo, wcat, wo);

    // fused qkvg + z projection (N = 1664 -> 13 tiles)
    gemm_f16<<<dim3(BTn / 128, 13), 256, smem_gemm>>>(xh, xl, wcat, q, k, v, g, z, BTn, Dn, 1);

    chunk_state_tc<<<Bn * Nn * Hn, 256, CS_SMEM>>>(k, v, z, Wgk2, bgk2, gk, U, dec);
    scan_kernel<<<Bn * Hn * 32, 256>>>(U, dec);
    output_tc<<<Bn * Nn * Hn, 256, OT_SMEM>>>(q, k, v, gk, U, o);
    gate_kernel<<<BTn, 512>>>(o, g, gnw, oh, ol);

    // output projection (N = 512)
    gemm_f16<<<dim3(BTn / 128, 4), 256, smem_gemm>>>(oh, ol, wo, out, 0, 0, 0, 0, BTn, Dn, 0);
}